// round 2
// baseline (speedup 1.0000x reference)
#include <cuda_runtime.h>

#define T_SEQ 2048
#define EMB   2048
#define NH    16
#define HD    128
#define LAT   64

// ---------------- scratch (static device globals; no allocation) ----------------
__device__ float g_Q[T_SEQ * EMB];          // 16 MB  [t][h*128+d]
__device__ float g_lk[T_SEQ * LAT];         // latent K [t][l]
__device__ float g_lv[T_SEQ * LAT];         // latent V [t][l]
__device__ float g_qlat[T_SEQ * NH * LAT];  // [t][h][l]
__device__ float g_qsum[T_SEQ * NH];        // sum_l q_latent
__device__ float g_ksum[T_SEQ];             // sum_l latent_k
__device__ float g_vexp[T_SEQ * NH * HD];   // [t][h][d]
__device__ float g_ctx[T_SEQ * EMB];        // attention output [t][h*128+d]

// ---------------- generic SGEMM: C[M,N] = A[M,K] @ B[N,K]^T ----------------
// 128x128 tile, BK=16, 256 threads, 8x8 per-thread microtile (4+4 split layout).
__global__ __launch_bounds__(256) void sgemm_abT(
    const float* __restrict__ A, const float* __restrict__ B,
    float* __restrict__ C, int M, int N, int K)
{
    __shared__ float As[16][128];
    __shared__ float Bs[16][128];

    const int tid = threadIdx.x;
    const int bm = blockIdx.y * 128;
    const int bn = blockIdx.x * 128;
    const int tx = tid & 15;
    const int ty = tid >> 4;
    const int lrow = tid >> 2;          // 0..63
    const int lcol = (tid & 3) << 2;    // 0,4,8,12

    float acc[8][8];
#pragma unroll
    for (int i = 0; i < 8; i++)
#pragma unroll
        for (int j = 0; j < 8; j++) acc[i][j] = 0.f;

    for (int k0 = 0; k0 < K; k0 += 16) {
#pragma unroll
        for (int i = 0; i < 2; i++) {
            int r = lrow + i * 64;
            float4 va = *(const float4*)(A + (size_t)(bm + r) * K + k0 + lcol);
            As[lcol + 0][r] = va.x; As[lcol + 1][r] = va.y;
            As[lcol + 2][r] = va.z; As[lcol + 3][r] = va.w;
            float4 vb = make_float4(0.f, 0.f, 0.f, 0.f);
            if (bn + r < N)
                vb = *(const float4*)(B + (size_t)(bn + r) * K + k0 + lcol);
            Bs[lcol + 0][r] = vb.x; Bs[lcol + 1][r] = vb.y;
            Bs[lcol + 2][r] = vb.z; Bs[lcol + 3][r] = vb.w;
        }
        __syncthreads();
#pragma unroll
        for (int k = 0; k < 16; k++) {
            float4 a0 = *(const float4*)&As[k][ty * 4];
            float4 a1 = *(const float4*)&As[k][64 + ty * 4];
            float4 b0 = *(const float4*)&Bs[k][tx * 4];
            float4 b1 = *(const float4*)&Bs[k][64 + tx * 4];
            float a[8] = {a0.x, a0.y, a0.z, a0.w, a1.x, a1.y, a1.z, a1.w};
            float b[8] = {b0.x, b0.y, b0.z, b0.w, b1.x, b1.y, b1.z, b1.w};
#pragma unroll
            for (int i = 0; i < 8; i++)
#pragma unroll
                for (int j = 0; j < 8; j++)
                    acc[i][j] = fmaf(a[i], b[j], acc[i][j]);
        }
        __syncthreads();
    }

#pragma unroll
    for (int i = 0; i < 8; i++) {
        int r = bm + ((i < 4) ? (ty * 4 + i) : (60 + ty * 4 + i));
#pragma unroll
        for (int j = 0; j < 8; j++) {
            int c = bn + ((j < 4) ? (tx * 4 + j) : (60 + tx * 4 + j));
            if (c < N) C[(size_t)r * N + c] = acc[i][j];
        }
    }
}

// ---------------- q_latent[t,h,l] = sum_d Q[t,h,d] * q2l[h,d,l] ----------------
// grid (T/32, H), 256 threads
__global__ __launch_bounds__(256) void qlatent_kernel(
    const float* __restrict__ Q, const float* __restrict__ q2l,
    float* __restrict__ qlat)
{
    __shared__ float Ws[128][64];   // 32 KB  q2l[h][d][l]
    __shared__ float Qs[32][128];   // 16 KB
    const int h = blockIdx.y;
    const int t0 = blockIdx.x * 32;
    const float* W = q2l + (size_t)h * 128 * 64;

    for (int i = threadIdx.x; i < 128 * 64; i += 256)
        Ws[i >> 6][i & 63] = W[i];
    for (int i = threadIdx.x; i < 32 * 128; i += 256)
        Qs[i >> 7][i & 127] = Q[(size_t)(t0 + (i >> 7)) * EMB + h * 128 + (i & 127)];
    __syncthreads();

    for (int o = threadIdx.x; o < 32 * 64; o += 256) {
        int tl = o >> 6, l = o & 63;
        float acc = 0.f;
#pragma unroll 8
        for (int d = 0; d < 128; d++) acc = fmaf(Qs[tl][d], Ws[d][l], acc);
        qlat[((size_t)(t0 + tl) * NH + h) * LAT + l] = acc;
    }
}

// ---------------- row sums for the reciprocal band term ----------------
__global__ void sums_kernel(const float* __restrict__ qlat,
                            const float* __restrict__ lk,
                            float* __restrict__ qsum, float* __restrict__ ksum)
{
    int i = blockIdx.x * blockDim.x + threadIdx.x;
    if (i < T_SEQ * NH) {
        float s = 0.f;
#pragma unroll 8
        for (int l = 0; l < LAT; l++) s += qlat[(size_t)i * LAT + l];
        qsum[i] = s;
    }
    if (i < T_SEQ) {
        float s = 0.f;
#pragma unroll 8
        for (int l = 0; l < LAT; l++) s += lk[(size_t)i * LAT + l];
        ksum[i] = s;
    }
}

// ---------------- V_exp[t,h,d] = sum_l lv[t,l] * v_up[h,l,d] ----------------
// grid (T/32, H), 128 threads
__global__ __launch_bounds__(128) void vexp_kernel(
    const float* __restrict__ lv, const float* __restrict__ vup,
    float* __restrict__ vexp)
{
    __shared__ float VU[64][128];   // 32 KB
    __shared__ float LVs[32][64];   // 8 KB
    const int h = blockIdx.y;
    const int t0 = blockIdx.x * 32;
    const float* W = vup + (size_t)h * 64 * 128;

    for (int i = threadIdx.x; i < 64 * 128; i += 128)
        VU[i >> 7][i & 127] = W[i];
    for (int i = threadIdx.x; i < 32 * 64; i += 128)
        LVs[i >> 6][i & 63] = lv[(size_t)(t0 + (i >> 6)) * LAT + (i & 63)];
    __syncthreads();

    int d = threadIdx.x;  // 0..127
    for (int tl = 0; tl < 32; tl++) {
        float acc = 0.f;
#pragma unroll 8
        for (int l = 0; l < 64; l++) acc = fmaf(LVs[tl][l], VU[l][d], acc);
        vexp[((size_t)(t0 + tl) * NH + h) * HD + d] = acc;
    }
}

// ---------------- causal flash attention (latent logits, K-dim = 64) ----------------
// grid (T/64, H), 256 threads, dynamic smem.
// Smem: Qs[64][65], Ks[64][65], Ss[64][68], Vs[64][128]  -> 83456 bytes
__global__ __launch_bounds__(256) void flash_kernel(
    const float* __restrict__ qlat, const float* __restrict__ lk,
    const float* __restrict__ vexp, const float* __restrict__ qsum,
    const float* __restrict__ ksum, float* __restrict__ ctx)
{
    extern __shared__ float sm[];
    float* Qs = sm;                 // stride 65
    float* Ks = Qs + 64 * 65;       // stride 65
    float* Ss = Ks + 64 * 65;       // stride 68 (float4-aligned rows)
    float* Vs = Ss + 64 * 68;       // stride 128
    __shared__ float qss[64];
    __shared__ float kss[64];
    __shared__ float s_alpha[64];
    __shared__ float s_linv[64];

    const int h = blockIdx.y;
    const int q0 = blockIdx.x * 64;
    const int tid = threadIdx.x;

    // S-compute mapping (16x16 threads, 4x4 microtile)
    const int sy = tid >> 4, sx = tid & 15;
    // softmax mapping (4 lanes per row)
    const int row = tid >> 2, qd = tid & 3;
    // O-update mapping (8 rows x 4 cols per thread)
    const int ry = tid >> 5, cx = tid & 31;

    // load Q tile + qsum
    for (int i = tid; i < 64 * 64; i += 256) {
        int r = i >> 6, l = i & 63;
        Qs[r * 65 + l] = qlat[((size_t)(q0 + r) * NH + h) * LAT + l];
    }
    if (tid < 64) qss[tid] = qsum[(size_t)(q0 + tid) * NH + h];

    float4 Oc[8];
#pragma unroll
    for (int r = 0; r < 8; r++) Oc[r] = make_float4(0.f, 0.f, 0.f, 0.f);
    float m_run = -1e30f, l_run = 0.f;

    const int nkb = blockIdx.x + 1;
    __syncthreads();

    for (int kb = 0; kb < nkb; kb++) {
        const int s0 = kb * 64;
        // load K tile, V tile, ksum tile
        for (int i = tid; i < 64 * 64; i += 256) {
            int r = i >> 6, l = i & 63;
            Ks[r * 65 + l] = lk[(size_t)(s0 + r) * LAT + l];
        }
        for (int i = tid; i < 64 * 128; i += 256) {
            int r = i >> 7, d = i & 127;
            Vs[r * 128 + d] = vexp[((size_t)(s0 + r) * NH + h) * HD + d];
        }
        if (tid < 64) kss[tid] = ksum[s0 + tid];
        __syncthreads();

        // S = Q @ K^T over latent dim 64
        float sacc[4][4];
#pragma unroll
        for (int i = 0; i < 4; i++)
#pragma unroll
            for (int j = 0; j < 4; j++) sacc[i][j] = 0.f;
#pragma unroll 4
        for (int l = 0; l < 64; l++) {
            float qa[4], kk[4];
#pragma unroll
            for (int i = 0; i < 4; i++) qa[i] = Qs[(sy * 4 + i) * 65 + l];
#pragma unroll
            for (int j = 0; j < 4; j++) kk[j] = Ks[(sx * 4 + j) * 65 + l];
#pragma unroll
            for (int i = 0; i < 4; i++)
#pragma unroll
                for (int j = 0; j < 4; j++)
                    sacc[i][j] = fmaf(qa[i], kk[j], sacc[i][j]);
        }
        // mask + scale + reciprocal band, write to Ss
#pragma unroll
        for (int i = 0; i < 4; i++) {
#pragma unroll
            for (int j = 0; j < 4; j++) {
                int li = sy * 4 + i, lj = sx * 4 + j;
                int gi = q0 + li, gj = s0 + lj;
                float v = -1e30f;
                if (gj <= gi) {
                    v = sacc[i][j] * 0.125f;                 // 1/sqrt(64)
                    if (gi - gj <= 64)
                        v += 0.0625f * qss[li] * kss[lj];     // 0.5 * 1/sqrt(64)
                }
                Ss[li * 68 + lj] = v;
            }
        }
        __syncthreads();

        // online softmax, 4 lanes per row
        float mx = -1e30f;
        for (int j = qd * 16; j < qd * 16 + 16; j++)
            mx = fmaxf(mx, Ss[row * 68 + j]);
        mx = fmaxf(mx, __shfl_xor_sync(0xffffffffu, mx, 1));
        mx = fmaxf(mx, __shfl_xor_sync(0xffffffffu, mx, 2));
        float m_new = fmaxf(m_run, mx);
        float alpha = __expf(m_run - m_new);
        float ps = 0.f;
        for (int j = qd * 16; j < qd * 16 + 16; j++) {
            float p = __expf(Ss[row * 68 + j] - m_new);
            Ss[row * 68 + j] = p;
            ps += p;
        }
        ps += __shfl_xor_sync(0xffffffffu, ps, 1);
        ps += __shfl_xor_sync(0xffffffffu, ps, 2);
        l_run = l_run * alpha + ps;
        m_run = m_new;
        if (qd == 0) s_alpha[row] = alpha;
        __syncthreads();

        // O = O*alpha + P @ V   (register-blocked 8 rows x 4 cols)
#pragma unroll
        for (int r = 0; r < 8; r++) {
            float a = s_alpha[ry * 8 + r];
            Oc[r].x *= a; Oc[r].y *= a; Oc[r].z *= a; Oc[r].w *= a;
        }
        for (int j = 0; j < 64; j++) {
            float4 bv = *(const float4*)&Vs[j * 128 + cx * 4];
#pragma unroll
            for (int r = 0; r < 8; r++) {
                float p = Ss[(ry * 8 + r) * 68 + j];
                Oc[r].x = fmaf(p, bv.x, Oc[r].x);
                Oc[r].y = fmaf(p, bv.y, Oc[r].y);
                Oc[r].z = fmaf(p, bv.z, Oc[r].z);
                Oc[r].w = fmaf(p, bv.w, Oc[r].w);
            }
        }
        __syncthreads();
    }

    if (qd == 0) s_linv[row] = 1.f / l_run;
    __syncthreads();

#pragma unroll
    for (int r = 0; r < 8; r++) {
        float s = s_linv[ry * 8 + r];
        int t = q0 + ry * 8 + r;
        float4 o = Oc[r];
        o.x *= s; o.y *= s; o.z *= s; o.w *= s;
        *(float4*)(ctx + (size_t)t * EMB + h * 128 + cx * 4) = o;
    }
}

// ---------------- host launcher ----------------
extern "C" void kernel_launch(void* const* d_in, const int* in_sizes, int n_in,
                              void* d_out, int out_size)
{
    const float* hidden = (const float*)d_in[0];
    const float* Wq  = (const float*)d_in[1];
    const float* Wk  = (const float*)d_in[2];
    const float* Wv  = (const float*)d_in[3];
    const float* q2l = (const float*)d_in[4];
    const float* vup = (const float*)d_in[5];
    const float* Wo  = (const float*)d_in[6];
    float* out = (float*)d_out;

    float *Qb, *lk, *lv, *qlat, *qs, *ks, *vexp, *ctx;
    cudaGetSymbolAddress((void**)&Qb,   g_Q);
    cudaGetSymbolAddress((void**)&lk,   g_lk);
    cudaGetSymbolAddress((void**)&lv,   g_lv);
    cudaGetSymbolAddress((void**)&qlat, g_qlat);
    cudaGetSymbolAddress((void**)&qs,   g_qsum);
    cudaGetSymbolAddress((void**)&ks,   g_ksum);
    cudaGetSymbolAddress((void**)&vexp, g_vexp);
    cudaGetSymbolAddress((void**)&ctx,  g_ctx);

    const int flash_smem = (64 * 65 + 64 * 65 + 64 * 68 + 64 * 128) * 4;  // 83456
    cudaFuncSetAttribute(flash_kernel,
                         cudaFuncAttributeMaxDynamicSharedMemorySize, flash_smem);

    // 1) Q = hidden @ Wq^T
    sgemm_abT<<<dim3(16, 16), 256>>>(hidden, Wq, Qb, T_SEQ, EMB, EMB);
    // 2) latent K / V
    sgemm_abT<<<dim3(1, 16), 256>>>(hidden, Wk, lk, T_SEQ, LAT, EMB);
    sgemm_abT<<<dim3(1, 16), 256>>>(hidden, Wv, lv, T_SEQ, LAT, EMB);
    // 3) q_latent
    qlatent_kernel<<<dim3(64, 16), 256>>>(Qb, q2l, qlat);
    // 4) row sums for reciprocal band
    sums_kernel<<<128, 256>>>(qlat, lk, qs, ks);
    // 5) V up-projection
    vexp_kernel<<<dim3(64, 16), 128>>>(lv, vup, vexp);
    // 6) causal flash attention with band term
    flash_kernel<<<dim3(32, 16), 256, flash_smem>>>(qlat, lk, vexp, qs, ks, ctx);
    // 7) out = ctx @ Wo^T
    sgemm_abT<<<dim3(16, 16), 256>>>(ctx, Wo, out, T_SEQ, EMB, EMB);
}

// round 3
// speedup vs baseline: 1.3066x; 1.3066x over previous
#include <cuda_runtime.h>

#define T_SEQ 2048
#define EMB   2048
#define NH    16
#define HD    128
#define LAT   64

// ---------------- scratch (static device globals; no allocation) ----------------
__device__ float g_WqT[EMB * EMB];            // Wq transposed [e][hd]   16 MB
__device__ float g_q2lT[NH * LAT * HD];       // q2l transposed [h][l][d] 512 KB
__device__ float g_Wf1[NH * LAT * EMB];       // folded Q->latent weight [hl][e] 8 MB
__device__ float g_Wf2T[EMB * NH * LAT];      // folded latent->out weight [e][hl] 8 MB
__device__ float g_lk[T_SEQ * LAT];           // latent K [t][l]
__device__ float g_lv[T_SEQ * LAT];           // latent V [t][l]
__device__ float g_lpart[8 * T_SEQ * LAT];    // split-K partials 4 MB
__device__ float g_qlat[T_SEQ * NH * LAT];    // q_latent [t][h*64+l] 8 MB
__device__ float g_qsum[T_SEQ * NH];
__device__ float g_ksum[T_SEQ];
__device__ float g_lctx[T_SEQ * NH * LAT];    // latent attention output [t][h*64+l] 8 MB

// ---------------- fast SGEMM: C[M,N] = A[M,K] @ B[N,K]^T (all dims %128==0) ----
__global__ __launch_bounds__(256) void sgemm_fast(
    const float* __restrict__ A, const float* __restrict__ B,
    float* __restrict__ C, int M, int N, int K)
{
    __shared__ float As[16][128];
    __shared__ float Bs[16][128];

    const int tid = threadIdx.x;
    const int bm = blockIdx.y * 128;
    const int bn = blockIdx.x * 128;
    const int tx = tid & 15;
    const int ty = tid >> 4;
    const int lrow = tid >> 2;          // 0..63
    const int lcol = (tid & 3) << 2;    // 0,4,8,12

    float acc[8][8];
#pragma unroll
    for (int i = 0; i < 8; i++)
#pragma unroll
        for (int j = 0; j < 8; j++) acc[i][j] = 0.f;

    for (int k0 = 0; k0 < K; k0 += 16) {
#pragma unroll
        for (int i = 0; i < 2; i++) {
            int r = lrow + i * 64;
            float4 va = *(const float4*)(A + (size_t)(bm + r) * K + k0 + lcol);
            As[lcol + 0][r] = va.x; As[lcol + 1][r] = va.y;
            As[lcol + 2][r] = va.z; As[lcol + 3][r] = va.w;
            float4 vb = *(const float4*)(B + (size_t)(bn + r) * K + k0 + lcol);
            Bs[lcol + 0][r] = vb.x; Bs[lcol + 1][r] = vb.y;
            Bs[lcol + 2][r] = vb.z; Bs[lcol + 3][r] = vb.w;
        }
        __syncthreads();
#pragma unroll
        for (int k = 0; k < 16; k++) {
            float4 a0 = *(const float4*)&As[k][ty * 4];
            float4 a1 = *(const float4*)&As[k][64 + ty * 4];
            float4 b0 = *(const float4*)&Bs[k][tx * 4];
            float4 b1 = *(const float4*)&Bs[k][64 + tx * 4];
            float a[8] = {a0.x, a0.y, a0.z, a0.w, a1.x, a1.y, a1.z, a1.w};
            float b[8] = {b0.x, b0.y, b0.z, b0.w, b1.x, b1.y, b1.z, b1.w};
#pragma unroll
            for (int i = 0; i < 8; i++)
#pragma unroll
                for (int j = 0; j < 8; j++)
                    acc[i][j] = fmaf(a[i], b[j], acc[i][j]);
        }
        __syncthreads();
    }

#pragma unroll
    for (int i = 0; i < 8; i++) {
        int r = bm + ((i < 4) ? (ty * 4 + i) : (60 + ty * 4 + i));
#pragma unroll
        for (int j = 0; j < 8; j++) {
            int c = bn + ((j < 4) ? (tx * 4 + j) : (60 + tx * 4 + j));
            C[(size_t)r * N + c] = acc[i][j];
        }
    }
}

// ---------------- generic strided/batched/split-K SGEMM (guarded) ----------------
// C[m][n] (+split slice) = sum_k A[m*lda + kbeg+k] * B[n*ldb + kbeg+k]
__global__ __launch_bounds__(256) void sgemm_strided(
    const float* __restrict__ A, const float* __restrict__ B, float* __restrict__ C,
    int M, int N, int K, int lda, int ldb, int ldc,
    long batchA, long batchB, long batchC,
    int nsplit, long splitStride)
{
    __shared__ float As[16][128];
    __shared__ float Bs[16][128];

    const int zb = blockIdx.z / nsplit;
    const int zs = blockIdx.z % nsplit;
    A += (long)zb * batchA;
    B += (long)zb * batchB;
    C += (long)zb * batchC + (long)zs * splitStride;
    const int Kc = K / nsplit;
    const int kbeg = zs * Kc;

    const int tid = threadIdx.x;
    const int bm = blockIdx.y * 128;
    const int bn = blockIdx.x * 128;
    const int tx = tid & 15;
    const int ty = tid >> 4;
    const int lrow = tid >> 2;
    const int lcol = (tid & 3) << 2;

    float acc[8][8];
#pragma unroll
    for (int i = 0; i < 8; i++)
#pragma unroll
        for (int j = 0; j < 8; j++) acc[i][j] = 0.f;

    for (int k0 = 0; k0 < Kc; k0 += 16) {
        const int kk = kbeg + k0;
#pragma unroll
        for (int i = 0; i < 2; i++) {
            int r = lrow + i * 64;
            float4 va = make_float4(0.f, 0.f, 0.f, 0.f);
            float4 vb = make_float4(0.f, 0.f, 0.f, 0.f);
            if (bm + r < M) va = *(const float4*)(A + (size_t)(bm + r) * lda + kk + lcol);
            if (bn + r < N) vb = *(const float4*)(B + (size_t)(bn + r) * ldb + kk + lcol);
            As[lcol + 0][r] = va.x; As[lcol + 1][r] = va.y;
            As[lcol + 2][r] = va.z; As[lcol + 3][r] = va.w;
            Bs[lcol + 0][r] = vb.x; Bs[lcol + 1][r] = vb.y;
            Bs[lcol + 2][r] = vb.z; Bs[lcol + 3][r] = vb.w;
        }
        __syncthreads();
#pragma unroll
        for (int k = 0; k < 16; k++) {
            float4 a0 = *(const float4*)&As[k][ty * 4];
            float4 a1 = *(const float4*)&As[k][64 + ty * 4];
            float4 b0 = *(const float4*)&Bs[k][tx * 4];
            float4 b1 = *(const float4*)&Bs[k][64 + tx * 4];
            float a[8] = {a0.x, a0.y, a0.z, a0.w, a1.x, a1.y, a1.z, a1.w};
            float b[8] = {b0.x, b0.y, b0.z, b0.w, b1.x, b1.y, b1.z, b1.w};
#pragma unroll
            for (int i = 0; i < 8; i++)
#pragma unroll
                for (int j = 0; j < 8; j++)
                    acc[i][j] = fmaf(a[i], b[j], acc[i][j]);
        }
        __syncthreads();
    }

#pragma unroll
    for (int i = 0; i < 8; i++) {
        int r = bm + ((i < 4) ? (ty * 4 + i) : (60 + ty * 4 + i));
        if (r >= M) continue;
#pragma unroll
        for (int j = 0; j < 8; j++) {
            int c = bn + ((j < 4) ? (tx * 4 + j) : (60 + tx * 4 + j));
            if (c < N) C[(size_t)r * ldc + c] = acc[i][j];
        }
    }
}

// ---------------- split-K reduce: out[i] = sum_s part[s*n + i] ----------------
__global__ void reduce_kernel(const float* __restrict__ part, float* __restrict__ out,
                              int n, int nsplit)
{
    int i = blockIdx.x * blockDim.x + threadIdx.x;
    if (i >= n) return;
    float s = 0.f;
    for (int k = 0; k < nsplit; k++) s += part[(size_t)k * n + i];
    out[i] = s;
}

// ---------------- batched tiled transpose: out[c][r] = in[r][c] ----------------
__global__ void transpose_k(const float* __restrict__ in, float* __restrict__ out,
                            int R, int C, long bIn, long bOut)
{
    __shared__ float t[32][33];
    in  += (long)blockIdx.z * bIn;
    out += (long)blockIdx.z * bOut;
    int x = blockIdx.x * 32 + threadIdx.x;
    for (int i = threadIdx.y; i < 32; i += 8) {
        int y = blockIdx.y * 32 + i;
        if (y < R && x < C) t[i][threadIdx.x] = in[(size_t)y * C + x];
    }
    __syncthreads();
    int x2 = blockIdx.y * 32 + threadIdx.x;
    for (int i = threadIdx.y; i < 32; i += 8) {
        int y2 = blockIdx.x * 32 + i;
        if (y2 < C && x2 < R) out[(size_t)y2 * R + x2] = t[threadIdx.x][i];
    }
}

// ---------------- row sums for the reciprocal band term ----------------
__global__ void sums_kernel(const float* __restrict__ qlat,
                            const float* __restrict__ lk,
                            float* __restrict__ qsum, float* __restrict__ ksum)
{
    int i = blockIdx.x * blockDim.x + threadIdx.x;
    if (i < T_SEQ * NH) {
        float s = 0.f;
#pragma unroll 8
        for (int l = 0; l < LAT; l++) s += qlat[(size_t)i * LAT + l];
        qsum[i] = s;
    }
    if (i < T_SEQ) {
        float s = 0.f;
#pragma unroll 8
        for (int l = 0; l < LAT; l++) s += lk[(size_t)i * LAT + l];
        ksum[i] = s;
    }
}

// ---------------- causal flash attention in latent space (K-dim = V-dim = 64) ----
// grid (T/64, H), 256 threads; outputs lctx[t][h*64+l] = softmax-normalized attn @ lv
__global__ __launch_bounds__(256) void flash_kernel(
    const float* __restrict__ qlat, const float* __restrict__ lk,
    const float* __restrict__ lv, const float* __restrict__ qsum,
    const float* __restrict__ ksum, float* __restrict__ lctx)
{
    extern __shared__ float sm[];
    float* Qs = sm;                 // 64 x (stride 65)
    float* Ks = Qs + 64 * 65;       // 64 x (stride 65)
    float* Ss = Ks + 64 * 65;       // 64 x (stride 68)
    float* Vs = Ss + 64 * 68;       // 64 x (stride 68)
    __shared__ float qss[64];
    __shared__ float kss[64];
    __shared__ float s_alpha[64];
    __shared__ float s_linv[64];

    const int h = blockIdx.y;
    const int qb = gridDim.x - 1 - blockIdx.x;   // heaviest q-blocks launch first
    const int q0 = qb * 64;
    const int tid = threadIdx.x;

    const int sy = tid >> 4, sx = tid & 15;      // S-compute & PV mapping (4x4 microtile)
    const int row = tid >> 2, qd = tid & 3;      // softmax mapping (4 lanes/row)

    // load Q tile + qsum
    for (int i = tid; i < 64 * 16; i += 256) {
        int r = i >> 4, c = (i & 15) << 2;
        float4 v = *(const float4*)(qlat + (size_t)(q0 + r) * (NH * LAT) + h * LAT + c);
        Qs[r * 65 + c + 0] = v.x; Qs[r * 65 + c + 1] = v.y;
        Qs[r * 65 + c + 2] = v.z; Qs[r * 65 + c + 3] = v.w;
    }
    if (tid < 64) qss[tid] = qsum[(size_t)(q0 + tid) * NH + h];

    float4 Oc[4];
#pragma unroll
    for (int r = 0; r < 4; r++) Oc[r] = make_float4(0.f, 0.f, 0.f, 0.f);
    float m_run = -1e30f, l_run = 0.f;
    __syncthreads();

    for (int kb = 0; kb <= qb; kb++) {
        const int s0 = kb * 64;
        for (int i = tid; i < 64 * 16; i += 256) {
            int r = i >> 4, c = (i & 15) << 2;
            float4 k4 = *(const float4*)(lk + (size_t)(s0 + r) * LAT + c);
            Ks[r * 65 + c + 0] = k4.x; Ks[r * 65 + c + 1] = k4.y;
            Ks[r * 65 + c + 2] = k4.z; Ks[r * 65 + c + 3] = k4.w;
            float4 v4 = *(const float4*)(lv + (size_t)(s0 + r) * LAT + c);
            Vs[r * 68 + c + 0] = v4.x; Vs[r * 68 + c + 1] = v4.y;
            Vs[r * 68 + c + 2] = v4.z; Vs[r * 68 + c + 3] = v4.w;
        }
        if (tid < 64) kss[tid] = ksum[s0 + tid];
        __syncthreads();

        // S = Q @ K^T over latent dim 64
        float sacc[4][4];
#pragma unroll
        for (int i = 0; i < 4; i++)
#pragma unroll
            for (int j = 0; j < 4; j++) sacc[i][j] = 0.f;
#pragma unroll 4
        for (int l = 0; l < 64; l++) {
            float qa[4], kk[4];
#pragma unroll
            for (int i = 0; i < 4; i++) qa[i] = Qs[(sy * 4 + i) * 65 + l];
#pragma unroll
            for (int j = 0; j < 4; j++) kk[j] = Ks[(sx * 4 + j) * 65 + l];
#pragma unroll
            for (int i = 0; i < 4; i++)
#pragma unroll
                for (int j = 0; j < 4; j++)
                    sacc[i][j] = fmaf(qa[i], kk[j], sacc[i][j]);
        }
        // mask + scale + reciprocal band
#pragma unroll
        for (int i = 0; i < 4; i++) {
#pragma unroll
            for (int j = 0; j < 4; j++) {
                int li = sy * 4 + i, lj = sx * 4 + j;
                int gi = q0 + li, gj = s0 + lj;
                float v = -1e30f;
                if (gj <= gi) {
                    v = sacc[i][j] * 0.125f;                  // 1/sqrt(64)
                    if (gi - gj <= 64)
                        v += 0.0625f * qss[li] * kss[lj];     // 0.5 / sqrt(64)
                }
                Ss[li * 68 + lj] = v;
            }
        }
        __syncthreads();

        // online softmax, 4 lanes per row
        float mx = -1e30f;
        for (int j = qd * 16; j < qd * 16 + 16; j++)
            mx = fmaxf(mx, Ss[row * 68 + j]);
        mx = fmaxf(mx, __shfl_xor_sync(0xffffffffu, mx, 1));
        mx = fmaxf(mx, __shfl_xor_sync(0xffffffffu, mx, 2));
        float m_new = fmaxf(m_run, mx);
        float alpha = __expf(m_run - m_new);
        float ps = 0.f;
        for (int j = qd * 16; j < qd * 16 + 16; j++) {
            float p = __expf(Ss[row * 68 + j] - m_new);
            Ss[row * 68 + j] = p;
            ps += p;
        }
        ps += __shfl_xor_sync(0xffffffffu, ps, 1);
        ps += __shfl_xor_sync(0xffffffffu, ps, 2);
        l_run = l_run * alpha + ps;
        m_run = m_new;
        if (qd == 0) s_alpha[row] = alpha;
        __syncthreads();

        // O = O*alpha + P @ V  (4 rows x 4 latent cols per thread)
#pragma unroll
        for (int r = 0; r < 4; r++) {
            float a = s_alpha[sy * 4 + r];
            Oc[r].x *= a; Oc[r].y *= a; Oc[r].z *= a; Oc[r].w *= a;
        }
        for (int j = 0; j < 64; j++) {
            float4 bv = *(const float4*)&Vs[j * 68 + sx * 4];
#pragma unroll
            for (int r = 0; r < 4; r++) {
                float p = Ss[(sy * 4 + r) * 68 + j];
                Oc[r].x = fmaf(p, bv.x, Oc[r].x);
                Oc[r].y = fmaf(p, bv.y, Oc[r].y);
                Oc[r].z = fmaf(p, bv.z, Oc[r].z);
                Oc[r].w = fmaf(p, bv.w, Oc[r].w);
            }
        }
        __syncthreads();
    }

    if (qd == 0) s_linv[row] = 1.f / l_run;
    __syncthreads();

#pragma unroll
    for (int r = 0; r < 4; r++) {
        float s = s_linv[sy * 4 + r];
        int t = q0 + sy * 4 + r;
        float4 o = Oc[r];
        o.x *= s; o.y *= s; o.z *= s; o.w *= s;
        *(float4*)(lctx + (size_t)t * (NH * LAT) + h * LAT + sx * 4) = o;
    }
}

// ---------------- host launcher ----------------
extern "C" void kernel_launch(void* const* d_in, const int* in_sizes, int n_in,
                              void* d_out, int out_size)
{
    const float* hidden = (const float*)d_in[0];
    const float* Wq  = (const float*)d_in[1];
    const float* Wk  = (const float*)d_in[2];
    const float* Wv  = (const float*)d_in[3];
    const float* q2l = (const float*)d_in[4];
    const float* vup = (const float*)d_in[5];
    const float* Wo  = (const float*)d_in[6];
    float* out = (float*)d_out;

    float *WqT, *q2lT, *Wf1, *Wf2T, *lk, *lv, *lpart, *qlat, *qs, *ks, *lctx;
    cudaGetSymbolAddress((void**)&WqT,   g_WqT);
    cudaGetSymbolAddress((void**)&q2lT,  g_q2lT);
    cudaGetSymbolAddress((void**)&Wf1,   g_Wf1);
    cudaGetSymbolAddress((void**)&Wf2T,  g_Wf2T);
    cudaGetSymbolAddress((void**)&lk,    g_lk);
    cudaGetSymbolAddress((void**)&lv,    g_lv);
    cudaGetSymbolAddress((void**)&lpart, g_lpart);
    cudaGetSymbolAddress((void**)&qlat,  g_qlat);
    cudaGetSymbolAddress((void**)&qs,    g_qsum);
    cudaGetSymbolAddress((void**)&ks,    g_ksum);
    cudaGetSymbolAddress((void**)&lctx,  g_lctx);

    const int flash_smem = (64 * 65 * 2 + 64 * 68 * 2) * 4;  // 68096 bytes
    cudaFuncSetAttribute(flash_kernel,
                         cudaFuncAttributeMaxDynamicSharedMemorySize, flash_smem);

    // --- weight preprocessing (cheap) ---
    // WqT[e][hd] = Wq[hd][e]
    transpose_k<<<dim3(64, 64, 1), dim3(32, 8)>>>(Wq, WqT, EMB, EMB, 0, 0);
    // q2lT[h][l][d] = q2l[h][d][l]
    transpose_k<<<dim3(2, 4, NH), dim3(32, 8)>>>(q2l, q2lT, HD, LAT,
                                                 (long)HD * LAT, (long)LAT * HD);
    // Wf1[h*64+l][e] = sum_d q2lT[h][l][d] * WqT[e][h*128+d]
    sgemm_strided<<<dim3(16, 1, NH), 256>>>(
        q2lT, WqT, Wf1, LAT, EMB, HD, HD, EMB, EMB,
        (long)LAT * HD, (long)HD, (long)LAT * EMB, 1, 0);
    // Wf2T[e][h*64+l] = sum_d Wo[e][h*128+d] * vup[h][l][d]
    sgemm_strided<<<dim3(1, 16, NH), 256>>>(
        Wo, vup, Wf2T, EMB, LAT, HD, EMB, HD, NH * LAT,
        (long)HD, (long)LAT * HD, (long)LAT, 1, 0);

    // --- latent K / V via deterministic split-K (8 slices + reduce) ---
    sgemm_strided<<<dim3(1, 16, 8), 256>>>(
        hidden, Wk, lpart, T_SEQ, LAT, EMB, EMB, EMB, LAT,
        0, 0, 0, 8, (long)T_SEQ * LAT);
    reduce_kernel<<<(T_SEQ * LAT + 255) / 256, 256>>>(lpart, lk, T_SEQ * LAT, 8);
    sgemm_strided<<<dim3(1, 16, 8), 256>>>(
        hidden, Wv, lpart, T_SEQ, LAT, EMB, EMB, EMB, LAT,
        0, 0, 0, 8, (long)T_SEQ * LAT);
    reduce_kernel<<<(T_SEQ * LAT + 255) / 256, 256>>>(lpart, lv, T_SEQ * LAT, 8);

    // --- q_latent = hidden @ Wf1^T  [2048 x 1024] ---
    sgemm_fast<<<dim3(8, 16), 256>>>(hidden, Wf1, qlat, T_SEQ, NH * LAT, EMB);

    // --- row sums for reciprocal band ---
    sums_kernel<<<128, 256>>>(qlat, lk, qs, ks);

    // --- causal flash attention in latent space ---
    flash_kernel<<<dim3(32, NH), 256, flash_smem>>>(qlat, lk, lv, qs, ks, lctx);

    // --- out = lctx @ Wf2T^T  [2048 x 2048] ---
    sgemm_fast<<<dim3(16, 16), 256>>>(lctx, Wf2T, out, T_SEQ, EMB, NH * LAT);
}

// round 6
// speedup vs baseline: 2.8012x; 2.1438x over previous
#include <cuda_runtime.h>
#include <cuda_bf16.h>
#include <cstdint>

#define T_SEQ 2048
#define EMB   2048
#define NH    16
#define HD    128
#define LAT   64

// ---------------- scratch (static device globals; no allocation) ----------------
__device__ float g_WqT[EMB * EMB];
__device__ float g_q2lT[NH * LAT * HD];
__device__ float g_Wf1[NH * LAT * EMB];
__device__ float g_Wf2T[EMB * NH * LAT];
__device__ float g_lk[T_SEQ * LAT];
__device__ float g_lv[T_SEQ * LAT];
__device__ float g_lpart[8 * T_SEQ * LAT];
__device__ float g_qlat[T_SEQ * NH * LAT];
__device__ float g_qsum[T_SEQ * NH];
__device__ float g_ksum[T_SEQ];
__device__ float g_lctx[T_SEQ * NH * LAT];
// K-extended bf16 split buffers: A' = [hi | lo | hi], B' = [hi | hi | lo]
__device__ __align__(16) __nv_bfloat16 g_hid3 [T_SEQ * 3 * EMB];        // 25 MB
__device__ __align__(16) __nv_bfloat16 g_Wf13 [NH * LAT * 3 * EMB];     // 12.6 MB
__device__ __align__(16) __nv_bfloat16 g_Wf23 [EMB * 3 * NH * LAT];     // 12.6 MB
__device__ __align__(16) __nv_bfloat16 g_lctx3[T_SEQ * 3 * NH * LAT];   // 12.6 MB

// ================= PTX helpers (baseline compute_103-safe only) =================
__device__ __forceinline__ uint32_t smem_u32(const void* p) {
    uint32_t a;
    asm("{ .reg .u64 t; cvta.to.shared.u64 t, %1; cvt.u32.u64 %0, t; }" : "=r"(a) : "l"(p));
    return a;
}
#define CP_ASYNC16(dst, src) \
    asm volatile("cp.async.cg.shared.global [%0], [%1], 16;" :: "r"(dst), "l"(src))
#define CP_COMMIT() asm volatile("cp.async.commit_group;")
#define CP_WAIT1()  asm volatile("cp.async.wait_group 1;")

__device__ __forceinline__ void ldmx4(uint32_t& r0, uint32_t& r1, uint32_t& r2, uint32_t& r3,
                                      uint32_t addr) {
    asm volatile("ldmatrix.sync.aligned.m8n8.x4.shared.b16 {%0,%1,%2,%3}, [%4];"
                 : "=r"(r0), "=r"(r1), "=r"(r2), "=r"(r3) : "r"(addr));
}
__device__ __forceinline__ void mma16816(float* d, const uint32_t* a, const uint32_t* b) {
    asm volatile("mma.sync.aligned.m16n8k16.row.col.f32.bf16.bf16.f32 "
                 "{%0,%1,%2,%3}, {%4,%5,%6,%7}, {%8,%9}, {%0,%1,%2,%3};"
                 : "+f"(d[0]), "+f"(d[1]), "+f"(d[2]), "+f"(d[3])
                 : "r"(a[0]), "r"(a[1]), "r"(a[2]), "r"(a[3]), "r"(b[0]), "r"(b[1]));
}

// ---------------- fp32 -> K-extended bf16 hi/lo split ----------------
// out row stride 3K; hi at [c] and [offH2 + c]; lo at [offL + c]
__global__ void cvt_split3(const float* __restrict__ x, __nv_bfloat16* __restrict__ out,
                           int total, int K, int offH2, int offL)
{
    int i = (blockIdx.x * blockDim.x + threadIdx.x) * 4;
    if (i >= total) return;
    float4 v = *(const float4*)(x + i);
    float vv[4] = {v.x, v.y, v.z, v.w};
    __nv_bfloat16 hb[4], lb[4];
#pragma unroll
    for (int k = 0; k < 4; k++) {
        hb[k] = __float2bfloat16(vv[k]);
        lb[k] = __float2bfloat16(vv[k] - __bfloat162float(hb[k]));
    }
    int r = i / K, c = i - r * K;
    size_t base = (size_t)r * 3 * K + c;
    *(uint2*)(out + base)         = *(uint2*)hb;
    *(uint2*)(out + base + offH2) = *(uint2*)hb;
    *(uint2*)(out + base + offL)  = *(uint2*)lb;
}

// ============== HMMA bf16 GEMM: C[M,N] fp32 = A[M,K] @ B[N,K]^T ==============
// 128x128 CTA tile, BK=64, 256 threads (2x4 warps, warp tile 64x32),
// 3-stage cp.async pipeline, smem stride 72 bf16 (conflict-free ldmatrix).
#define GS 72                         // smem row stride in bf16
#define STAGE_ELTS (128 * GS)         // per operand per stage
#define HMMA_SMEM (3 * 2 * STAGE_ELTS * 2)   // 3 stages * (A+B) * 2 bytes = 110592

__global__ __launch_bounds__(256) void hmma_gemm(
    const __nv_bfloat16* __restrict__ A, const __nv_bfloat16* __restrict__ B,
    float* __restrict__ C, int M, int N, int K)
{
    extern __shared__ __align__(16) __nv_bfloat16 sm[];
    const int tid = threadIdx.x;
    const int wid = tid >> 5;
    const int lane = tid & 31;
    const int warp_m = wid >> 2;          // 0..1
    const int warp_n = wid & 3;           // 0..3
    const int bm = blockIdx.y * 128;
    const int bn = blockIdx.x * 128;
    const uint32_t sbase = smem_u32(sm);

    const int nk = K >> 6;

    // gmem->smem: 1024 16B chunks per operand per stage, 4 per thread
    auto load_stage = [&](int stage, int k0) {
        __nv_bfloat16* As = sm + stage * 2 * STAGE_ELTS;
        __nv_bfloat16* Bs = As + STAGE_ELTS;
#pragma unroll
        for (int i = 0; i < 4; i++) {
            int c = tid + i * 256;        // 0..1023
            int row = c >> 3;
            int col8 = (c & 7) * 8;
            uint32_t da = smem_u32(As + row * GS + col8);
            CP_ASYNC16(da, A + (size_t)(bm + row) * K + k0 + col8);
            uint32_t db = smem_u32(Bs + row * GS + col8);
            CP_ASYNC16(db, B + (size_t)(bn + row) * K + k0 + col8);
        }
    };

    float acc[4][4][4];
#pragma unroll
    for (int mi = 0; mi < 4; mi++)
#pragma unroll
        for (int ni = 0; ni < 4; ni++)
#pragma unroll
            for (int r = 0; r < 4; r++) acc[mi][ni][r] = 0.f;

    load_stage(0, 0); CP_COMMIT();
    if (nk > 1) { load_stage(1, 64); CP_COMMIT(); }

    // ldmatrix lane address components
    const int a_row = (lane & 15);
    const int a_koff = (lane >> 4) * 8;
    const int b_row = (lane & 7) + ((lane >> 4) & 1) * 8;
    const int b_koff = ((lane >> 3) & 1) * 8;

    for (int it = 0; it < nk; it++) {
        CP_WAIT1();
        __syncthreads();
        if (it + 2 < nk) { load_stage((it + 2) % 3, (it + 2) * 64); CP_COMMIT(); }

        const int stage = it % 3;
        const uint32_t sA = sbase + (uint32_t)(stage * 2 * STAGE_ELTS) * 2;
        const uint32_t sB = sA + STAGE_ELTS * 2;

#pragma unroll
        for (int kk = 0; kk < 64; kk += 16) {
            uint32_t af[4][4];
#pragma unroll
            for (int mi = 0; mi < 4; mi++) {
                uint32_t addr = sA + ((warp_m * 64 + mi * 16 + a_row) * GS + kk + a_koff) * 2;
                ldmx4(af[mi][0], af[mi][1], af[mi][2], af[mi][3], addr);
            }
            uint32_t bf[4][2];
#pragma unroll
            for (int ni2 = 0; ni2 < 2; ni2++) {
                uint32_t addr = sB + ((warp_n * 32 + ni2 * 16 + b_row) * GS + kk + b_koff) * 2;
                uint32_t r0, r1, r2, r3;
                ldmx4(r0, r1, r2, r3, addr);
                bf[ni2 * 2 + 0][0] = r0; bf[ni2 * 2 + 0][1] = r1;
                bf[ni2 * 2 + 1][0] = r2; bf[ni2 * 2 + 1][1] = r3;
            }
#pragma unroll
            for (int mi = 0; mi < 4; mi++)
#pragma unroll
                for (int ni = 0; ni < 4; ni++)
                    mma16816(acc[mi][ni], af[mi], bf[ni]);
        }
        __syncthreads();
    }

    // epilogue
    const int er = lane >> 2;
    const int ec = (lane & 3) * 2;
#pragma unroll
    for (int mi = 0; mi < 4; mi++) {
#pragma unroll
        for (int ni = 0; ni < 4; ni++) {
            int m0 = bm + warp_m * 64 + mi * 16 + er;
            int n0 = bn + warp_n * 32 + ni * 8 + ec;
            *(float2*)(C + (size_t)m0 * N + n0) = make_float2(acc[mi][ni][0], acc[mi][ni][1]);
            *(float2*)(C + (size_t)(m0 + 8) * N + n0) = make_float2(acc[mi][ni][2], acc[mi][ni][3]);
        }
    }
}

// ---------------- generic strided/batched/split-K SGEMM (guarded) ----------------
__global__ __launch_bounds__(256) void sgemm_strided(
    const float* __restrict__ A, const float* __restrict__ B, float* __restrict__ C,
    int M, int N, int K, int lda, int ldb, int ldc,
    long batchA, long batchB, long batchC,
    int nsplit, long splitStride)
{
    __shared__ float As[16][128];
    __shared__ float Bs[16][128];

    const int zb = blockIdx.z / nsplit;
    const int zs = blockIdx.z % nsplit;
    A += (long)zb * batchA;
    B += (long)zb * batchB;
    C += (long)zb * batchC + (long)zs * splitStride;
    const int Kc = K / nsplit;
    const int kbeg = zs * Kc;

    const int tid = threadIdx.x;
    const int bm = blockIdx.y * 128;
    const int bn = blockIdx.x * 128;
    const int tx = tid & 15;
    const int ty = tid >> 4;
    const int lrow = tid >> 2;
    const int lcol = (tid & 3) << 2;

    float acc[8][8];
#pragma unroll
    for (int i = 0; i < 8; i++)
#pragma unroll
        for (int j = 0; j < 8; j++) acc[i][j] = 0.f;

    for (int k0 = 0; k0 < Kc; k0 += 16) {
        const int kk = kbeg + k0;
#pragma unroll
        for (int i = 0; i < 2; i++) {
            int r = lrow + i * 64;
            float4 va = make_float4(0.f, 0.f, 0.f, 0.f);
            float4 vb = make_float4(0.f, 0.f, 0.f, 0.f);
            if (bm + r < M) va = *(const float4*)(A + (size_t)(bm + r) * lda + kk + lcol);
            if (bn + r < N) vb = *(const float4*)(B + (size_t)(bn + r) * ldb + kk + lcol);
            As[lcol + 0][r] = va.x; As[lcol + 1][r] = va.y;
            As[lcol + 2][r] = va.z; As[lcol + 3][r] = va.w;
            Bs[lcol + 0][r] = vb.x; Bs[lcol + 1][r] = vb.y;
            Bs[lcol + 2][r] = vb.z; Bs[lcol + 3][r] = vb.w;
        }
        __syncthreads();
#pragma unroll
        for (int k = 0; k < 16; k++) {
            float4 a0 = *(const float4*)&As[k][ty * 4];
            float4 a1 = *(const float4*)&As[k][64 + ty * 4];
            float4 b0 = *(const float4*)&Bs[k][tx * 4];
            float4 b1 = *(const float4*)&Bs[k][64 + tx * 4];
            float a[8] = {a0.x, a0.y, a0.z, a0.w, a1.x, a1.y, a1.z, a1.w};
            float b[8] = {b0.x, b0.y, b0.z, b0.w, b1.x, b1.y, b1.z, b1.w};
#pragma unroll
            for (int i = 0; i < 8; i++)
#pragma unroll
                for (int j = 0; j < 8; j++)
                    acc[i][j] = fmaf(a[i], b[j], acc[i][j]);
        }
        __syncthreads();
    }

#pragma unroll
    for (int i = 0; i < 8; i++) {
        int r = bm + ((i < 4) ? (ty * 4 + i) : (60 + ty * 4 + i));
        if (r >= M) continue;
#pragma unroll
        for (int j = 0; j < 8; j++) {
            int c = bn + ((j < 4) ? (tx * 4 + j) : (60 + tx * 4 + j));
            if (c < N) C[(size_t)r * ldc + c] = acc[i][j];
        }
    }
}

// ---------------- split-K reduce ----------------
__global__ void reduce_kernel(const float* __restrict__ part, float* __restrict__ out,
                              int n, int nsplit)
{
    int i = blockIdx.x * blockDim.x + threadIdx.x;
    if (i >= n) return;
    float s = 0.f;
    for (int k = 0; k < nsplit; k++) s += part[(size_t)k * n + i];
    out[i] = s;
}

// ---------------- batched tiled transpose ----------------
__global__ void transpose_k(const float* __restrict__ in, float* __restrict__ out,
                            int R, int C, long bIn, long bOut)
{
    __shared__ float t[32][33];
    in  += (long)blockIdx.z * bIn;
    out += (long)blockIdx.z * bOut;
    int x = blockIdx.x * 32 + threadIdx.x;
    for (int i = threadIdx.y; i < 32; i += 8) {
        int y = blockIdx.y * 32 + i;
        if (y < R && x < C) t[i][threadIdx.x] = in[(size_t)y * C + x];
    }
    __syncthreads();
    int x2 = blockIdx.y * 32 + threadIdx.x;
    for (int i = threadIdx.y; i < 32; i += 8) {
        int y2 = blockIdx.x * 32 + i;
        if (y2 < C && x2 < R) out[(size_t)y2 * R + x2] = t[threadIdx.x][i];
    }
}

// ---------------- row sums for the reciprocal band term ----------------
__global__ void sums_kernel(const float* __restrict__ qlat,
                            const float* __restrict__ lk,
                            float* __restrict__ qsum, float* __restrict__ ksum)
{
    int i = blockIdx.x * blockDim.x + threadIdx.x;
    if (i < T_SEQ * NH) {
        float s = 0.f;
#pragma unroll 8
        for (int l = 0; l < LAT; l++) s += qlat[(size_t)i * LAT + l];
        qsum[i] = s;
    }
    if (i < T_SEQ) {
        float s = 0.f;
#pragma unroll 8
        for (int l = 0; l < LAT; l++) s += lk[(size_t)i * LAT + l];
        ksum[i] = s;
    }
}

// ---------------- causal flash attention in latent space ----------------
__global__ __launch_bounds__(256) void flash_kernel(
    const float* __restrict__ qlat, const float* __restrict__ lk,
    const float* __restrict__ lv, const float* __restrict__ qsum,
    const float* __restrict__ ksum, float* __restrict__ lctx)
{
    extern __shared__ float smf[];
    float* Qs = smf;                // 64 x (stride 65)
    float* Ks = Qs + 64 * 65;
    float* Ss = Ks + 64 * 65;       // stride 68
    float* Vs = Ss + 64 * 68;       // stride 68
    __shared__ float qss[64];
    __shared__ float kss[64];
    __shared__ float s_alpha[64];
    __shared__ float s_linv[64];

    const int h = blockIdx.y;
    const int qb = gridDim.x - 1 - blockIdx.x;
    const int q0 = qb * 64;
    const int tid = threadIdx.x;

    const int sy = tid >> 4, sx = tid & 15;
    const int row = tid >> 2, qd = tid & 3;

    for (int i = tid; i < 64 * 16; i += 256) {
        int r = i >> 4, c = (i & 15) << 2;
        float4 v = *(const float4*)(qlat + (size_t)(q0 + r) * (NH * LAT) + h * LAT + c);
        Qs[r * 65 + c + 0] = v.x; Qs[r * 65 + c + 1] = v.y;
        Qs[r * 65 + c + 2] = v.z; Qs[r * 65 + c + 3] = v.w;
    }
    if (tid < 64) qss[tid] = qsum[(size_t)(q0 + tid) * NH + h];

    float4 Oc[4];
#pragma unroll
    for (int r = 0; r < 4; r++) Oc[r] = make_float4(0.f, 0.f, 0.f, 0.f);
    float m_run = -1e30f, l_run = 0.f;
    __syncthreads();

    for (int kb = 0; kb <= qb; kb++) {
        const int s0 = kb * 64;
        for (int i = tid; i < 64 * 16; i += 256) {
            int r = i >> 4, c = (i & 15) << 2;
            float4 k4 = *(const float4*)(lk + (size_t)(s0 + r) * LAT + c);
            Ks[r * 65 + c + 0] = k4.x; Ks[r * 65 + c + 1] = k4.y;
            Ks[r * 65 + c + 2] = k4.z; Ks[r * 65 + c + 3] = k4.w;
            float4 v4 = *(const float4*)(lv + (size_t)(s0 + r) * LAT + c);
            Vs[r * 68 + c + 0] = v4.x; Vs[r * 68 + c + 1] = v4.y;
            Vs[r * 68 + c + 2] = v4.z; Vs[r * 68 + c + 3] = v4.w;
        }
        if (tid < 64) kss[tid] = ksum[s0 + tid];
        __syncthreads();

        float sacc[4][4];
#pragma unroll
        for (int i = 0; i < 4; i++)
#pragma unroll
            for (int j = 0; j < 4; j++) sacc[i][j] = 0.f;
#pragma unroll 4
        for (int l = 0; l < 64; l++) {
            float qa[4], kk[4];
#pragma unroll
            for (int i = 0; i < 4; i++) qa[i] = Qs[(sy * 4 + i) * 65 + l];
#pragma unroll
            for (int j = 0; j < 4; j++) kk[j] = Ks[(sx * 4 + j) * 65 + l];
#pragma unroll
            for (int i = 0; i < 4; i++)
#pragma unroll
                for (int j = 0; j < 4; j++)
                    sacc[i][j] = fmaf(qa[i], kk[j], sacc[i][j]);
        }
#pragma unroll
        for (int i = 0; i < 4; i++) {
#pragma unroll
            for (int j = 0; j < 4; j++) {
                int li = sy * 4 + i, lj = sx * 4 + j;
                int gi = q0 + li, gj = s0 + lj;
                float v = -1e30f;
                if (gj <= gi) {
                    v = sacc[i][j] * 0.125f;
                    if (gi - gj <= 64)
                        v += 0.0625f * qss[li] * kss[lj];
                }
                Ss[li * 68 + lj] = v;
            }
        }
        __syncthreads();

        float mx = -1e30f;
        for (int j = qd * 16; j < qd * 16 + 16; j++)
            mx = fmaxf(mx, Ss[row * 68 + j]);
        mx = fmaxf(mx, __shfl_xor_sync(0xffffffffu, mx, 1));
        mx = fmaxf(mx, __shfl_xor_sync(0xffffffffu, mx, 2));
        float m_new = fmaxf(m_run, mx);
        float alpha = __expf(m_run - m_new);
        float ps = 0.f;
        for (int j = qd * 16; j < qd * 16 + 16; j++) {
            float p = __expf(Ss[row * 68 + j] - m_new);
            Ss[row * 68 + j] = p;
            ps += p;
        }
        ps += __shfl_xor_sync(0xffffffffu, ps, 1);
        ps += __shfl_xor_sync(0xffffffffu, ps, 2);
        l_run = l_run * alpha + ps;
        m_run = m_new;
        if (qd == 0) s_alpha[row] = alpha;
        __syncthreads();

#pragma unroll
        for (int r = 0; r < 4; r++) {
            float a = s_alpha[sy * 4 + r];
            Oc[r].x *= a; Oc[r].y *= a; Oc[r].z *= a; Oc[r].w *= a;
        }
        for (int j = 0; j < 64; j++) {
            float4 bv = *(const float4*)&Vs[j * 68 + sx * 4];
#pragma unroll
            for (int r = 0; r < 4; r++) {
                float p = Ss[(sy * 4 + r) * 68 + j];
                Oc[r].x = fmaf(p, bv.x, Oc[r].x);
                Oc[r].y = fmaf(p, bv.y, Oc[r].y);
                Oc[r].z = fmaf(p, bv.z, Oc[r].z);
                Oc[r].w = fmaf(p, bv.w, Oc[r].w);
            }
        }
        __syncthreads();
    }

    if (qd == 0) s_linv[row] = 1.f / l_run;
    __syncthreads();

#pragma unroll
    for (int r = 0; r < 4; r++) {
        float s = s_linv[sy * 4 + r];
        int t = q0 + sy * 4 + r;
        float4 o = Oc[r];
        o.x *= s; o.y *= s; o.z *= s; o.w *= s;
        *(float4*)(lctx + (size_t)t * (NH * LAT) + h * LAT + sx * 4) = o;
    }
}

// ---------------- host launcher ----------------
extern "C" void kernel_launch(void* const* d_in, const int* in_sizes, int n_in,
                              void* d_out, int out_size)
{
    const float* hidden = (const float*)d_in[0];
    const float* Wq  = (const float*)d_in[1];
    const float* Wk  = (const float*)d_in[2];
    const float* Wv  = (const float*)d_in[3];
    const float* q2l = (const float*)d_in[4];
    const float* vup = (const float*)d_in[5];
    const float* Wo  = (const float*)d_in[6];
    float* out = (float*)d_out;

    float *WqT, *q2lT, *Wf1, *Wf2T, *lk, *lv, *lpart, *qlat, *qs, *ks, *lctx;
    __nv_bfloat16 *hid3, *Wf13, *Wf23, *lctx3;
    cudaGetSymbolAddress((void**)&WqT,   g_WqT);
    cudaGetSymbolAddress((void**)&q2lT,  g_q2lT);
    cudaGetSymbolAddress((void**)&Wf1,   g_Wf1);
    cudaGetSymbolAddress((void**)&Wf2T,  g_Wf2T);
    cudaGetSymbolAddress((void**)&lk,    g_lk);
    cudaGetSymbolAddress((void**)&lv,    g_lv);
    cudaGetSymbolAddress((void**)&lpart, g_lpart);
    cudaGetSymbolAddress((void**)&qlat,  g_qlat);
    cudaGetSymbolAddress((void**)&qs,    g_qsum);
    cudaGetSymbolAddress((void**)&ks,    g_ksum);
    cudaGetSymbolAddress((void**)&lctx,  g_lctx);
    cudaGetSymbolAddress((void**)&hid3,  g_hid3);
    cudaGetSymbolAddress((void**)&Wf13,  g_Wf13);
    cudaGetSymbolAddress((void**)&Wf23,  g_Wf23);
    cudaGetSymbolAddress((void**)&lctx3, g_lctx3);

    const int flash_smem = (64 * 65 * 2 + 64 * 68 * 2) * 4;  // 68096
    cudaFuncSetAttribute(flash_kernel,
                         cudaFuncAttributeMaxDynamicSharedMemorySize, flash_smem);
    cudaFuncSetAttribute(hmma_gemm,
                         cudaFuncAttributeMaxDynamicSharedMemorySize, HMMA_SMEM);

    // --- weight preprocessing ---
    transpose_k<<<dim3(64, 64, 1), dim3(32, 8)>>>(Wq, WqT, EMB, EMB, 0, 0);
    transpose_k<<<dim3(2, 4, NH), dim3(32, 8)>>>(q2l, q2lT, HD, LAT,
                                                 (long)HD * LAT, (long)LAT * HD);
    sgemm_strided<<<dim3(16, 1, NH), 256>>>(
        q2lT, WqT, Wf1, LAT, EMB, HD, HD, EMB, EMB,
        (long)LAT * HD, (long)HD, (long)LAT * EMB, 1, 0);
    sgemm_strided<<<dim3(1, 16, NH), 256>>>(
        Wo, vup, Wf2T, EMB, LAT, HD, EMB, HD, NH * LAT,
        (long)HD, (long)LAT * HD, (long)LAT, 1, 0);

    // --- latent K / V via deterministic split-K ---
    sgemm_strided<<<dim3(1, 16, 8), 256>>>(
        hidden, Wk, lpart, T_SEQ, LAT, EMB, EMB, EMB, LAT,
        0, 0, 0, 8, (long)T_SEQ * LAT);
    reduce_kernel<<<(T_SEQ * LAT + 255) / 256, 256>>>(lpart, lk, T_SEQ * LAT, 8);
    sgemm_strided<<<dim3(1, 16, 8), 256>>>(
        hidden, Wv, lpart, T_SEQ, LAT, EMB, EMB, EMB, LAT,
        0, 0, 0, 8, (long)T_SEQ * LAT);
    reduce_kernel<<<(T_SEQ * LAT + 255) / 256, 256>>>(lpart, lv, T_SEQ * LAT, 8);

    // --- K-extended bf16 split conversions ---
    // A-side: [hi | lo | hi]; B-side: [hi | hi | lo]
    cvt_split3<<<(T_SEQ * EMB / 4 + 255) / 256, 256>>>(
        hidden, hid3, T_SEQ * EMB, EMB, 2 * EMB, EMB);
    cvt_split3<<<(NH * LAT * EMB / 4 + 255) / 256, 256>>>(
        Wf1, Wf13, NH * LAT * EMB, EMB, EMB, 2 * EMB);
    cvt_split3<<<(EMB * NH * LAT / 4 + 255) / 256, 256>>>(
        Wf2T, Wf23, EMB * NH * LAT, NH * LAT, NH * LAT, 2 * NH * LAT);

    // --- q_latent = hidden @ Wf1^T  [2048 x 1024]  (HMMA bf16, K'=6144) ---
    hmma_gemm<<<dim3(8, 16), 256, HMMA_SMEM>>>(hid3, Wf13, qlat,
                                               T_SEQ, NH * LAT, 3 * EMB);

    // --- row sums for reciprocal band ---
    sums_kernel<<<128, 256>>>(qlat, lk, qs, ks);

    // --- causal flash attention in latent space ---
    flash_kernel<<<dim3(32, NH), 256, flash_smem>>>(qlat, lk, lv, qs, ks, lctx);

    // --- out = lctx @ Wf2T^T  [2048 x 2048]  (HMMA bf16, K'=3072) ---
    cvt_split3<<<(T_SEQ * NH * LAT / 4 + 255) / 256, 256>>>(
        lctx, lctx3, T_SEQ * NH * LAT, NH * LAT, 2 * NH * LAT, NH * LAT);
    hmma_gemm<<<dim3(16, 16), 256, HMMA_SMEM>>>(lctx3, Wf23, out,
                                                T_SEQ, EMB, 3 * NH * LAT);
}

// round 7
// speedup vs baseline: 3.0614x; 1.0929x over previous
#include <cuda_runtime.h>
#include <cuda_bf16.h>
#include <cstdint>

#define T_SEQ 2048
#define EMB   2048
#define NH    16
#define HD    128
#define LAT   64

// ---------------- scratch (static device globals; no allocation) ----------------
__device__ float g_WqT[EMB * EMB];
__device__ float g_q2lT[NH * LAT * HD];
__device__ float g_Wf1[NH * LAT * EMB];
__device__ float g_Wf2T[EMB * NH * LAT];
__device__ float g_lkv[T_SEQ * 2 * LAT];           // [t][ lk(64) | lv(64) ]
__device__ float g_qlat[T_SEQ * NH * LAT];
__device__ float g_qsum[T_SEQ * NH];
__device__ float g_ksum[T_SEQ];
// bf16 K-extended split buffers
__device__ __align__(16) __nv_bfloat16 g_hid3 [T_SEQ * 3 * EMB];        // A [hi|lo|hi]
__device__ __align__(16) __nv_bfloat16 g_Wf13 [NH * LAT * 3 * EMB];     // B [hi|hi|lo]
__device__ __align__(16) __nv_bfloat16 g_Wf23 [EMB * 3 * NH * LAT];     // B [hi|hi|lo]
__device__ __align__(16) __nv_bfloat16 g_Wkv3 [2 * LAT * 3 * EMB];      // B [hi|hi|lo]
__device__ __align__(16) __nv_bfloat16 g_qlat3[T_SEQ * NH * 3 * LAT];   // A [hi|lo|hi]
__device__ __align__(16) __nv_bfloat16 g_lk3  [T_SEQ * 3 * LAT];        // B [hi|hi|lo]
__device__ __align__(16) __nv_bfloat16 g_lvTh [LAT * T_SEQ];            // V^T hi
__device__ __align__(16) __nv_bfloat16 g_lvTl [LAT * T_SEQ];            // V^T lo
__device__ __align__(16) __nv_bfloat16 g_lctx3[T_SEQ * 3 * NH * LAT];   // A [hi|lo|hi]

// ================= PTX helpers (baseline compute_103-safe only) =================
__device__ __forceinline__ uint32_t smem_u32(const void* p) {
    uint32_t a;
    asm("{ .reg .u64 t; cvta.to.shared.u64 t, %1; cvt.u32.u64 %0, t; }" : "=r"(a) : "l"(p));
    return a;
}
#define CP_ASYNC16(dst, src) \
    asm volatile("cp.async.cg.shared.global [%0], [%1], 16;" :: "r"(dst), "l"(src))
#define CP_COMMIT() asm volatile("cp.async.commit_group;")
#define CP_WAIT1()  asm volatile("cp.async.wait_group 1;")
#define CP_WAIT0()  asm volatile("cp.async.wait_group 0;")

__device__ __forceinline__ void ldmx4(uint32_t& r0, uint32_t& r1, uint32_t& r2, uint32_t& r3,
                                      uint32_t addr) {
    asm volatile("ldmatrix.sync.aligned.m8n8.x4.shared.b16 {%0,%1,%2,%3}, [%4];"
                 : "=r"(r0), "=r"(r1), "=r"(r2), "=r"(r3) : "r"(addr));
}
__device__ __forceinline__ void mma16816(float* d, const uint32_t* a, const uint32_t* b) {
    asm volatile("mma.sync.aligned.m16n8k16.row.col.f32.bf16.bf16.f32 "
                 "{%0,%1,%2,%3}, {%4,%5,%6,%7}, {%8,%9}, {%0,%1,%2,%3};"
                 : "+f"(d[0]), "+f"(d[1]), "+f"(d[2]), "+f"(d[3])
                 : "r"(a[0]), "r"(a[1]), "r"(a[2]), "r"(a[3]), "r"(b[0]), "r"(b[1]));
}

// ---------------- fp32 -> K-extended bf16 hi/lo split ----------------
// rows of length K, out row stride 3K; hi at [c] and [offH2+c]; lo at [offL+c]
__global__ void cvt_split3(const float* __restrict__ x, __nv_bfloat16* __restrict__ out,
                           int total, int K, int offH2, int offL)
{
    int i = (blockIdx.x * blockDim.x + threadIdx.x) * 4;
    if (i >= total) return;
    float4 v = *(const float4*)(x + i);
    float vv[4] = {v.x, v.y, v.z, v.w};
    __nv_bfloat16 hb[4], lb[4];
#pragma unroll
    for (int k = 0; k < 4; k++) {
        hb[k] = __float2bfloat16(vv[k]);
        lb[k] = __float2bfloat16(vv[k] - __bfloat162float(hb[k]));
    }
    int r = i / K, c = i - r * K;
    size_t base = (size_t)r * 3 * K + c;
    *(uint2*)(out + base)         = *(uint2*)hb;
    *(uint2*)(out + base + offH2) = *(uint2*)hb;
    *(uint2*)(out + base + offL)  = *(uint2*)lb;
}

// ============== HMMA bf16 GEMM: C[M,N] fp32 = A[M,K] @ B[N,K]^T ==============
#define GS 72
#define STAGE_ELTS (128 * GS)
#define HMMA_SMEM (3 * 2 * STAGE_ELTS * 2)

__global__ __launch_bounds__(256) void hmma_gemm(
    const __nv_bfloat16* __restrict__ A, const __nv_bfloat16* __restrict__ B,
    float* __restrict__ C, int M, int N, int K)
{
    extern __shared__ __align__(16) __nv_bfloat16 sm[];
    const int tid = threadIdx.x;
    const int wid = tid >> 5;
    const int lane = tid & 31;
    const int warp_m = wid >> 2;
    const int warp_n = wid & 3;
    const int bm = blockIdx.y * 128;
    const int bn = blockIdx.x * 128;
    const uint32_t sbase = smem_u32(sm);

    const int nk = K >> 6;

    auto load_stage = [&](int stage, int k0) {
        __nv_bfloat16* As = sm + stage * 2 * STAGE_ELTS;
        __nv_bfloat16* Bs = As + STAGE_ELTS;
#pragma unroll
        for (int i = 0; i < 4; i++) {
            int c = tid + i * 256;
            int row = c >> 3;
            int col8 = (c & 7) * 8;
            CP_ASYNC16(smem_u32(As + row * GS + col8), A + (size_t)(bm + row) * K + k0 + col8);
            CP_ASYNC16(smem_u32(Bs + row * GS + col8), B + (size_t)(bn + row) * K + k0 + col8);
        }
    };

    float acc[4][4][4];
#pragma unroll
    for (int mi = 0; mi < 4; mi++)
#pragma unroll
        for (int ni = 0; ni < 4; ni++)
#pragma unroll
            for (int r = 0; r < 4; r++) acc[mi][ni][r] = 0.f;

    load_stage(0, 0); CP_COMMIT();
    if (nk > 1) { load_stage(1, 64); CP_COMMIT(); }

    const int a_row = (lane & 15);
    const int a_koff = (lane >> 4) * 8;
    const int b_row = (lane & 7) + ((lane >> 4) & 1) * 8;
    const int b_koff = ((lane >> 3) & 1) * 8;

    for (int it = 0; it < nk; it++) {
        CP_WAIT1();
        __syncthreads();
        if (it + 2 < nk) { load_stage((it + 2) % 3, (it + 2) * 64); CP_COMMIT(); }

        const int stage = it % 3;
        const uint32_t sA = sbase + (uint32_t)(stage * 2 * STAGE_ELTS) * 2;
        const uint32_t sB = sA + STAGE_ELTS * 2;

#pragma unroll
        for (int kk = 0; kk < 64; kk += 16) {
            uint32_t af[4][4];
#pragma unroll
            for (int mi = 0; mi < 4; mi++) {
                uint32_t addr = sA + ((warp_m * 64 + mi * 16 + a_row) * GS + kk + a_koff) * 2;
                ldmx4(af[mi][0], af[mi][1], af[mi][2], af[mi][3], addr);
            }
            uint32_t bf[4][2];
#pragma unroll
            for (int ni2 = 0; ni2 < 2; ni2++) {
                uint32_t addr = sB + ((warp_n * 32 + ni2 * 16 + b_row) * GS + kk + b_koff) * 2;
                uint32_t r0, r1, r2, r3;
                ldmx4(r0, r1, r2, r3, addr);
                bf[ni2 * 2 + 0][0] = r0; bf[ni2 * 2 + 0][1] = r1;
                bf[ni2 * 2 + 1][0] = r2; bf[ni2 * 2 + 1][1] = r3;
            }
#pragma unroll
            for (int mi = 0; mi < 4; mi++)
#pragma unroll
                for (int ni = 0; ni < 4; ni++)
                    mma16816(acc[mi][ni], af[mi], bf[ni]);
        }
        __syncthreads();
    }

    const int er = lane >> 2;
    const int ec = (lane & 3) * 2;
#pragma unroll
    for (int mi = 0; mi < 4; mi++) {
#pragma unroll
        for (int ni = 0; ni < 4; ni++) {
            int m0 = bm + warp_m * 64 + mi * 16 + er;
            int n0 = bn + warp_n * 32 + ni * 8 + ec;
            *(float2*)(C + (size_t)m0 * N + n0) = make_float2(acc[mi][ni][0], acc[mi][ni][1]);
            *(float2*)(C + (size_t)(m0 + 8) * N + n0) = make_float2(acc[mi][ni][2], acc[mi][ni][3]);
        }
    }
}

// ---------------- generic strided/batched SGEMM (folds only) ----------------
__global__ __launch_bounds__(256) void sgemm_strided(
    const float* __restrict__ A, const float* __restrict__ B, float* __restrict__ C,
    int M, int N, int K, int lda, int ldb, int ldc,
    long batchA, long batchB, long batchC)
{
    __shared__ float As[16][128];
    __shared__ float Bs[16][128];

    const int zb = blockIdx.z;
    A += (long)zb * batchA;
    B += (long)zb * batchB;
    C += (long)zb * batchC;

    const int tid = threadIdx.x;
    const int bm = blockIdx.y * 128;
    const int bn = blockIdx.x * 128;
    const int tx = tid & 15;
    const int ty = tid >> 4;
    const int lrow = tid >> 2;
    const int lcol = (tid & 3) << 2;

    float acc[8][8];
#pragma unroll
    for (int i = 0; i < 8; i++)
#pragma unroll
        for (int j = 0; j < 8; j++) acc[i][j] = 0.f;

    for (int k0 = 0; k0 < K; k0 += 16) {
#pragma unroll
        for (int i = 0; i < 2; i++) {
            int r = lrow + i * 64;
            float4 va = make_float4(0.f, 0.f, 0.f, 0.f);
            float4 vb = make_float4(0.f, 0.f, 0.f, 0.f);
            if (bm + r < M) va = *(const float4*)(A + (size_t)(bm + r) * lda + k0 + lcol);
            if (bn + r < N) vb = *(const float4*)(B + (size_t)(bn + r) * ldb + k0 + lcol);
            As[lcol + 0][r] = va.x; As[lcol + 1][r] = va.y;
            As[lcol + 2][r] = va.z; As[lcol + 3][r] = va.w;
            Bs[lcol + 0][r] = vb.x; Bs[lcol + 1][r] = vb.y;
            Bs[lcol + 2][r] = vb.z; Bs[lcol + 3][r] = vb.w;
        }
        __syncthreads();
#pragma unroll
        for (int k = 0; k < 16; k++) {
            float4 a0 = *(const float4*)&As[k][ty * 4];
            float4 a1 = *(const float4*)&As[k][64 + ty * 4];
            float4 b0 = *(const float4*)&Bs[k][tx * 4];
            float4 b1 = *(const float4*)&Bs[k][64 + tx * 4];
            float a[8] = {a0.x, a0.y, a0.z, a0.w, a1.x, a1.y, a1.z, a1.w};
            float b[8] = {b0.x, b0.y, b0.z, b0.w, b1.x, b1.y, b1.z, b1.w};
#pragma unroll
            for (int i = 0; i < 8; i++)
#pragma unroll
                for (int j = 0; j < 8; j++)
                    acc[i][j] = fmaf(a[i], b[j], acc[i][j]);
        }
        __syncthreads();
    }

#pragma unroll
    for (int i = 0; i < 8; i++) {
        int r = bm + ((i < 4) ? (ty * 4 + i) : (60 + ty * 4 + i));
        if (r >= M) continue;
#pragma unroll
        for (int j = 0; j < 8; j++) {
            int c = bn + ((j < 4) ? (tx * 4 + j) : (60 + tx * 4 + j));
            if (c < N) C[(size_t)r * ldc + c] = acc[i][j];
        }
    }
}

// ---------------- batched tiled transpose ----------------
__global__ void transpose_k(const float* __restrict__ in, float* __restrict__ out,
                            int R, int C, long bIn, long bOut)
{
    __shared__ float t[32][33];
    in  += (long)blockIdx.z * bIn;
    out += (long)blockIdx.z * bOut;
    int x = blockIdx.x * 32 + threadIdx.x;
    for (int i = threadIdx.y; i < 32; i += 8) {
        int y = blockIdx.y * 32 + i;
        if (y < R && x < C) t[i][threadIdx.x] = in[(size_t)y * C + x];
    }
    __syncthreads();
    int x2 = blockIdx.y * 32 + threadIdx.x;
    for (int i = threadIdx.y; i < 32; i += 8) {
        int y2 = blockIdx.x * 32 + i;
        if (y2 < C && x2 < R) out[(size_t)y2 * R + x2] = t[threadIdx.x][i];
    }
}

// ---- cvt_kv: from lkv [T][128] build lk3 [T][192], lvTh/lvTl [64][T], ksum ----
__global__ __launch_bounds__(256) void cvt_kv(
    const float* __restrict__ lkv, __nv_bfloat16* __restrict__ lk3,
    __nv_bfloat16* __restrict__ lvTh, __nv_bfloat16* __restrict__ lvTl,
    float* __restrict__ ksum)
{
    __shared__ __nv_bfloat16 vh[64][65], vl[64][65];
    const int t0 = blockIdx.x * 64;
    const int tid = threadIdx.x;
    for (int i = tid; i < 64 * 64; i += 256) {
        int r = i >> 6, l = i & 63;
        float v = lkv[(size_t)(t0 + r) * 128 + 64 + l];
        __nv_bfloat16 h = __float2bfloat16(v);
        vh[l][r] = h;
        vl[l][r] = __float2bfloat16(v - __bfloat162float(h));
        float kv = lkv[(size_t)(t0 + r) * 128 + l];
        __nv_bfloat16 kh = __float2bfloat16(kv);
        __nv_bfloat16 kl = __float2bfloat16(kv - __bfloat162float(kh));
        lk3[(size_t)(t0 + r) * 192 + l]       = kh;
        lk3[(size_t)(t0 + r) * 192 + 64 + l]  = kh;
        lk3[(size_t)(t0 + r) * 192 + 128 + l] = kl;
    }
    __syncthreads();
    for (int i = tid; i < 64 * 64; i += 256) {
        int l = i >> 6, r = i & 63;
        lvTh[(size_t)l * T_SEQ + t0 + r] = vh[l][r];
        lvTl[(size_t)l * T_SEQ + t0 + r] = vl[l][r];
    }
    if (tid < 64) {
        float s = 0.f;
#pragma unroll 8
        for (int l = 0; l < 64; l++) s += lkv[(size_t)(t0 + tid) * 128 + l];
        ksum[t0 + tid] = s;
    }
}

// ---------------- qsum ----------------
__global__ void qsum_kernel(const float* __restrict__ qlat, float* __restrict__ qsum)
{
    int i = blockIdx.x * blockDim.x + threadIdx.x;
    if (i >= T_SEQ * NH) return;
    float s = 0.f;
#pragma unroll 8
    for (int l = 0; l < LAT; l++) s += qlat[(size_t)i * LAT + l];
    qsum[i] = s;
}

// ========== HMMA causal flash attention in latent space (K' = 192) ==========
// grid (T/64, H), 256 threads = 8 warps, warp tile 16x32.
#define FGS 200
#define FLASH_SMEM ((64 * FGS * 6) * 2 + 64 * 68 * 4)   // 171008

__global__ __launch_bounds__(256) void flash_hmma(
    const __nv_bfloat16* __restrict__ qlat3, const __nv_bfloat16* __restrict__ lk3,
    const __nv_bfloat16* __restrict__ lvTh, const __nv_bfloat16* __restrict__ lvTl,
    const float* __restrict__ qsum, const float* __restrict__ ksum,
    __nv_bfloat16* __restrict__ lctx3)
{
    extern __shared__ __align__(16) __nv_bfloat16 smb[];
    __nv_bfloat16* Qs = smb;                       // 64*FGS
    __nv_bfloat16* Ks = Qs + 64 * FGS;             // 2 bufs
    __nv_bfloat16* VT = Ks + 2 * 64 * FGS;         // 2 bufs
    __nv_bfloat16* Ps = VT + 2 * 64 * FGS;         // 64*FGS
    float* Ss = (float*)(Ps + 64 * FGS);           // 64*68
    __shared__ float qss[64], kss[64], s_alpha[64], s_linv[64];

    const int h = blockIdx.y;
    const int qb = gridDim.x - 1 - blockIdx.x;     // heavy blocks first
    const int q0 = qb * 64;
    const int tid = threadIdx.x;
    const int lane = tid & 31;
    const int wid = tid >> 5;
    const int rm = (wid >> 1) * 16;                // warp row base
    const int cn = (wid & 1) * 32;                 // warp col base

    const int a_row = lane & 15, a_koff = (lane >> 4) * 8;
    const int b_row = (lane & 7) + ((lane >> 4) & 1) * 8;
    const int b_koff = ((lane >> 3) & 1) * 8;
    const int er = lane >> 2, ec = (lane & 3) * 2;
    const int row = tid >> 2, qd = tid & 3;

    // Q tile (64 rows x 192) via cp.async
    for (int i = tid; i < 64 * 32; i += 256) {
        int r = i >> 5, c = i & 31;
        if (c < 24)
            CP_ASYNC16(smem_u32(Qs + r * FGS + c * 8),
                       qlat3 + ((size_t)(q0 + r) * NH + h) * 192 + c * 8);
    }
    if (tid < 64) qss[tid] = qsum[(size_t)(q0 + tid) * NH + h];

    auto load_kv = [&](int buf, int s0) {
        __nv_bfloat16* ks = Ks + buf * 64 * FGS;
        __nv_bfloat16* vt = VT + buf * 64 * FGS;
        for (int i = tid; i < 64 * 32; i += 256) {
            int r = i >> 5, c = i & 31;
            if (c < 24) {
                CP_ASYNC16(smem_u32(ks + r * FGS + c * 8),
                           lk3 + (size_t)(s0 + r) * 192 + c * 8);
                int seg = c >> 3, c8 = c & 7;
                const __nv_bfloat16* src = (seg < 2) ? lvTh : lvTl;
                CP_ASYNC16(smem_u32(vt + r * FGS + c * 8),
                           src + (size_t)r * T_SEQ + s0 + c8 * 8);
            }
        }
    };

    load_kv(0, 0); CP_COMMIT();

    float acc_o[4][4];
#pragma unroll
    for (int ni = 0; ni < 4; ni++)
#pragma unroll
        for (int r = 0; r < 4; r++) acc_o[ni][r] = 0.f;
    float m_run = -1e30f, l_run = 0.f;

    for (int kb = 0; kb <= qb; kb++) {
        const int buf = kb & 1;
        const int s0 = kb * 64;
        if (kb + 1 <= qb) { load_kv(buf ^ 1, (kb + 1) * 64); CP_COMMIT(); CP_WAIT1(); }
        else              { CP_WAIT0(); }
        if (tid < 64) kss[tid] = ksum[s0 + tid];
        __syncthreads();

        // ---- S = Q3 @ K3^T ----
        const uint32_t sQ = smem_u32(Qs);
        const uint32_t sK = smem_u32(Ks + buf * 64 * FGS);
        float sacc[4][4];
#pragma unroll
        for (int ni = 0; ni < 4; ni++)
#pragma unroll
            for (int r = 0; r < 4; r++) sacc[ni][r] = 0.f;
#pragma unroll
        for (int kk = 0; kk < 192; kk += 16) {
            uint32_t af[4];
            ldmx4(af[0], af[1], af[2], af[3], sQ + ((rm + a_row) * FGS + kk + a_koff) * 2);
            uint32_t bfr[4][2];
#pragma unroll
            for (int n2 = 0; n2 < 2; n2++) {
                uint32_t r0, r1, r2, r3;
                ldmx4(r0, r1, r2, r3, sK + ((cn + n2 * 16 + b_row) * FGS + kk + b_koff) * 2);
                bfr[n2 * 2 + 0][0] = r0; bfr[n2 * 2 + 0][1] = r1;
                bfr[n2 * 2 + 1][0] = r2; bfr[n2 * 2 + 1][1] = r3;
            }
#pragma unroll
            for (int ni = 0; ni < 4; ni++) mma16816(sacc[ni], af, bfr[ni]);
        }
        // frag -> Ss with mask + band
#pragma unroll
        for (int ni = 0; ni < 4; ni++) {
#pragma unroll
            for (int rr = 0; rr < 2; rr++) {
                int li = rm + er + rr * 8;
                int gi = q0 + li;
#pragma unroll
                for (int cc = 0; cc < 2; cc++) {
                    int jj = cn + ni * 8 + ec + cc;
                    int gj = s0 + jj;
                    float v = -1e30f;
                    if (gj <= gi) {
                        v = sacc[ni][rr * 2 + cc] * 0.125f;
                        if (gi - gj <= 64) v += 0.0625f * qss[li] * kss[jj];
                    }
                    Ss[li * 68 + jj] = v;
                }
            }
        }
        __syncthreads();

        // ---- online softmax (4 lanes / row), write P split into Ps ----
        float mx = -1e30f;
        for (int j = qd * 16; j < qd * 16 + 16; j++)
            mx = fmaxf(mx, Ss[row * 68 + j]);
        mx = fmaxf(mx, __shfl_xor_sync(0xffffffffu, mx, 1));
        mx = fmaxf(mx, __shfl_xor_sync(0xffffffffu, mx, 2));
        float m_new = fmaxf(m_run, mx);
        float alpha = __expf(m_run - m_new);
        float ps = 0.f;
        for (int j = qd * 16; j < qd * 16 + 16; j++) {
            float p = __expf(Ss[row * 68 + j] - m_new);
            ps += p;
            __nv_bfloat16 ph = __float2bfloat16(p);
            __nv_bfloat16 pl = __float2bfloat16(p - __bfloat162float(ph));
            Ps[row * FGS + j] = ph;
            Ps[row * FGS + 64 + j] = pl;
            Ps[row * FGS + 128 + j] = ph;
        }
        ps += __shfl_xor_sync(0xffffffffu, ps, 1);
        ps += __shfl_xor_sync(0xffffffffu, ps, 2);
        l_run = l_run * alpha + ps;
        m_run = m_new;
        if (qd == 0) s_alpha[row] = alpha;
        __syncthreads();

        // ---- O = O*alpha + P3 @ V3^T ----
        {
            float a0 = s_alpha[rm + er], a1 = s_alpha[rm + er + 8];
#pragma unroll
            for (int ni = 0; ni < 4; ni++) {
                acc_o[ni][0] *= a0; acc_o[ni][1] *= a0;
                acc_o[ni][2] *= a1; acc_o[ni][3] *= a1;
            }
        }
        const uint32_t sP = smem_u32(Ps);
        const uint32_t sV = smem_u32(VT + buf * 64 * FGS);
#pragma unroll
        for (int kk = 0; kk < 192; kk += 16) {
            uint32_t af[4];
            ldmx4(af[0], af[1], af[2], af[3], sP + ((rm + a_row) * FGS + kk + a_koff) * 2);
            uint32_t bfr[4][2];
#pragma unroll
            for (int n2 = 0; n2 < 2; n2++) {
                uint32_t r0, r1, r2, r3;
                ldmx4(r0, r1, r2, r3, sV + ((cn + n2 * 16 + b_row) * FGS + kk + b_koff) * 2);
                bfr[n2 * 2 + 0][0] = r0; bfr[n2 * 2 + 0][1] = r1;
                bfr[n2 * 2 + 1][0] = r2; bfr[n2 * 2 + 1][1] = r3;
            }
#pragma unroll
            for (int ni = 0; ni < 4; ni++) mma16816(acc_o[ni], af, bfr[ni]);
        }
        __syncthreads();
    }

    if (qd == 0) s_linv[row] = 1.f / l_run;
    __syncthreads();

    const float li0 = s_linv[rm + er], li1 = s_linv[rm + er + 8];
#pragma unroll
    for (int ni = 0; ni < 4; ni++) {
        int l0 = cn + ni * 8 + ec;
#pragma unroll
        for (int rr = 0; rr < 2; rr++) {
            int t = q0 + rm + er + rr * 8;
            float sc = rr ? li1 : li0;
            float v0 = acc_o[ni][rr * 2 + 0] * sc;
            float v1 = acc_o[ni][rr * 2 + 1] * sc;
            __nv_bfloat16 h0 = __float2bfloat16(v0);
            __nv_bfloat16 h1 = __float2bfloat16(v1);
            __nv_bfloat162 hp; hp.x = h0; hp.y = h1;
            __nv_bfloat162 lp;
            lp.x = __float2bfloat16(v0 - __bfloat162float(h0));
            lp.y = __float2bfloat16(v1 - __bfloat162float(h1));
            size_t base = (size_t)t * 3072 + h * 64 + l0;
            *(__nv_bfloat162*)(lctx3 + base)        = hp;   // hi
            *(__nv_bfloat162*)(lctx3 + base + 1024) = lp;   // lo
            *(__nv_bfloat162*)(lctx3 + base + 2048) = hp;   // hi
        }
    }
}

// ---------------- host launcher ----------------
extern "C" void kernel_launch(void* const* d_in, const int* in_sizes, int n_in,
                              void* d_out, int out_size)
{
    const float* hidden = (const float*)d_in[0];
    const float* Wq  = (const float*)d_in[1];
    const float* Wk  = (const float*)d_in[2];
    const float* Wv  = (const float*)d_in[3];
    const float* q2l = (const float*)d_in[4];
    const float* vup = (const float*)d_in[5];
    const float* Wo  = (const float*)d_in[6];
    float* out = (float*)d_out;

    float *WqT, *q2lT, *Wf1, *Wf2T, *lkv, *qlat, *qs, *ks;
    __nv_bfloat16 *hid3, *Wf13, *Wf23, *Wkv3, *qlat3, *lk3, *lvTh, *lvTl, *lctx3;
    cudaGetSymbolAddress((void**)&WqT,   g_WqT);
    cudaGetSymbolAddress((void**)&q2lT,  g_q2lT);
    cudaGetSymbolAddress((void**)&Wf1,   g_Wf1);
    cudaGetSymbolAddress((void**)&Wf2T,  g_Wf2T);
    cudaGetSymbolAddress((void**)&lkv,   g_lkv);
    cudaGetSymbolAddress((void**)&qlat,  g_qlat);
    cudaGetSymbolAddress((void**)&qs,    g_qsum);
    cudaGetSymbolAddress((void**)&ks,    g_ksum);
    cudaGetSymbolAddress((void**)&hid3,  g_hid3);
    cudaGetSymbolAddress((void**)&Wf13,  g_Wf13);
    cudaGetSymbolAddress((void**)&Wf23,  g_Wf23);
    cudaGetSymbolAddress((void**)&Wkv3,  g_Wkv3);
    cudaGetSymbolAddress((void**)&qlat3, g_qlat3);
    cudaGetSymbolAddress((void**)&lk3,   g_lk3);
    cudaGetSymbolAddress((void**)&lvTh,  g_lvTh);
    cudaGetSymbolAddress((void**)&lvTl,  g_lvTl);
    cudaGetSymbolAddress((void**)&lctx3, g_lctx3);

    cudaFuncSetAttribute(hmma_gemm,
                         cudaFuncAttributeMaxDynamicSharedMemorySize, HMMA_SMEM);
    cudaFuncSetAttribute(flash_hmma,
                         cudaFuncAttributeMaxDynamicSharedMemorySize, FLASH_SMEM);

    // --- weight preprocessing (FFMA folds; small) ---
    transpose_k<<<dim3(64, 64, 1), dim3(32, 8)>>>(Wq, WqT, EMB, EMB, 0, 0);
    transpose_k<<<dim3(2, 4, NH), dim3(32, 8)>>>(q2l, q2lT, HD, LAT,
                                                 (long)HD * LAT, (long)LAT * HD);
    sgemm_strided<<<dim3(16, 1, NH), 256>>>(
        q2lT, WqT, Wf1, LAT, EMB, HD, HD, EMB, EMB,
        (long)LAT * HD, (long)HD, (long)LAT * EMB);
    sgemm_strided<<<dim3(1, 16, NH), 256>>>(
        Wo, vup, Wf2T, EMB, LAT, HD, EMB, HD, NH * LAT,
        (long)HD, (long)LAT * HD, (long)LAT);

    // --- bf16 splits for hidden / Wk|Wv / Wf1 / Wf2 ---
    cvt_split3<<<(T_SEQ * EMB / 4 + 255) / 256, 256>>>(
        hidden, hid3, T_SEQ * EMB, EMB, 2 * EMB, EMB);                 // A [hi|lo|hi]
    cvt_split3<<<(LAT * EMB / 4 + 255) / 256, 256>>>(
        Wk, Wkv3, LAT * EMB, EMB, EMB, 2 * EMB);                       // B rows 0..63
    cvt_split3<<<(LAT * EMB / 4 + 255) / 256, 256>>>(
        Wv, Wkv3 + (size_t)LAT * 3 * EMB, LAT * EMB, EMB, EMB, 2 * EMB); // rows 64..127
    cvt_split3<<<(NH * LAT * EMB / 4 + 255) / 256, 256>>>(
        Wf1, Wf13, NH * LAT * EMB, EMB, EMB, 2 * EMB);                 // B [hi|hi|lo]
    cvt_split3<<<(EMB * NH * LAT / 4 + 255) / 256, 256>>>(
        Wf2T, Wf23, EMB * NH * LAT, NH * LAT, NH * LAT, 2 * NH * LAT); // B [hi|hi|lo]

    // --- lkv = hidden @ [Wk;Wv]^T  [2048 x 128]  (HMMA) ---
    hmma_gemm<<<dim3(1, 16), 256, HMMA_SMEM>>>(hid3, Wkv3, lkv, T_SEQ, 2 * LAT, 3 * EMB);
    cvt_kv<<<32, 256>>>(lkv, lk3, lvTh, lvTl, ks);

    // --- q_latent = hidden @ Wf1^T  [2048 x 1024]  (HMMA) ---
    hmma_gemm<<<dim3(8, 16), 256, HMMA_SMEM>>>(hid3, Wf13, qlat, T_SEQ, NH * LAT, 3 * EMB);
    cvt_split3<<<(T_SEQ * NH * LAT / 4 + 255) / 256, 256>>>(
        qlat, qlat3, T_SEQ * NH * LAT, LAT, 2 * LAT, LAT);             // A [hi|lo|hi]
    qsum_kernel<<<(T_SEQ * NH + 255) / 256, 256>>>(qlat, qs);

    // --- HMMA causal flash attention (writes lctx3 split directly) ---
    flash_hmma<<<dim3(32, NH), 256, FLASH_SMEM>>>(qlat3, lk3, lvTh, lvTl, qs, ks, lctx3);

    // --- out = lctx @ Wf2T^T  [2048 x 2048]  (HMMA) ---
    hmma_gemm<<<dim3(16, 16), 256, HMMA_SMEM>>>(lctx3, Wf23, out, T_SEQ, EMB, 3 * NH * LAT);
}

// round 8
// speedup vs baseline: 4.4760x; 1.4621x over previous
#include <cuda_runtime.h>
#include <cuda_bf16.h>
#include <cuda_fp16.h>
#include <cstdint>

#define T_SEQ 2048
#define EMB   2048
#define NH    16
#define HD    128
#define LAT   64

// ---------------- scratch (static device globals; no allocation) ----------------
__device__ float g_WqT[EMB * EMB];
__device__ float g_q2lT[NH * LAT * HD];
__device__ float g_Wf1[NH * LAT * EMB];
__device__ float g_Wf2T[EMB * NH * LAT];
__device__ float g_lkv[T_SEQ * 2 * LAT];            // [t][ lk(64) | lv(64) ]
__device__ float g_lpart[8 * T_SEQ * 2 * LAT];      // split-K partials (8 MB)
__device__ float g_qlat[T_SEQ * NH * LAT];
__device__ float g_qsum[T_SEQ * NH];
__device__ float g_ksum[T_SEQ];
// bf16 K-extended split buffers
__device__ __align__(16) __nv_bfloat16 g_hid3 [T_SEQ * 3 * EMB];        // A [hi|lo|hi]
__device__ __align__(16) __nv_bfloat16 g_Wf13 [NH * LAT * 3 * EMB];     // B [hi|hi|lo]
__device__ __align__(16) __nv_bfloat16 g_Wf23 [EMB * 3 * NH * LAT];     // B [hi|hi|lo]
__device__ __align__(16) __nv_bfloat16 g_Wkv3 [2 * LAT * 3 * EMB];      // B [hi|hi|lo]
__device__ __align__(16) __nv_bfloat16 g_qlat3[T_SEQ * NH * 3 * LAT];   // A [hi|lo|hi]
__device__ __align__(16) __nv_bfloat16 g_lk3  [T_SEQ * 3 * LAT];        // B [hi|hi|lo]
__device__ __align__(16) __half        g_lvTh [LAT * T_SEQ];            // V^T hi (fp16)
__device__ __align__(16) __half        g_lvTl [LAT * T_SEQ];            // V^T lo (fp16)
__device__ __align__(16) __nv_bfloat16 g_lctx3[T_SEQ * 3 * NH * LAT];   // A [hi|lo|hi]

// ================= PTX helpers (baseline compute_103-safe only) =================
__device__ __forceinline__ uint32_t smem_u32(const void* p) {
    uint32_t a;
    asm("{ .reg .u64 t; cvta.to.shared.u64 t, %1; cvt.u32.u64 %0, t; }" : "=r"(a) : "l"(p));
    return a;
}
#define CP_ASYNC16(dst, src) \
    asm volatile("cp.async.cg.shared.global [%0], [%1], 16;" :: "r"(dst), "l"(src))
#define CP_COMMIT() asm volatile("cp.async.commit_group;")
#define CP_WAIT1()  asm volatile("cp.async.wait_group 1;")
#define CP_WAIT0()  asm volatile("cp.async.wait_group 0;")

__device__ __forceinline__ void ldmx4(uint32_t& r0, uint32_t& r1, uint32_t& r2, uint32_t& r3,
                                      uint32_t addr) {
    asm volatile("ldmatrix.sync.aligned.m8n8.x4.shared.b16 {%0,%1,%2,%3}, [%4];"
                 : "=r"(r0), "=r"(r1), "=r"(r2), "=r"(r3) : "r"(addr));
}
__device__ __forceinline__ void mma16816(float* d, const uint32_t* a, const uint32_t* b) {
    asm volatile("mma.sync.aligned.m16n8k16.row.col.f32.bf16.bf16.f32 "
                 "{%0,%1,%2,%3}, {%4,%5,%6,%7}, {%8,%9}, {%0,%1,%2,%3};"
                 : "+f"(d[0]), "+f"(d[1]), "+f"(d[2]), "+f"(d[3])
                 : "r"(a[0]), "r"(a[1]), "r"(a[2]), "r"(a[3]), "r"(b[0]), "r"(b[1]));
}
__device__ __forceinline__ void mma16816h(float* d, const uint32_t* a, const uint32_t* b) {
    asm volatile("mma.sync.aligned.m16n8k16.row.col.f32.f16.f16.f32 "
                 "{%0,%1,%2,%3}, {%4,%5,%6,%7}, {%8,%9}, {%0,%1,%2,%3};"
                 : "+f"(d[0]), "+f"(d[1]), "+f"(d[2]), "+f"(d[3])
                 : "r"(a[0]), "r"(a[1]), "r"(a[2]), "r"(a[3]), "r"(b[0]), "r"(b[1]));
}

// ---------------- fp32 -> K-extended bf16 hi/lo split ----------------
__global__ void cvt_split3(const float* __restrict__ x, __nv_bfloat16* __restrict__ out,
                           int total, int K, int offH2, int offL)
{
    int i = (blockIdx.x * blockDim.x + threadIdx.x) * 4;
    if (i >= total) return;
    float4 v = *(const float4*)(x + i);
    float vv[4] = {v.x, v.y, v.z, v.w};
    __nv_bfloat16 hb[4], lb[4];
#pragma unroll
    for (int k = 0; k < 4; k++) {
        hb[k] = __float2bfloat16(vv[k]);
        lb[k] = __float2bfloat16(vv[k] - __bfloat162float(hb[k]));
    }
    int r = i / K, c = i - r * K;
    size_t base = (size_t)r * 3 * K + c;
    *(uint2*)(out + base)         = *(uint2*)hb;
    *(uint2*)(out + base + offH2) = *(uint2*)hb;
    *(uint2*)(out + base + offL)  = *(uint2*)lb;
}

// ============== HMMA bf16 GEMM (+split-K): C = A[M,K] @ B[N,K]^T ==============
#define GS 72
#define STAGE_ELTS (128 * GS)
#define HMMA_SMEM (3 * 2 * STAGE_ELTS * 2)

__global__ __launch_bounds__(256) void hmma_gemm(
    const __nv_bfloat16* __restrict__ A, const __nv_bfloat16* __restrict__ B,
    float* __restrict__ C, int M, int N, int K, int nsplit)
{
    extern __shared__ __align__(16) __nv_bfloat16 sm[];
    const int tid = threadIdx.x;
    const int wid = tid >> 5;
    const int lane = tid & 31;
    const int warp_m = wid >> 2;
    const int warp_n = wid & 3;
    const int bm = blockIdx.y * 128;
    const int bn = blockIdx.x * 128;
    const uint32_t sbase = smem_u32(sm);

    const int Kc = K / nsplit;
    const int kbeg = blockIdx.z * Kc;
    C += (size_t)blockIdx.z * M * N;
    const int nk = Kc >> 6;

    auto load_stage = [&](int stage, int k0) {
        __nv_bfloat16* As = sm + stage * 2 * STAGE_ELTS;
        __nv_bfloat16* Bs = As + STAGE_ELTS;
#pragma unroll
        for (int i = 0; i < 4; i++) {
            int c = tid + i * 256;
            int row = c >> 3;
            int col8 = (c & 7) * 8;
            CP_ASYNC16(smem_u32(As + row * GS + col8),
                       A + (size_t)(bm + row) * K + kbeg + k0 + col8);
            CP_ASYNC16(smem_u32(Bs + row * GS + col8),
                       B + (size_t)(bn + row) * K + kbeg + k0 + col8);
        }
    };

    float acc[4][4][4];
#pragma unroll
    for (int mi = 0; mi < 4; mi++)
#pragma unroll
        for (int ni = 0; ni < 4; ni++)
#pragma unroll
            for (int r = 0; r < 4; r++) acc[mi][ni][r] = 0.f;

    load_stage(0, 0); CP_COMMIT();
    if (nk > 1) { load_stage(1, 64); CP_COMMIT(); }

    const int a_row = (lane & 15);
    const int a_koff = (lane >> 4) * 8;
    const int b_row = (lane & 7) + ((lane >> 4) & 1) * 8;
    const int b_koff = ((lane >> 3) & 1) * 8;

    for (int it = 0; it < nk; it++) {
        CP_WAIT1();
        __syncthreads();
        if (it + 2 < nk) { load_stage((it + 2) % 3, (it + 2) * 64); CP_COMMIT(); }

        const int stage = it % 3;
        const uint32_t sA = sbase + (uint32_t)(stage * 2 * STAGE_ELTS) * 2;
        const uint32_t sB = sA + STAGE_ELTS * 2;

#pragma unroll
        for (int kk = 0; kk < 64; kk += 16) {
            uint32_t af[4][4];
#pragma unroll
            for (int mi = 0; mi < 4; mi++) {
                uint32_t addr = sA + ((warp_m * 64 + mi * 16 + a_row) * GS + kk + a_koff) * 2;
                ldmx4(af[mi][0], af[mi][1], af[mi][2], af[mi][3], addr);
            }
            uint32_t bf[4][2];
#pragma unroll
            for (int ni2 = 0; ni2 < 2; ni2++) {
                uint32_t addr = sB + ((warp_n * 32 + ni2 * 16 + b_row) * GS + kk + b_koff) * 2;
                uint32_t r0, r1, r2, r3;
                ldmx4(r0, r1, r2, r3, addr);
                bf[ni2 * 2 + 0][0] = r0; bf[ni2 * 2 + 0][1] = r1;
                bf[ni2 * 2 + 1][0] = r2; bf[ni2 * 2 + 1][1] = r3;
            }
#pragma unroll
            for (int mi = 0; mi < 4; mi++)
#pragma unroll
                for (int ni = 0; ni < 4; ni++)
                    mma16816(acc[mi][ni], af[mi], bf[ni]);
        }
        __syncthreads();
    }

    const int er = lane >> 2;
    const int ec = (lane & 3) * 2;
#pragma unroll
    for (int mi = 0; mi < 4; mi++) {
#pragma unroll
        for (int ni = 0; ni < 4; ni++) {
            int m0 = bm + warp_m * 64 + mi * 16 + er;
            int n0 = bn + warp_n * 32 + ni * 8 + ec;
            *(float2*)(C + (size_t)m0 * N + n0) = make_float2(acc[mi][ni][0], acc[mi][ni][1]);
            *(float2*)(C + (size_t)(m0 + 8) * N + n0) = make_float2(acc[mi][ni][2], acc[mi][ni][3]);
        }
    }
}

// ---------------- split-K reduce ----------------
__global__ void reduce_kernel(const float* __restrict__ part, float* __restrict__ out,
                              int n, int nsplit)
{
    int i = blockIdx.x * blockDim.x + threadIdx.x;
    if (i >= n) return;
    float s = 0.f;
    for (int k = 0; k < nsplit; k++) s += part[(size_t)k * n + i];
    out[i] = s;
}

// ---------------- generic strided/batched SGEMM (folds only) ----------------
__global__ __launch_bounds__(256) void sgemm_strided(
    const float* __restrict__ A, const float* __restrict__ B, float* __restrict__ C,
    int M, int N, int K, int lda, int ldb, int ldc,
    long batchA, long batchB, long batchC)
{
    __shared__ float As[16][128];
    __shared__ float Bs[16][128];

    const int zb = blockIdx.z;
    A += (long)zb * batchA;
    B += (long)zb * batchB;
    C += (long)zb * batchC;

    const int tid = threadIdx.x;
    const int bm = blockIdx.y * 128;
    const int bn = blockIdx.x * 128;
    const int tx = tid & 15;
    const int ty = tid >> 4;
    const int lrow = tid >> 2;
    const int lcol = (tid & 3) << 2;

    float acc[8][8];
#pragma unroll
    for (int i = 0; i < 8; i++)
#pragma unroll
        for (int j = 0; j < 8; j++) acc[i][j] = 0.f;

    for (int k0 = 0; k0 < K; k0 += 16) {
#pragma unroll
        for (int i = 0; i < 2; i++) {
            int r = lrow + i * 64;
            float4 va = make_float4(0.f, 0.f, 0.f, 0.f);
            float4 vb = make_float4(0.f, 0.f, 0.f, 0.f);
            if (bm + r < M) va = *(const float4*)(A + (size_t)(bm + r) * lda + k0 + lcol);
            if (bn + r < N) vb = *(const float4*)(B + (size_t)(bn + r) * ldb + k0 + lcol);
            As[lcol + 0][r] = va.x; As[lcol + 1][r] = va.y;
            As[lcol + 2][r] = va.z; As[lcol + 3][r] = va.w;
            Bs[lcol + 0][r] = vb.x; Bs[lcol + 1][r] = vb.y;
            Bs[lcol + 2][r] = vb.z; Bs[lcol + 3][r] = vb.w;
        }
        __syncthreads();
#pragma unroll
        for (int k = 0; k < 16; k++) {
            float4 a0 = *(const float4*)&As[k][ty * 4];
            float4 a1 = *(const float4*)&As[k][64 + ty * 4];
            float4 b0 = *(const float4*)&Bs[k][tx * 4];
            float4 b1 = *(const float4*)&Bs[k][64 + tx * 4];
            float a[8] = {a0.x, a0.y, a0.z, a0.w, a1.x, a1.y, a1.z, a1.w};
            float b[8] = {b0.x, b0.y, b0.z, b0.w, b1.x, b1.y, b1.z, b1.w};
#pragma unroll
            for (int i = 0; i < 8; i++)
#pragma unroll
                for (int j = 0; j < 8; j++)
                    acc[i][j] = fmaf(a[i], b[j], acc[i][j]);
        }
        __syncthreads();
    }

#pragma unroll
    for (int i = 0; i < 8; i++) {
        int r = bm + ((i < 4) ? (ty * 4 + i) : (60 + ty * 4 + i));
        if (r >= M) continue;
#pragma unroll
        for (int j = 0; j < 8; j++) {
            int c = bn + ((j < 4) ? (tx * 4 + j) : (60 + tx * 4 + j));
            if (c < N) C[(size_t)r * ldc + c] = acc[i][j];
        }
    }
}

// ---------------- batched tiled transpose ----------------
__global__ void transpose_k(const float* __restrict__ in, float* __restrict__ out,
                            int R, int C, long bIn, long bOut)
{
    __shared__ float t[32][33];
    in  += (long)blockIdx.z * bIn;
    out += (long)blockIdx.z * bOut;
    int x = blockIdx.x * 32 + threadIdx.x;
    for (int i = threadIdx.y; i < 32; i += 8) {
        int y = blockIdx.y * 32 + i;
        if (y < R && x < C) t[i][threadIdx.x] = in[(size_t)y * C + x];
    }
    __syncthreads();
    int x2 = blockIdx.y * 32 + threadIdx.x;
    for (int i = threadIdx.y; i < 32; i += 8) {
        int y2 = blockIdx.x * 32 + i;
        if (y2 < C && x2 < R) out[(size_t)y2 * R + x2] = t[threadIdx.x][i];
    }
}

// ---- cvt_kv: from lkv [T][128] build lk3 [T][192], fp16 lvTh/lvTl [64][T], ksum ----
__global__ __launch_bounds__(256) void cvt_kv(
    const float* __restrict__ lkv, __nv_bfloat16* __restrict__ lk3,
    __half* __restrict__ lvTh, __half* __restrict__ lvTl,
    float* __restrict__ ksum)
{
    __shared__ __half vh[64][65], vl[64][65];
    const int t0 = blockIdx.x * 64;
    const int tid = threadIdx.x;
    for (int i = tid; i < 64 * 64; i += 256) {
        int r = i >> 6, l = i & 63;
        float v = lkv[(size_t)(t0 + r) * 128 + 64 + l];
        __half h = __float2half(v);
        vh[l][r] = h;
        vl[l][r] = __float2half(v - __half2float(h));
        float kv = lkv[(size_t)(t0 + r) * 128 + l];
        __nv_bfloat16 kh = __float2bfloat16(kv);
        __nv_bfloat16 kl = __float2bfloat16(kv - __bfloat162float(kh));
        lk3[(size_t)(t0 + r) * 192 + l]       = kh;
        lk3[(size_t)(t0 + r) * 192 + 64 + l]  = kh;
        lk3[(size_t)(t0 + r) * 192 + 128 + l] = kl;
    }
    __syncthreads();
    for (int i = tid; i < 64 * 64; i += 256) {
        int l = i >> 6, r = i & 63;
        lvTh[(size_t)l * T_SEQ + t0 + r] = vh[l][r];
        lvTl[(size_t)l * T_SEQ + t0 + r] = vl[l][r];
    }
    if (tid < 64) {
        float s = 0.f;
#pragma unroll 8
        for (int l = 0; l < 64; l++) s += lkv[(size_t)(t0 + tid) * 128 + l];
        ksum[t0 + tid] = s;
    }
}

// ---------------- qsum ----------------
__global__ void qsum_kernel(const float* __restrict__ qlat, float* __restrict__ qsum)
{
    int i = blockIdx.x * blockDim.x + threadIdx.x;
    if (i >= T_SEQ * NH) return;
    float s = 0.f;
#pragma unroll 8
    for (int l = 0; l < LAT; l++) s += qlat[(size_t)i * LAT + l];
    qsum[i] = s;
}

// ========== FA2-style HMMA flash: register softmax, PV-from-accumulator ==========
// grid (T/128, H), 256 threads = 8 warps, warp tile 16 rows x 64 keys.
#define FQS 200     // bf16 stride for Q/K tiles (192 data)
#define FVS 136     // f16 stride for V^T tiles (128 data)
#define FLASH_SMEM ((128 * FQS + 2 * 64 * FQS + 2 * 80 * FVS) * 2)   // 145920

__global__ __launch_bounds__(256) void flash_hmma(
    const __nv_bfloat16* __restrict__ qlat3, const __nv_bfloat16* __restrict__ lk3,
    const __half* __restrict__ lvTh, const __half* __restrict__ lvTl,
    const float* __restrict__ qsum, const float* __restrict__ ksum,
    __nv_bfloat16* __restrict__ lctx3)
{
    extern __shared__ __align__(16) __nv_bfloat16 smb[];
    __nv_bfloat16* Qs = smb;                         // 128 x FQS
    __nv_bfloat16* Ks = Qs + 128 * FQS;              // 2 x 64 x FQS
    __half* VT = (__half*)(Ks + 2 * 64 * FQS);       // 2 x 80 x FVS
    __shared__ float kss[64];

    const int h = blockIdx.y;
    const int qt = gridDim.x - 1 - blockIdx.x;       // heavy tiles first
    const int q0 = qt * 128;
    const int tid = threadIdx.x;
    const int lane = tid & 31;
    const int wid = tid >> 5;
    const int rm = wid * 16;

    const int a_row = lane & 15, a_koff = (lane >> 4) * 8;
    const int b_row = (lane & 7) + ((lane >> 4) & 1) * 8;
    const int b_koff = ((lane >> 3) & 1) * 8;
    const int er = lane >> 2, ec = (lane & 3) * 2;
    const float L2E = 1.4426950408889634f;

    // VT constant rows 64..79 (ones column at l=64 hi-term; zeros elsewhere)
    for (int i = tid; i < 2 * 16 * FVS; i += 256) {
        int buf = i / (16 * FVS);
        int rr = (i / FVS) % 16;
        int c = i % FVS;
        __half v = __ushort_as_half((unsigned short)0);
        if (rr == 0 && c < 64) v = __float2half(1.0f);
        VT[buf * 80 * FVS + (64 + rr) * FVS + c] = v;
    }
    // Q tile (128 x 192)
    for (int i = tid; i < 128 * 24; i += 256) {
        int r = i / 24, c = i % 24;
        CP_ASYNC16(smem_u32(Qs + r * FQS + c * 8),
                   qlat3 + ((size_t)(q0 + r) * NH + h) * 192 + c * 8);
    }

    auto load_kv = [&](int buf, int s0) {
        __nv_bfloat16* ks = Ks + buf * 64 * FQS;
        __half* vt = VT + buf * 80 * FVS;
        for (int i = tid; i < 64 * 24; i += 256) {
            int r = i / 24, c = i % 24;
            CP_ASYNC16(smem_u32(ks + r * FQS + c * 8),
                       lk3 + (size_t)(s0 + r) * 192 + c * 8);
        }
        for (int i = tid; i < 64 * 16; i += 256) {
            int r = i >> 4, c = i & 15;
            const __half* src = (c < 8) ? lvTh : lvTl;
            CP_ASYNC16(smem_u32(vt + r * FVS + c * 8),
                       src + (size_t)r * T_SEQ + s0 + (c & 7) * 8);
        }
    };

    load_kv(0, 0); CP_COMMIT();

    // per-lane row state (rows rm+er, rm+er+8); qss pre-scaled by 0.5/sqrt(64)
    const float qss0 = qsum[(size_t)(q0 + rm + er) * NH + h] * 0.0625f;
    const float qss1 = qsum[(size_t)(q0 + rm + er + 8) * NH + h] * 0.0625f;
    const int gi0 = q0 + rm + er, gi1 = gi0 + 8;

    float Oa[9][4];
#pragma unroll
    for (int ni = 0; ni < 9; ni++)
#pragma unroll
        for (int r = 0; r < 4; r++) Oa[ni][r] = 0.f;
    float m0 = -1e30f, m1 = -1e30f;

    const int nkb = 2 * qt + 2;
    for (int kb = 0; kb < nkb; kb++) {
        const int buf = kb & 1;
        const int s0 = kb * 64;
        if (kb + 1 < nkb) { load_kv(buf ^ 1, (kb + 1) * 64); CP_COMMIT(); CP_WAIT1(); }
        else              { CP_WAIT0(); }
        if (tid < 64) kss[tid] = ksum[s0 + tid];
        __syncthreads();

        // ---- S = Q3 @ K3^T  (K' = 192, 3-term bf16) ----
        float sacc[8][4];
#pragma unroll
        for (int ni = 0; ni < 8; ni++)
#pragma unroll
            for (int r = 0; r < 4; r++) sacc[ni][r] = 0.f;
        const uint32_t aQrow = smem_u32(Qs) + ((rm + a_row) * FQS + a_koff) * 2;
        const uint32_t sKb = smem_u32(Ks) + (uint32_t)(buf * 64 * FQS) * 2;
#pragma unroll
        for (int kk = 0; kk < 192; kk += 16) {
            uint32_t af[4];
            ldmx4(af[0], af[1], af[2], af[3], aQrow + kk * 2);
            uint32_t bfr[8][2];
#pragma unroll
            for (int n4 = 0; n4 < 4; n4++) {
                uint32_t r0, r1, r2, r3;
                ldmx4(r0, r1, r2, r3, sKb + ((n4 * 16 + b_row) * FQS + kk + b_koff) * 2);
                bfr[n4 * 2 + 0][0] = r0; bfr[n4 * 2 + 0][1] = r1;
                bfr[n4 * 2 + 1][0] = r2; bfr[n4 * 2 + 1][1] = r3;
            }
#pragma unroll
            for (int ni = 0; ni < 8; ni++) mma16816(sacc[ni], af, bfr[ni]);
        }

        // ---- scale + causal mask + reciprocal band (registers) ----
#pragma unroll
        for (int ni = 0; ni < 8; ni++) {
#pragma unroll
            for (int cc = 0; cc < 2; cc++) {
                int gj = s0 + ni * 8 + ec + cc;
                float ksv = kss[ni * 8 + ec + cc];
                float v = sacc[ni][cc] * 0.125f;
                if (gi0 - gj <= 64) v += qss0 * ksv;
                sacc[ni][cc] = (gj <= gi0) ? v : -1e30f;
                float w = sacc[ni][2 + cc] * 0.125f;
                if (gi1 - gj <= 64) w += qss1 * ksv;
                sacc[ni][2 + cc] = (gj <= gi1) ? w : -1e30f;
            }
        }

        // ---- online softmax on registers (quad shfl) ----
        float mx0 = -1e30f, mx1 = -1e30f;
#pragma unroll
        for (int ni = 0; ni < 8; ni++) {
            mx0 = fmaxf(mx0, fmaxf(sacc[ni][0], sacc[ni][1]));
            mx1 = fmaxf(mx1, fmaxf(sacc[ni][2], sacc[ni][3]));
        }
        mx0 = fmaxf(mx0, __shfl_xor_sync(0xffffffffu, mx0, 1));
        mx0 = fmaxf(mx0, __shfl_xor_sync(0xffffffffu, mx0, 2));
        mx1 = fmaxf(mx1, __shfl_xor_sync(0xffffffffu, mx1, 1));
        mx1 = fmaxf(mx1, __shfl_xor_sync(0xffffffffu, mx1, 2));
        float mn0 = fmaxf(m0, mx0), mn1 = fmaxf(m1, mx1);
        float al0 = exp2f((m0 - mn0) * L2E);
        float al1 = exp2f((m1 - mn1) * L2E);
        m0 = mn0; m1 = mn1;
#pragma unroll
        for (int ni = 0; ni < 9; ni++) {
            Oa[ni][0] *= al0; Oa[ni][1] *= al0;
            Oa[ni][2] *= al1; Oa[ni][3] *= al1;
        }
        // p = 2^((S-m)*log2e) in f16x2 — directly the PV A-fragments
        uint32_t p01[8], p23[8];
#pragma unroll
        for (int ni = 0; ni < 8; ni++) {
            float x0 = (sacc[ni][0] - mn0) * L2E;
            float x1 = (sacc[ni][1] - mn0) * L2E;
            float x2 = (sacc[ni][2] - mn1) * L2E;
            float x3 = (sacc[ni][3] - mn1) * L2E;
            uint32_t hx;
            asm("cvt.rn.f16x2.f32 %0, %1, %2;" : "=r"(hx) : "f"(x1), "f"(x0));
            asm("ex2.approx.f16x2 %0, %1;" : "=r"(p01[ni]) : "r"(hx));
            asm("cvt.rn.f16x2.f32 %0, %1, %2;" : "=r"(hx) : "f"(x3), "f"(x2));
            asm("ex2.approx.f16x2 %0, %1;" : "=r"(p23[ni]) : "r"(hx));
        }

        // ---- O += P @ [Vh ; Vl]^T  (fp16, 2 terms; col 64 = ones -> row sum) ----
        const uint32_t sVb = smem_u32(VT) + (uint32_t)(buf * 80 * FVS) * 2;
#pragma unroll
        for (int term = 0; term < 2; term++) {
#pragma unroll
            for (int kk = 0; kk < 64; kk += 16) {
                int f = kk >> 3;
                uint32_t af[4] = { p01[f], p23[f], p01[f + 1], p23[f + 1] };
                uint32_t bfr[10][2];
#pragma unroll
                for (int n4 = 0; n4 < 5; n4++) {
                    uint32_t r0, r1, r2, r3;
                    ldmx4(r0, r1, r2, r3,
                          sVb + ((n4 * 16 + b_row) * FVS + term * 64 + kk + b_koff) * 2);
                    bfr[n4 * 2 + 0][0] = r0; bfr[n4 * 2 + 0][1] = r1;
                    bfr[n4 * 2 + 1][0] = r2; bfr[n4 * 2 + 1][1] = r3;
                }
#pragma unroll
                for (int ni = 0; ni < 9; ni++) mma16816h(Oa[ni], af, bfr[ni]);
            }
        }
        __syncthreads();   // all warps done reading this buffer before next-iter overwrite
    }

    // ---- epilogue: normalize by ones-column sum, write split lctx3 ----
    float ls0 = __shfl_sync(0xffffffffu, Oa[8][0], lane & ~3);
    float ls1 = __shfl_sync(0xffffffffu, Oa[8][2], lane & ~3);
    float li0 = 1.f / ls0, li1 = 1.f / ls1;
    const int t0 = q0 + rm + er, t1 = t0 + 8;
#pragma unroll
    for (int ni = 0; ni < 8; ni++) {
        int c0 = ni * 8 + ec;
        float v0 = Oa[ni][0] * li0, v1 = Oa[ni][1] * li0;
        float v2 = Oa[ni][2] * li1, v3 = Oa[ni][3] * li1;
        __nv_bfloat16 h0 = __float2bfloat16(v0), h1 = __float2bfloat16(v1);
        __nv_bfloat162 hp0; hp0.x = h0; hp0.y = h1;
        __nv_bfloat162 lp0;
        lp0.x = __float2bfloat16(v0 - __bfloat162float(h0));
        lp0.y = __float2bfloat16(v1 - __bfloat162float(h1));
        size_t b0 = (size_t)t0 * 3072 + h * 64 + c0;
        *(__nv_bfloat162*)(lctx3 + b0)        = hp0;
        *(__nv_bfloat162*)(lctx3 + b0 + 1024) = lp0;
        *(__nv_bfloat162*)(lctx3 + b0 + 2048) = hp0;
        __nv_bfloat16 h2 = __float2bfloat16(v2), h3 = __float2bfloat16(v3);
        __nv_bfloat162 hp1; hp1.x = h2; hp1.y = h3;
        __nv_bfloat162 lp1;
        lp1.x = __float2bfloat16(v2 - __bfloat162float(h2));
        lp1.y = __float2bfloat16(v3 - __bfloat162float(h3));
        size_t b1 = (size_t)t1 * 3072 + h * 64 + c0;
        *(__nv_bfloat162*)(lctx3 + b1)        = hp1;
        *(__nv_bfloat162*)(lctx3 + b1 + 1024) = lp1;
        *(__nv_bfloat162*)(lctx3 + b1 + 2048) = hp1;
    }
}

// ---------------- host launcher ----------------
extern "C" void kernel_launch(void* const* d_in, const int* in_sizes, int n_in,
                              void* d_out, int out_size)
{
    const float* hidden = (const float*)d_in[0];
    const float* Wq  = (const float*)d_in[1];
    const float* Wk  = (const float*)d_in[2];
    const float* Wv  = (const float*)d_in[3];
    const float* q2l = (const float*)d_in[4];
    const float* vup = (const float*)d_in[5];
    const float* Wo  = (const float*)d_in[6];
    float* out = (float*)d_out;

    float *WqT, *q2lT, *Wf1, *Wf2T, *lkv, *lpart, *qlat, *qs, *ks;
    __nv_bfloat16 *hid3, *Wf13, *Wf23, *Wkv3, *qlat3, *lk3, *lctx3;
    __half *lvTh, *lvTl;
    cudaGetSymbolAddress((void**)&WqT,   g_WqT);
    cudaGetSymbolAddress((void**)&q2lT,  g_q2lT);
    cudaGetSymbolAddress((void**)&Wf1,   g_Wf1);
    cudaGetSymbolAddress((void**)&Wf2T,  g_Wf2T);
    cudaGetSymbolAddress((void**)&lkv,   g_lkv);
    cudaGetSymbolAddress((void**)&lpart, g_lpart);
    cudaGetSymbolAddress((void**)&qlat,  g_qlat);
    cudaGetSymbolAddress((void**)&qs,    g_qsum);
    cudaGetSymbolAddress((void**)&ks,    g_ksum);
    cudaGetSymbolAddress((void**)&hid3,  g_hid3);
    cudaGetSymbolAddress((void**)&Wf13,  g_Wf13);
    cudaGetSymbolAddress((void**)&Wf23,  g_Wf23);
    cudaGetSymbolAddress((void**)&Wkv3,  g_Wkv3);
    cudaGetSymbolAddress((void**)&qlat3, g_qlat3);
    cudaGetSymbolAddress((void**)&lk3,   g_lk3);
    cudaGetSymbolAddress((void**)&lvTh,  g_lvTh);
    cudaGetSymbolAddress((void**)&lvTl,  g_lvTl);
    cudaGetSymbolAddress((void**)&lctx3, g_lctx3);

    cudaFuncSetAttribute(hmma_gemm,
                         cudaFuncAttributeMaxDynamicSharedMemorySize, HMMA_SMEM);
    cudaFuncSetAttribute(flash_hmma,
                         cudaFuncAttributeMaxDynamicSharedMemorySize, FLASH_SMEM);

    // --- weight preprocessing (FFMA folds; small) ---
    transpose_k<<<dim3(64, 64, 1), dim3(32, 8)>>>(Wq, WqT, EMB, EMB, 0, 0);
    transpose_k<<<dim3(2, 4, NH), dim3(32, 8)>>>(q2l, q2lT, HD, LAT,
                                                 (long)HD * LAT, (long)LAT * HD);
    sgemm_strided<<<dim3(16, 1, NH), 256>>>(
        q2lT, WqT, Wf1, LAT, EMB, HD, HD, EMB, EMB,
        (long)LAT * HD, (long)HD, (long)LAT * EMB);
    sgemm_strided<<<dim3(1, 16, NH), 256>>>(
        Wo, vup, Wf2T, EMB, LAT, HD, EMB, HD, NH * LAT,
        (long)HD, (long)LAT * HD, (long)LAT);

    // --- bf16 splits ---
    cvt_split3<<<(T_SEQ * EMB / 4 + 255) / 256, 256>>>(
        hidden, hid3, T_SEQ * EMB, EMB, 2 * EMB, EMB);
    cvt_split3<<<(LAT * EMB / 4 + 255) / 256, 256>>>(
        Wk, Wkv3, LAT * EMB, EMB, EMB, 2 * EMB);
    cvt_split3<<<(LAT * EMB / 4 + 255) / 256, 256>>>(
        Wv, Wkv3 + (size_t)LAT * 3 * EMB, LAT * EMB, EMB, EMB, 2 * EMB);
    cvt_split3<<<(NH * LAT * EMB / 4 + 255) / 256, 256>>>(
        Wf1, Wf13, NH * LAT * EMB, EMB, EMB, 2 * EMB);
    cvt_split3<<<(EMB * NH * LAT / 4 + 255) / 256, 256>>>(
        Wf2T, Wf23, EMB * NH * LAT, NH * LAT, NH * LAT, 2 * NH * LAT);

    // --- lkv = hidden @ [Wk;Wv]^T  (HMMA split-K x8 + deterministic reduce) ---
    hmma_gemm<<<dim3(1, 16, 8), 256, HMMA_SMEM>>>(hid3, Wkv3, lpart,
                                                  T_SEQ, 2 * LAT, 3 * EMB, 8);
    reduce_kernel<<<(T_SEQ * 128 + 255) / 256, 256>>>(lpart, lkv, T_SEQ * 128, 8);
    cvt_kv<<<32, 256>>>(lkv, lk3, lvTh, lvTl, ks);

    // --- q_latent = hidden @ Wf1^T  [2048 x 1024]  (HMMA) ---
    hmma_gemm<<<dim3(8, 16, 1), 256, HMMA_SMEM>>>(hid3, Wf13, qlat,
                                                  T_SEQ, NH * LAT, 3 * EMB, 1);
    cvt_split3<<<(T_SEQ * NH * LAT / 4 + 255) / 256, 256>>>(
        qlat, qlat3, T_SEQ * NH * LAT, LAT, 2 * LAT, LAT);
    qsum_kernel<<<(T_SEQ * NH + 255) / 256, 256>>>(qlat, qs);

    // --- FA2-style HMMA flash attention ---
    flash_hmma<<<dim3(16, NH), 256, FLASH_SMEM>>>(qlat3, lk3, lvTh, lvTl, qs, ks, lctx3);

    // --- out = lctx @ Wf2T^T  [2048 x 2048]  (HMMA) ---
    hmma_gemm<<<dim3(16, 16, 1), 256, HMMA_SMEM>>>(lctx3, Wf23, out,
                                                   T_SEQ, EMB, 3 * NH * LAT, 1);
}

// round 9
// speedup vs baseline: 5.1329x; 1.1468x over previous
#include <cuda_runtime.h>
#include <cuda_bf16.h>
#include <cuda_fp16.h>
#include <cstdint>

#define T_SEQ 2048
#define EMB   2048
#define NH    16
#define HD    128
#define LAT   64

// ---------------- scratch (static device globals; no allocation) ----------------
__device__ float g_q2lT[NH * LAT * HD];             // q2l transposed [h][l][d]
__device__ float g_lpart[8 * T_SEQ * 2 * LAT];      // lkv split-K partials (8 MB)
__device__ float g_qlat[T_SEQ * NH * LAT];
__device__ float g_qsum[T_SEQ * NH];
__device__ float g_ksum[T_SEQ];
// bf16 K-extended split buffers
__device__ __align__(16) __nv_bfloat16 g_hid3 [T_SEQ * 3 * EMB];        // A [hi|lo|hi]
__device__ __align__(16) __nv_bfloat16 g_WqT3 [EMB * NH * 3 * HD];      // B [hi|hi|lo] per (e,h)
__device__ __align__(16) __nv_bfloat16 g_Wo3  [EMB * NH * 3 * HD];      // A [hi|lo|hi] per (e,h)
__device__ __align__(16) __nv_bfloat16 g_q2l3p[NH * HD * 3 * HD];       // A [hi|lo|hi], rows padded to 128
__device__ __align__(16) __nv_bfloat16 g_vup3p[NH * HD * 3 * HD];       // B [hi|hi|lo], rows padded to 128
__device__ __align__(16) __nv_bfloat16 g_Wf13 [NH * LAT * 3 * EMB];     // B [hi|hi|lo]
__device__ __align__(16) __nv_bfloat16 g_Wf23 [EMB * 3 * NH * LAT];     // B [hi|hi|lo]
__device__ __align__(16) __nv_bfloat16 g_Wkv3 [2 * LAT * 3 * EMB];      // B [hi|hi|lo]
__device__ __align__(16) __nv_bfloat16 g_qlat3[T_SEQ * NH * 3 * LAT];   // A [hi|lo|hi]
__device__ __align__(16) __nv_bfloat16 g_lk3  [T_SEQ * 3 * LAT];        // B [hi|hi|lo]
__device__ __align__(16) __half        g_lvTh [LAT * T_SEQ];            // V^T hi (fp16)
__device__ __align__(16) __half        g_lvTl [LAT * T_SEQ];            // V^T lo (fp16)
__device__ __align__(16) __nv_bfloat16 g_lctx3[T_SEQ * 3 * NH * LAT];   // A [hi|lo|hi]

// ================= PTX helpers (baseline compute_103-safe only) =================
__device__ __forceinline__ uint32_t smem_u32(const void* p) {
    uint32_t a;
    asm("{ .reg .u64 t; cvta.to.shared.u64 t, %1; cvt.u32.u64 %0, t; }" : "=r"(a) : "l"(p));
    return a;
}
#define CP_ASYNC16(dst, src) \
    asm volatile("cp.async.cg.shared.global [%0], [%1], 16;" :: "r"(dst), "l"(src))
#define CP_COMMIT() asm volatile("cp.async.commit_group;")
#define CP_WAIT1()  asm volatile("cp.async.wait_group 1;")
#define CP_WAIT0()  asm volatile("cp.async.wait_group 0;")

__device__ __forceinline__ void ldmx4(uint32_t& r0, uint32_t& r1, uint32_t& r2, uint32_t& r3,
                                      uint32_t addr) {
    asm volatile("ldmatrix.sync.aligned.m8n8.x4.shared.b16 {%0,%1,%2,%3}, [%4];"
                 : "=r"(r0), "=r"(r1), "=r"(r2), "=r"(r3) : "r"(addr));
}
__device__ __forceinline__ void mma16816(float* d, const uint32_t* a, const uint32_t* b) {
    asm volatile("mma.sync.aligned.m16n8k16.row.col.f32.bf16.bf16.f32 "
                 "{%0,%1,%2,%3}, {%4,%5,%6,%7}, {%8,%9}, {%0,%1,%2,%3};"
                 : "+f"(d[0]), "+f"(d[1]), "+f"(d[2]), "+f"(d[3])
                 : "r"(a[0]), "r"(a[1]), "r"(a[2]), "r"(a[3]), "r"(b[0]), "r"(b[1]));
}
__device__ __forceinline__ void mma16816h(float* d, const uint32_t* a, const uint32_t* b) {
    asm volatile("mma.sync.aligned.m16n8k16.row.col.f32.f16.f16.f32 "
                 "{%0,%1,%2,%3}, {%4,%5,%6,%7}, {%8,%9}, {%0,%1,%2,%3};"
                 : "+f"(d[0]), "+f"(d[1]), "+f"(d[2]), "+f"(d[3])
                 : "r"(a[0]), "r"(a[1]), "r"(a[2]), "r"(a[3]), "r"(b[0]), "r"(b[1]));
}

// ---------------- fp32 -> K-extended bf16 hi/lo split (contiguous rows) -------
__global__ void cvt_split3(const float* __restrict__ x, __nv_bfloat16* __restrict__ out,
                           int total, int K, int offH2, int offL)
{
    int i = (blockIdx.x * blockDim.x + threadIdx.x) * 4;
    if (i >= total) return;
    float4 v = *(const float4*)(x + i);
    float vv[4] = {v.x, v.y, v.z, v.w};
    __nv_bfloat16 hb[4], lb[4];
#pragma unroll
    for (int k = 0; k < 4; k++) {
        hb[k] = __float2bfloat16(vv[k]);
        lb[k] = __float2bfloat16(vv[k] - __bfloat162float(hb[k]));
    }
    int r = i / K, c = i - r * K;
    size_t base = (size_t)r * 3 * K + c;
    *(uint2*)(out + base)         = *(uint2*)hb;
    *(uint2*)(out + base + offH2) = *(uint2*)hb;
    *(uint2*)(out + base + offL)  = *(uint2*)lb;
}

// ---- padded batched variant: nb batches of rows x K, out padded to padRows ----
__global__ void cvt_split3_pad(const float* __restrict__ x, __nv_bfloat16* __restrict__ out,
                               int nb, int rows, int K, int padRows, int offH2, int offL)
{
    int i = (blockIdx.x * blockDim.x + threadIdx.x) * 4;
    int total = nb * padRows * K;
    if (i >= total) return;
    int b = i / (padRows * K);
    int rem = i - b * (padRows * K);
    int r = rem / K, c = rem - r * K;
    float vv[4] = {0.f, 0.f, 0.f, 0.f};
    if (r < rows) {
        float4 v = *(const float4*)(x + (size_t)b * rows * K + (size_t)r * K + c);
        vv[0] = v.x; vv[1] = v.y; vv[2] = v.z; vv[3] = v.w;
    }
    __nv_bfloat16 hb[4], lb[4];
#pragma unroll
    for (int k = 0; k < 4; k++) {
        hb[k] = __float2bfloat16(vv[k]);
        lb[k] = __float2bfloat16(vv[k] - __bfloat162float(hb[k]));
    }
    size_t base = (size_t)b * padRows * 3 * K + (size_t)r * 3 * K + c;
    *(uint2*)(out + base)         = *(uint2*)hb;
    *(uint2*)(out + base + offH2) = *(uint2*)hb;
    *(uint2*)(out + base + offL)  = *(uint2*)lb;
}

// ---- fused transpose + split: Wq [hd][e] -> WqT3 [e][h][384] B-layout [hi|hi|lo]
__global__ void transpose_split3(const float* __restrict__ in, __nv_bfloat16* __restrict__ out)
{
    __shared__ float t[32][33];
    int x = blockIdx.x * 32 + threadIdx.x;                 // e
    for (int i = threadIdx.y; i < 32; i += 8) {
        int y = blockIdx.y * 32 + i;                       // hd
        t[i][threadIdx.x] = in[(size_t)y * EMB + x];
    }
    __syncthreads();
    int e = blockIdx.y * 32;                               // row block of output = e? no:
    // output row = e (from x-dim), col = hd (from y-dim)
    int e2 = blockIdx.x * 32 + threadIdx.y;                // iterate e via y-threads
    for (int i = threadIdx.y; i < 32; i += 8) {
        int eo = blockIdx.x * 32 + i;                      // e
        int hd = blockIdx.y * 32 + threadIdx.x;            // hd
        float v = t[threadIdx.x][i];
        __nv_bfloat16 h = __float2bfloat16(v);
        __nv_bfloat16 l = __float2bfloat16(v - __bfloat162float(h));
        int hh = hd >> 7, d = hd & 127;
        size_t base = (size_t)eo * (NH * 3 * HD) + hh * 384 + d;
        out[base]       = h;
        out[base + 128] = h;
        out[base + 256] = l;
    }
    (void)e; (void)e2;
}

// ============== HMMA bf16 GEMM (+split-K): C = A[M,K] @ B[N,K]^T ==============
#define GS 72
#define STAGE_ELTS (128 * GS)
#define HMMA_SMEM (3 * 2 * STAGE_ELTS * 2)

__global__ __launch_bounds__(256) void hmma_gemm(
    const __nv_bfloat16* __restrict__ A, const __nv_bfloat16* __restrict__ B,
    float* __restrict__ C, int M, int N, int K, int nsplit)
{
    extern __shared__ __align__(16) __nv_bfloat16 sm[];
    const int tid = threadIdx.x;
    const int wid = tid >> 5;
    const int lane = tid & 31;
    const int warp_m = wid >> 2;
    const int warp_n = wid & 3;
    const int bm = blockIdx.y * 128;
    const int bn = blockIdx.x * 128;
    const uint32_t sbase = smem_u32(sm);

    const int Kc = K / nsplit;
    const int kbeg = blockIdx.z * Kc;
    C += (size_t)blockIdx.z * M * N;
    const int nk = Kc >> 6;

    auto load_stage = [&](int stage, int k0) {
        __nv_bfloat16* As = sm + stage * 2 * STAGE_ELTS;
        __nv_bfloat16* Bs = As + STAGE_ELTS;
#pragma unroll
        for (int i = 0; i < 4; i++) {
            int c = tid + i * 256;
            int row = c >> 3;
            int col8 = (c & 7) * 8;
            CP_ASYNC16(smem_u32(As + row * GS + col8),
                       A + (size_t)(bm + row) * K + kbeg + k0 + col8);
            CP_ASYNC16(smem_u32(Bs + row * GS + col8),
                       B + (size_t)(bn + row) * K + kbeg + k0 + col8);
        }
    };

    float acc[4][4][4];
#pragma unroll
    for (int mi = 0; mi < 4; mi++)
#pragma unroll
        for (int ni = 0; ni < 4; ni++)
#pragma unroll
            for (int r = 0; r < 4; r++) acc[mi][ni][r] = 0.f;

    load_stage(0, 0); CP_COMMIT();
    if (nk > 1) { load_stage(1, 64); CP_COMMIT(); }

    const int a_row = (lane & 15);
    const int a_koff = (lane >> 4) * 8;
    const int b_row = (lane & 7) + ((lane >> 4) & 1) * 8;
    const int b_koff = ((lane >> 3) & 1) * 8;

    for (int it = 0; it < nk; it++) {
        CP_WAIT1();
        __syncthreads();
        if (it + 2 < nk) { load_stage((it + 2) % 3, (it + 2) * 64); CP_COMMIT(); }

        const int stage = it % 3;
        const uint32_t sA = sbase + (uint32_t)(stage * 2 * STAGE_ELTS) * 2;
        const uint32_t sB = sA + STAGE_ELTS * 2;

#pragma unroll
        for (int kk = 0; kk < 64; kk += 16) {
            uint32_t af[4][4];
#pragma unroll
            for (int mi = 0; mi < 4; mi++) {
                uint32_t addr = sA + ((warp_m * 64 + mi * 16 + a_row) * GS + kk + a_koff) * 2;
                ldmx4(af[mi][0], af[mi][1], af[mi][2], af[mi][3], addr);
            }
            uint32_t bf[4][2];
#pragma unroll
            for (int ni2 = 0; ni2 < 2; ni2++) {
                uint32_t addr = sB + ((warp_n * 32 + ni2 * 16 + b_row) * GS + kk + b_koff) * 2;
                uint32_t r0, r1, r2, r3;
                ldmx4(r0, r1, r2, r3, addr);
                bf[ni2 * 2 + 0][0] = r0; bf[ni2 * 2 + 0][1] = r1;
                bf[ni2 * 2 + 1][0] = r2; bf[ni2 * 2 + 1][1] = r3;
            }
#pragma unroll
            for (int mi = 0; mi < 4; mi++)
#pragma unroll
                for (int ni = 0; ni < 4; ni++)
                    mma16816(acc[mi][ni], af[mi], bf[ni]);
        }
        __syncthreads();
    }

    const int er = lane >> 2;
    const int ec = (lane & 3) * 2;
#pragma unroll
    for (int mi = 0; mi < 4; mi++) {
#pragma unroll
        for (int ni = 0; ni < 4; ni++) {
            int m0 = bm + warp_m * 64 + mi * 16 + er;
            int n0 = bn + warp_n * 32 + ni * 8 + ec;
            *(float2*)(C + (size_t)m0 * N + n0) = make_float2(acc[mi][ni][0], acc[mi][ni][1]);
            *(float2*)(C + (size_t)(m0 + 8) * N + n0) = make_float2(acc[mi][ni][2], acc[mi][ni][3]);
        }
    }
}

// ==== HMMA fold GEMM: batched, strided operands, bf16 split-writing epilogue ====
// C3[m*ldc3 + n + {0, offH2c}] = hi, [.. + offLc] = lo; guarded by validM/validN.
__global__ __launch_bounds__(256) void hmma_fold(
    const __nv_bfloat16* __restrict__ A, const __nv_bfloat16* __restrict__ B,
    __nv_bfloat16* __restrict__ C3, int K, int lda, int ldb,
    long batchA, long batchB, long batchC,
    int ldc3, int offH2c, int offLc, int validM, int validN)
{
    extern __shared__ __align__(16) __nv_bfloat16 sm[];
    const int tid = threadIdx.x;
    const int wid = tid >> 5;
    const int lane = tid & 31;
    const int warp_m = wid >> 2;
    const int warp_n = wid & 3;
    const int bm = blockIdx.y * 128;
    const int bn = blockIdx.x * 128;
    const uint32_t sbase = smem_u32(sm);

    A  += (size_t)blockIdx.z * batchA;
    B  += (size_t)blockIdx.z * batchB;
    C3 += (size_t)blockIdx.z * batchC;
    const int nk = K >> 6;

    auto load_stage = [&](int stage, int k0) {
        __nv_bfloat16* As = sm + stage * 2 * STAGE_ELTS;
        __nv_bfloat16* Bs = As + STAGE_ELTS;
#pragma unroll
        for (int i = 0; i < 4; i++) {
            int c = tid + i * 256;
            int row = c >> 3;
            int col8 = (c & 7) * 8;
            CP_ASYNC16(smem_u32(As + row * GS + col8),
                       A + (size_t)(bm + row) * lda + k0 + col8);
            CP_ASYNC16(smem_u32(Bs + row * GS + col8),
                       B + (size_t)(bn + row) * ldb + k0 + col8);
        }
    };

    float acc[4][4][4];
#pragma unroll
    for (int mi = 0; mi < 4; mi++)
#pragma unroll
        for (int ni = 0; ni < 4; ni++)
#pragma unroll
            for (int r = 0; r < 4; r++) acc[mi][ni][r] = 0.f;

    load_stage(0, 0); CP_COMMIT();
    if (nk > 1) { load_stage(1, 64); CP_COMMIT(); }

    const int a_row = (lane & 15);
    const int a_koff = (lane >> 4) * 8;
    const int b_row = (lane & 7) + ((lane >> 4) & 1) * 8;
    const int b_koff = ((lane >> 3) & 1) * 8;

    for (int it = 0; it < nk; it++) {
        CP_WAIT1();
        __syncthreads();
        if (it + 2 < nk) { load_stage((it + 2) % 3, (it + 2) * 64); CP_COMMIT(); }

        const int stage = it % 3;
        const uint32_t sA = sbase + (uint32_t)(stage * 2 * STAGE_ELTS) * 2;
        const uint32_t sB = sA + STAGE_ELTS * 2;

#pragma unroll
        for (int kk = 0; kk < 64; kk += 16) {
            uint32_t af[4][4];
#pragma unroll
            for (int mi = 0; mi < 4; mi++) {
                uint32_t addr = sA + ((warp_m * 64 + mi * 16 + a_row) * GS + kk + a_koff) * 2;
                ldmx4(af[mi][0], af[mi][1], af[mi][2], af[mi][3], addr);
            }
            uint32_t bf[4][2];
#pragma unroll
            for (int ni2 = 0; ni2 < 2; ni2++) {
                uint32_t addr = sB + ((warp_n * 32 + ni2 * 16 + b_row) * GS + kk + b_koff) * 2;
                uint32_t r0, r1, r2, r3;
                ldmx4(r0, r1, r2, r3, addr);
                bf[ni2 * 2 + 0][0] = r0; bf[ni2 * 2 + 0][1] = r1;
                bf[ni2 * 2 + 1][0] = r2; bf[ni2 * 2 + 1][1] = r3;
            }
#pragma unroll
            for (int mi = 0; mi < 4; mi++)
#pragma unroll
                for (int ni = 0; ni < 4; ni++)
                    mma16816(acc[mi][ni], af[mi], bf[ni]);
        }
        __syncthreads();
    }

    const int er = lane >> 2;
    const int ec = (lane & 3) * 2;
#pragma unroll
    for (int mi = 0; mi < 4; mi++) {
#pragma unroll
        for (int ni = 0; ni < 4; ni++) {
            int n0 = bn + warp_n * 32 + ni * 8 + ec;
            if (n0 >= validN) continue;
#pragma unroll
            for (int rr = 0; rr < 2; rr++) {
                int m0 = bm + warp_m * 64 + mi * 16 + er + rr * 8;
                if (m0 >= validM) continue;
                float v0 = acc[mi][ni][rr * 2 + 0];
                float v1 = acc[mi][ni][rr * 2 + 1];
                __nv_bfloat16 h0 = __float2bfloat16(v0), h1 = __float2bfloat16(v1);
                __nv_bfloat162 hp; hp.x = h0; hp.y = h1;
                __nv_bfloat162 lp;
                lp.x = __float2bfloat16(v0 - __bfloat162float(h0));
                lp.y = __float2bfloat16(v1 - __bfloat162float(h1));
                size_t base = (size_t)m0 * ldc3 + n0;
                *(__nv_bfloat162*)(C3 + base)          = hp;
                *(__nv_bfloat162*)(C3 + base + offH2c) = hp;
                *(__nv_bfloat162*)(C3 + base + offLc)  = lp;
            }
        }
    }
}

// ---------------- batched tiled transpose (fp32) ----------------
__global__ void transpose_k(const float* __restrict__ in, float* __restrict__ out,
                            int R, int C, long bIn, long bOut)
{
    __shared__ float t[32][33];
    in  += (long)blockIdx.z * bIn;
    out += (long)blockIdx.z * bOut;
    int x = blockIdx.x * 32 + threadIdx.x;
    for (int i = threadIdx.y; i < 32; i += 8) {
        int y = blockIdx.y * 32 + i;
        if (y < R && x < C) t[i][threadIdx.x] = in[(size_t)y * C + x];
    }
    __syncthreads();
    int x2 = blockIdx.y * 32 + threadIdx.x;
    for (int i = threadIdx.y; i < 32; i += 8) {
        int y2 = blockIdx.x * 32 + i;
        if (y2 < C && x2 < R) out[(size_t)y2 * R + x2] = t[threadIdx.x][i];
    }
}

// ---- cvt_kv (fused split-K reduce): lpart[8][T][128] -> lk3, lvTh/l, ksum ----
__global__ __launch_bounds__(256) void cvt_kv(
    const float* __restrict__ lpart, __nv_bfloat16* __restrict__ lk3,
    __half* __restrict__ lvTh, __half* __restrict__ lvTl,
    float* __restrict__ ksum)
{
    __shared__ __half vh[64][65], vl[64][65];
    __shared__ float ksm[64][17];
    const int t0 = blockIdx.x * 64;
    const int tid = threadIdx.x;
    for (int i = tid; i < 64 * 64; i += 256) {
        int r = i >> 6, l = i & 63;
        size_t idx = (size_t)(t0 + r) * 128 + l;
        float kv = 0.f, vv = 0.f;
#pragma unroll
        for (int s = 0; s < 8; s++) {
            kv += lpart[(size_t)s * T_SEQ * 128 + idx];
            vv += lpart[(size_t)s * T_SEQ * 128 + idx + 64];
        }
        __half h = __float2half(vv);
        vh[l][r] = h;
        vl[l][r] = __float2half(vv - __half2float(h));
        __nv_bfloat16 kh = __float2bfloat16(kv);
        __nv_bfloat16 kl = __float2bfloat16(kv - __bfloat162float(kh));
        lk3[(size_t)(t0 + r) * 192 + l]       = kh;
        lk3[(size_t)(t0 + r) * 192 + 64 + l]  = kh;
        lk3[(size_t)(t0 + r) * 192 + 128 + l] = kl;
        // partial ksum: thread covers 16 l-values per r? accumulate via shared
        if (l % 4 == 0) {
            // handled below instead
        }
        if (l == 0) ksm[r][16] = 0.f;
    }
    __syncthreads();
    // ksum: 4 threads per row
    if (tid < 256) {
        int r = tid >> 2, q = tid & 3;
        if (r < 64) {
            float s = 0.f;
            size_t idx = (size_t)(t0 + r) * 128;
            for (int l = q * 16; l < q * 16 + 16; l++) {
                float kv = 0.f;
#pragma unroll
                for (int sp = 0; sp < 8; sp++)
                    kv += lpart[(size_t)sp * T_SEQ * 128 + idx + l];
                s += kv;
            }
            ksm[r][q] = s;
        }
    }
    __syncthreads();
    for (int i = tid; i < 64 * 64; i += 256) {
        int l = i >> 6, r = i & 63;
        lvTh[(size_t)l * T_SEQ + t0 + r] = vh[l][r];
        lvTl[(size_t)l * T_SEQ + t0 + r] = vl[l][r];
    }
    if (tid < 64)
        ksum[t0 + tid] = ksm[tid][0] + ksm[tid][1] + ksm[tid][2] + ksm[tid][3];
}

// ---------------- qsum ----------------
__global__ void qsum_kernel(const float* __restrict__ qlat, float* __restrict__ qsum)
{
    int i = blockIdx.x * blockDim.x + threadIdx.x;
    if (i >= T_SEQ * NH) return;
    float s = 0.f;
#pragma unroll 8
    for (int l = 0; l < LAT; l++) s += qlat[(size_t)i * LAT + l];
    qsum[i] = s;
}

// ========== FA2-style HMMA flash, paired q-tiles for perfect balance ==========
// grid (8, H): CTA i handles q-tiles {15-i, i} -> exactly 34 key-blocks each.
#define FQS 200
#define FVS 136
#define FLASH_SMEM ((128 * FQS + 2 * 64 * FQS + 2 * 80 * FVS) * 2)   // 145920

__global__ __launch_bounds__(256) void flash_hmma(
    const __nv_bfloat16* __restrict__ qlat3, const __nv_bfloat16* __restrict__ lk3,
    const __half* __restrict__ lvTh, const __half* __restrict__ lvTl,
    const float* __restrict__ qsum, const float* __restrict__ ksum,
    __nv_bfloat16* __restrict__ lctx3)
{
    extern __shared__ __align__(16) __nv_bfloat16 smb[];
    __nv_bfloat16* Qs = smb;
    __nv_bfloat16* Ks = Qs + 128 * FQS;
    __half* VT = (__half*)(Ks + 2 * 64 * FQS);
    __shared__ float kss[64];

    const int h = blockIdx.y;
    const int tid = threadIdx.x;
    const int lane = tid & 31;
    const int wid = tid >> 5;
    const int rm = wid * 16;

    const int a_row = lane & 15, a_koff = (lane >> 4) * 8;
    const int b_row = (lane & 7) + ((lane >> 4) & 1) * 8;
    const int b_koff = ((lane >> 3) & 1) * 8;
    const int er = lane >> 2, ec = (lane & 3) * 2;
    const float L2E = 1.4426950408889634f;

    // VT constant rows 64..79 (ones column for row-sum trick)
    for (int i = tid; i < 2 * 16 * FVS; i += 256) {
        int buf = i / (16 * FVS);
        int rr = (i / FVS) % 16;
        int c = i % FVS;
        __half v = __ushort_as_half((unsigned short)0);
        if (rr == 0 && c < 64) v = __float2half(1.0f);
        VT[buf * 80 * FVS + (64 + rr) * FVS + c] = v;
    }

    auto load_kv = [&](int buf, int s0) {
        __nv_bfloat16* ks = Ks + buf * 64 * FQS;
        __half* vt = VT + buf * 80 * FVS;
        for (int i = tid; i < 64 * 24; i += 256) {
            int r = i / 24, c = i % 24;
            CP_ASYNC16(smem_u32(ks + r * FQS + c * 8),
                       lk3 + (size_t)(s0 + r) * 192 + c * 8);
        }
        for (int i = tid; i < 64 * 16; i += 256) {
            int r = i >> 4, c = i & 15;
            const __half* src = (c < 8) ? lvTh : lvTl;
            CP_ASYNC16(smem_u32(vt + r * FVS + c * 8),
                       src + (size_t)r * T_SEQ + s0 + (c & 7) * 8);
        }
    };

#pragma unroll 1
    for (int pass = 0; pass < 2; pass++) {
        const int qt = pass == 0 ? (15 - blockIdx.x) : blockIdx.x;
        const int q0 = qt * 128;
        __syncthreads();

        // Q tile (128 x 192)
        for (int i = tid; i < 128 * 24; i += 256) {
            int r = i / 24, c = i % 24;
            CP_ASYNC16(smem_u32(Qs + r * FQS + c * 8),
                       qlat3 + ((size_t)(q0 + r) * NH + h) * 192 + c * 8);
        }
        load_kv(0, 0); CP_COMMIT();

        const float qss0 = qsum[(size_t)(q0 + rm + er) * NH + h] * 0.0625f;
        const float qss1 = qsum[(size_t)(q0 + rm + er + 8) * NH + h] * 0.0625f;
        const int gi0 = q0 + rm + er, gi1 = gi0 + 8;

        float Oa[9][4];
#pragma unroll
        for (int ni = 0; ni < 9; ni++)
#pragma unroll
            for (int r = 0; r < 4; r++) Oa[ni][r] = 0.f;
        float m0 = -1e30f, m1 = -1e30f;

        const int nkb = 2 * qt + 2;
        for (int kb = 0; kb < nkb; kb++) {
            const int buf = kb & 1;
            const int s0 = kb * 64;
            if (kb + 1 < nkb) { load_kv(buf ^ 1, (kb + 1) * 64); CP_COMMIT(); CP_WAIT1(); }
            else              { CP_WAIT0(); }
            if (tid < 64) kss[tid] = ksum[s0 + tid];
            __syncthreads();

            // ---- S = Q3 @ K3^T ----
            float sacc[8][4];
#pragma unroll
            for (int ni = 0; ni < 8; ni++)
#pragma unroll
                for (int r = 0; r < 4; r++) sacc[ni][r] = 0.f;
            const uint32_t aQrow = smem_u32(Qs) + ((rm + a_row) * FQS + a_koff) * 2;
            const uint32_t sKb = smem_u32(Ks) + (uint32_t)(buf * 64 * FQS) * 2;
#pragma unroll
            for (int kk = 0; kk < 192; kk += 16) {
                uint32_t af[4];
                ldmx4(af[0], af[1], af[2], af[3], aQrow + kk * 2);
                uint32_t bfr[8][2];
#pragma unroll
                for (int n4 = 0; n4 < 4; n4++) {
                    uint32_t r0, r1, r2, r3;
                    ldmx4(r0, r1, r2, r3, sKb + ((n4 * 16 + b_row) * FQS + kk + b_koff) * 2);
                    bfr[n4 * 2 + 0][0] = r0; bfr[n4 * 2 + 0][1] = r1;
                    bfr[n4 * 2 + 1][0] = r2; bfr[n4 * 2 + 1][1] = r3;
                }
#pragma unroll
                for (int ni = 0; ni < 8; ni++) mma16816(sacc[ni], af, bfr[ni]);
            }

            // ---- scale + causal mask + reciprocal band ----
#pragma unroll
            for (int ni = 0; ni < 8; ni++) {
#pragma unroll
                for (int cc = 0; cc < 2; cc++) {
                    int gj = s0 + ni * 8 + ec + cc;
                    float ksv = kss[ni * 8 + ec + cc];
                    float v = sacc[ni][cc] * 0.125f;
                    if (gi0 - gj <= 64) v += qss0 * ksv;
                    sacc[ni][cc] = (gj <= gi0) ? v : -1e30f;
                    float w = sacc[ni][2 + cc] * 0.125f;
                    if (gi1 - gj <= 64) w += qss1 * ksv;
                    sacc[ni][2 + cc] = (gj <= gi1) ? w : -1e30f;
                }
            }

            // ---- online softmax (registers) ----
            float mx0 = -1e30f, mx1 = -1e30f;
#pragma unroll
            for (int ni = 0; ni < 8; ni++) {
                mx0 = fmaxf(mx0, fmaxf(sacc[ni][0], sacc[ni][1]));
                mx1 = fmaxf(mx1, fmaxf(sacc[ni][2], sacc[ni][3]));
            }
            mx0 = fmaxf(mx0, __shfl_xor_sync(0xffffffffu, mx0, 1));
            mx0 = fmaxf(mx0, __shfl_xor_sync(0xffffffffu, mx0, 2));
            mx1 = fmaxf(mx1, __shfl_xor_sync(0xffffffffu, mx1, 1));
            mx1 = fmaxf(mx1, __shfl_xor_sync(0xffffffffu, mx1, 2));
            float mn0 = fmaxf(m0, mx0), mn1 = fmaxf(m1, mx1);
            float al0 = exp2f((m0 - mn0) * L2E);
            float al1 = exp2f((m1 - mn1) * L2E);
            m0 = mn0; m1 = mn1;
#pragma unroll
            for (int ni = 0; ni < 9; ni++) {
                Oa[ni][0] *= al0; Oa[ni][1] *= al0;
                Oa[ni][2] *= al1; Oa[ni][3] *= al1;
            }
            uint32_t p01[8], p23[8];
#pragma unroll
            for (int ni = 0; ni < 8; ni++) {
                float x0 = (sacc[ni][0] - mn0) * L2E;
                float x1 = (sacc[ni][1] - mn0) * L2E;
                float x2 = (sacc[ni][2] - mn1) * L2E;
                float x3 = (sacc[ni][3] - mn1) * L2E;
                uint32_t hx;
                asm("cvt.rn.f16x2.f32 %0, %1, %2;" : "=r"(hx) : "f"(x1), "f"(x0));
                asm("ex2.approx.f16x2 %0, %1;" : "=r"(p01[ni]) : "r"(hx));
                asm("cvt.rn.f16x2.f32 %0, %1, %2;" : "=r"(hx) : "f"(x3), "f"(x2));
                asm("ex2.approx.f16x2 %0, %1;" : "=r"(p23[ni]) : "r"(hx));
            }

            // ---- O += P @ [Vh ; Vl]^T ----
            const uint32_t sVb = smem_u32(VT) + (uint32_t)(buf * 80 * FVS) * 2;
#pragma unroll
            for (int term = 0; term < 2; term++) {
#pragma unroll
                for (int kk = 0; kk < 64; kk += 16) {
                    int f = kk >> 3;
                    uint32_t af[4] = { p01[f], p23[f], p01[f + 1], p23[f + 1] };
                    uint32_t bfr[10][2];
#pragma unroll
                    for (int n4 = 0; n4 < 5; n4++) {
                        uint32_t r0, r1, r2, r3;
                        ldmx4(r0, r1, r2, r3,
                              sVb + ((n4 * 16 + b_row) * FVS + term * 64 + kk + b_koff) * 2);
                        bfr[n4 * 2 + 0][0] = r0; bfr[n4 * 2 + 0][1] = r1;
                        bfr[n4 * 2 + 1][0] = r2; bfr[n4 * 2 + 1][1] = r3;
                    }
#pragma unroll
                    for (int ni = 0; ni < 9; ni++) mma16816h(Oa[ni], af, bfr[ni]);
                }
            }
            __syncthreads();
        }

        // ---- epilogue ----
        float ls0 = __shfl_sync(0xffffffffu, Oa[8][0], lane & ~3);
        float ls1 = __shfl_sync(0xffffffffu, Oa[8][2], lane & ~3);
        float li0 = 1.f / ls0, li1 = 1.f / ls1;
        const int t0 = q0 + rm + er, t1 = t0 + 8;
#pragma unroll
        for (int ni = 0; ni < 8; ni++) {
            int c0 = ni * 8 + ec;
            float v0 = Oa[ni][0] * li0, v1 = Oa[ni][1] * li0;
            float v2 = Oa[ni][2] * li1, v3 = Oa[ni][3] * li1;
            __nv_bfloat16 h0 = __float2bfloat16(v0), h1 = __float2bfloat16(v1);
            __nv_bfloat162 hp0; hp0.x = h0; hp0.y = h1;
            __nv_bfloat162 lp0;
            lp0.x = __float2bfloat16(v0 - __bfloat162float(h0));
            lp0.y = __float2bfloat16(v1 - __bfloat162float(h1));
            size_t b0 = (size_t)t0 * 3072 + h * 64 + c0;
            *(__nv_bfloat162*)(lctx3 + b0)        = hp0;
            *(__nv_bfloat162*)(lctx3 + b0 + 1024) = lp0;
            *(__nv_bfloat162*)(lctx3 + b0 + 2048) = hp0;
            __nv_bfloat16 h2 = __float2bfloat16(v2), h3 = __float2bfloat16(v3);
            __nv_bfloat162 hp1; hp1.x = h2; hp1.y = h3;
            __nv_bfloat162 lp1;
            lp1.x = __float2bfloat16(v2 - __bfloat162float(h2));
            lp1.y = __float2bfloat16(v3 - __bfloat162float(h3));
            size_t b1 = (size_t)t1 * 3072 + h * 64 + c0;
            *(__nv_bfloat162*)(lctx3 + b1)        = hp1;
            *(__nv_bfloat162*)(lctx3 + b1 + 1024) = lp1;
            *(__nv_bfloat162*)(lctx3 + b1 + 2048) = hp1;
        }
    }
}

// ---------------- host launcher ----------------
extern "C" void kernel_launch(void* const* d_in, const int* in_sizes, int n_in,
                              void* d_out, int out_size)
{
    const float* hidden = (const float*)d_in[0];
    const float* Wq  = (const float*)d_in[1];
    const float* Wk  = (const float*)d_in[2];
    const float* Wv  = (const float*)d_in[3];
    const float* q2l = (const float*)d_in[4];
    const float* vup = (const float*)d_in[5];
    const float* Wo  = (const float*)d_in[6];
    float* out = (float*)d_out;

    float *q2lT, *lpart, *qlat, *qs, *ks;
    __nv_bfloat16 *hid3, *WqT3, *Wo3, *q2l3p, *vup3p, *Wf13, *Wf23, *Wkv3, *qlat3, *lk3, *lctx3;
    __half *lvTh, *lvTl;
    cudaGetSymbolAddress((void**)&q2lT,  g_q2lT);
    cudaGetSymbolAddress((void**)&lpart, g_lpart);
    cudaGetSymbolAddress((void**)&qlat,  g_qlat);
    cudaGetSymbolAddress((void**)&qs,    g_qsum);
    cudaGetSymbolAddress((void**)&ks,    g_ksum);
    cudaGetSymbolAddress((void**)&hid3,  g_hid3);
    cudaGetSymbolAddress((void**)&WqT3,  g_WqT3);
    cudaGetSymbolAddress((void**)&Wo3,   g_Wo3);
    cudaGetSymbolAddress((void**)&q2l3p, g_q2l3p);
    cudaGetSymbolAddress((void**)&vup3p, g_vup3p);
    cudaGetSymbolAddress((void**)&Wf13,  g_Wf13);
    cudaGetSymbolAddress((void**)&Wf23,  g_Wf23);
    cudaGetSymbolAddress((void**)&Wkv3,  g_Wkv3);
    cudaGetSymbolAddress((void**)&qlat3, g_qlat3);
    cudaGetSymbolAddress((void**)&lk3,   g_lk3);
    cudaGetSymbolAddress((void**)&lvTh,  g_lvTh);
    cudaGetSymbolAddress((void**)&lvTl,  g_lvTl);
    cudaGetSymbolAddress((void**)&lctx3, g_lctx3);

    cudaFuncSetAttribute(hmma_gemm,
                         cudaFuncAttributeMaxDynamicSharedMemorySize, HMMA_SMEM);
    cudaFuncSetAttribute(hmma_fold,
                         cudaFuncAttributeMaxDynamicSharedMemorySize, HMMA_SMEM);
    cudaFuncSetAttribute(flash_hmma,
                         cudaFuncAttributeMaxDynamicSharedMemorySize, FLASH_SMEM);

    // --- weight preprocessing ---
    transpose_k<<<dim3(2, 4, NH), dim3(32, 8)>>>(q2l, q2lT, HD, LAT,
                                                 (long)HD * LAT, (long)LAT * HD);
    transpose_split3<<<dim3(64, 64), dim3(32, 8)>>>(Wq, WqT3);            // B [hi|hi|lo]
    cvt_split3<<<(EMB * EMB / 4 + 255) / 256, 256>>>(
        Wo, Wo3, EMB * EMB, HD, 2 * HD, HD);                              // A [hi|lo|hi]
    cvt_split3_pad<<<(NH * HD * HD / 4 + 255) / 256, 256>>>(
        q2lT, q2l3p, NH, LAT, HD, HD, 2 * HD, HD);                        // A [hi|lo|hi], padded
    cvt_split3_pad<<<(NH * HD * HD / 4 + 255) / 256, 256>>>(
        vup, vup3p, NH, LAT, HD, HD, HD, 2 * HD);                         // B [hi|hi|lo], padded

    // --- folds on tensor cores, writing bf16 splits directly ---
    // Wf13[h*64+l][3*2048] = split( q2l3p[h] @ (WqT3 head slice)^T )
    hmma_fold<<<dim3(16, 1, NH), 256, HMMA_SMEM>>>(
        q2l3p, WqT3, Wf13, 3 * HD, 3 * HD, NH * 3 * HD,
        (long)HD * 3 * HD, (long)3 * HD, (long)LAT * 3 * EMB,
        3 * EMB, EMB, 2 * EMB, LAT, EMB);
    // Wf23[e][3*1024] (cols h*64+l) = split( Wo3 head slice @ vup3p[h]^T )
    hmma_fold<<<dim3(1, 16, NH), 256, HMMA_SMEM>>>(
        Wo3, vup3p, Wf23, 3 * HD, NH * 3 * HD, 3 * HD,
        (long)3 * HD, (long)HD * 3 * HD, (long)LAT,
        3 * NH * LAT, NH * LAT, 2 * NH * LAT, EMB, LAT);

    // --- input splits ---
    cvt_split3<<<(T_SEQ * EMB / 4 + 255) / 256, 256>>>(
        hidden, hid3, T_SEQ * EMB, EMB, 2 * EMB, EMB);
    cvt_split3<<<(LAT * EMB / 4 + 255) / 256, 256>>>(
        Wk, Wkv3, LAT * EMB, EMB, EMB, 2 * EMB);
    cvt_split3<<<(LAT * EMB / 4 + 255) / 256, 256>>>(
        Wv, Wkv3 + (size_t)LAT * 3 * EMB, LAT * EMB, EMB, EMB, 2 * EMB);

    // --- lkv = hidden @ [Wk;Wv]^T  (HMMA split-K x8; reduce fused in cvt_kv) ---
    hmma_gemm<<<dim3(1, 16, 8), 256, HMMA_SMEM>>>(hid3, Wkv3, lpart,
                                                  T_SEQ, 2 * LAT, 3 * EMB, 8);
    cvt_kv<<<32, 256>>>(lpart, lk3, lvTh, lvTl, ks);

    // --- q_latent = hidden @ Wf1^T  [2048 x 1024]  (HMMA) ---
    hmma_gemm<<<dim3(8, 16, 1), 256, HMMA_SMEM>>>(hid3, Wf13, qlat,
                                                  T_SEQ, NH * LAT, 3 * EMB, 1);
    cvt_split3<<<(T_SEQ * NH * LAT / 4 + 255) / 256, 256>>>(
        qlat, qlat3, T_SEQ * NH * LAT, LAT, 2 * LAT, LAT);
    qsum_kernel<<<(T_SEQ * NH + 255) / 256, 256>>>(qlat, qs);

    // --- FA2-style HMMA flash attention (paired q-tiles) ---
    flash_hmma<<<dim3(8, NH), 256, FLASH_SMEM>>>(qlat3, lk3, lvTh, lvTl, qs, ks, lctx3);

    // --- out = lctx @ Wf2T^T  [2048 x 2048]  (HMMA) ---
    hmma_gemm<<<dim3(16, 16, 1), 256, HMMA_SMEM>>>(lctx3, Wf23, out,
                                                   T_SEQ, EMB, 3 * NH * LAT, 1);
}

// round 10
// speedup vs baseline: 5.2080x; 1.0146x over previous
#include <cuda_runtime.h>
#include <cuda_bf16.h>
#include <cuda_fp16.h>
#include <cstdint>

#define T_SEQ 2048
#define EMB   2048
#define NH    16
#define HD    128
#define LAT   64

// ---------------- scratch (static device globals; no allocation) ----------------
__device__ float g_q2lT[NH * LAT * HD];
__device__ float g_lpart[8 * T_SEQ * 2 * LAT];
__device__ float g_qsum[T_SEQ * NH];
__device__ float g_ksum[T_SEQ];
// bf16 K-extended split buffers
__device__ __align__(16) __nv_bfloat16 g_hid3 [T_SEQ * 3 * EMB];        // A [hi|lo|hi]
__device__ __align__(16) __nv_bfloat16 g_WqT3 [EMB * NH * 3 * HD];      // B [hi|hi|lo]
__device__ __align__(16) __nv_bfloat16 g_Wo3  [EMB * NH * 3 * HD];      // A [hi|lo|hi]
__device__ __align__(16) __nv_bfloat16 g_q2l3p[NH * HD * 3 * HD];       // A, padded rows
__device__ __align__(16) __nv_bfloat16 g_vup3p[NH * HD * 3 * HD];       // B, padded rows
__device__ __align__(16) __nv_bfloat16 g_Wf13 [NH * LAT * 3 * EMB];     // B [hi|hi|lo]
__device__ __align__(16) __nv_bfloat16 g_Wf23 [EMB * 3 * NH * LAT];     // B [hi|hi|lo]
__device__ __align__(16) __nv_bfloat16 g_Wkv3 [2 * LAT * 3 * EMB];      // B [hi|hi|lo]
__device__ __align__(16) __nv_bfloat16 g_qlat3[T_SEQ * NH * 3 * LAT];   // A [hi|lo|hi]
__device__ __align__(16) __nv_bfloat16 g_lk3  [T_SEQ * 3 * LAT];        // B [hi|hi|lo]
__device__ __align__(16) __half        g_lvTh [LAT * T_SEQ];            // V^T (fp16)
__device__ __align__(16) __nv_bfloat16 g_lctx3[T_SEQ * 3 * NH * LAT];   // A [hi|lo|hi]

// ================= PTX helpers (baseline compute_103-safe only) =================
__device__ __forceinline__ uint32_t smem_u32(const void* p) {
    uint32_t a;
    asm("{ .reg .u64 t; cvta.to.shared.u64 t, %1; cvt.u32.u64 %0, t; }" : "=r"(a) : "l"(p));
    return a;
}
#define CP_ASYNC16(dst, src) \
    asm volatile("cp.async.cg.shared.global [%0], [%1], 16;" :: "r"(dst), "l"(src))
#define CP_COMMIT() asm volatile("cp.async.commit_group;")
#define CP_WAIT1()  asm volatile("cp.async.wait_group 1;")
#define CP_WAIT0()  asm volatile("cp.async.wait_group 0;")

__device__ __forceinline__ void ldmx4(uint32_t& r0, uint32_t& r1, uint32_t& r2, uint32_t& r3,
                                      uint32_t addr) {
    asm volatile("ldmatrix.sync.aligned.m8n8.x4.shared.b16 {%0,%1,%2,%3}, [%4];"
                 : "=r"(r0), "=r"(r1), "=r"(r2), "=r"(r3) : "r"(addr));
}
__device__ __forceinline__ void mma16816(float* d, const uint32_t* a, const uint32_t* b) {
    asm volatile("mma.sync.aligned.m16n8k16.row.col.f32.bf16.bf16.f32 "
                 "{%0,%1,%2,%3}, {%4,%5,%6,%7}, {%8,%9}, {%0,%1,%2,%3};"
                 : "+f"(d[0]), "+f"(d[1]), "+f"(d[2]), "+f"(d[3])
                 : "r"(a[0]), "r"(a[1]), "r"(a[2]), "r"(a[3]), "r"(b[0]), "r"(b[1]));
}
__device__ __forceinline__ void mma16816h(float* d, const uint32_t* a, const uint32_t* b) {
    asm volatile("mma.sync.aligned.m16n8k16.row.col.f32.f16.f16.f32 "
                 "{%0,%1,%2,%3}, {%4,%5,%6,%7}, {%8,%9}, {%0,%1,%2,%3};"
                 : "+f"(d[0]), "+f"(d[1]), "+f"(d[2]), "+f"(d[3])
                 : "r"(a[0]), "r"(a[1]), "r"(a[2]), "r"(a[3]), "r"(b[0]), "r"(b[1]));
}

// ---------------- fp32 -> K-extended bf16 hi/lo split ----------------
__global__ void cvt_split3(const float* __restrict__ x, __nv_bfloat16* __restrict__ out,
                           int total, int K, int offH2, int offL)
{
    int i = (blockIdx.x * blockDim.x + threadIdx.x) * 4;
    if (i >= total) return;
    float4 v = *(const float4*)(x + i);
    float vv[4] = {v.x, v.y, v.z, v.w};
    __nv_bfloat16 hb[4], lb[4];
#pragma unroll
    for (int k = 0; k < 4; k++) {
        hb[k] = __float2bfloat16(vv[k]);
        lb[k] = __float2bfloat16(vv[k] - __bfloat162float(hb[k]));
    }
    int r = i / K, c = i - r * K;
    size_t base = (size_t)r * 3 * K + c;
    *(uint2*)(out + base)         = *(uint2*)hb;
    *(uint2*)(out + base + offH2) = *(uint2*)hb;
    *(uint2*)(out + base + offL)  = *(uint2*)lb;
}

// ---- padded batched variant ----
__global__ void cvt_split3_pad(const float* __restrict__ x, __nv_bfloat16* __restrict__ out,
                               int nb, int rows, int K, int padRows, int offH2, int offL)
{
    int i = (blockIdx.x * blockDim.x + threadIdx.x) * 4;
    int total = nb * padRows * K;
    if (i >= total) return;
    int b = i / (padRows * K);
    int rem = i - b * (padRows * K);
    int r = rem / K, c = rem - r * K;
    float vv[4] = {0.f, 0.f, 0.f, 0.f};
    if (r < rows) {
        float4 v = *(const float4*)(x + (size_t)b * rows * K + (size_t)r * K + c);
        vv[0] = v.x; vv[1] = v.y; vv[2] = v.z; vv[3] = v.w;
    }
    __nv_bfloat16 hb[4], lb[4];
#pragma unroll
    for (int k = 0; k < 4; k++) {
        hb[k] = __float2bfloat16(vv[k]);
        lb[k] = __float2bfloat16(vv[k] - __bfloat162float(hb[k]));
    }
    size_t base = (size_t)b * padRows * 3 * K + (size_t)r * 3 * K + c;
    *(uint2*)(out + base)         = *(uint2*)hb;
    *(uint2*)(out + base + offH2) = *(uint2*)hb;
    *(uint2*)(out + base + offL)  = *(uint2*)lb;
}

// ---- fused transpose + split: Wq [hd][e] -> WqT3 [e][h][384] B-layout ----
__global__ void transpose_split3(const float* __restrict__ in, __nv_bfloat16* __restrict__ out)
{
    __shared__ float t[32][33];
    int x = blockIdx.x * 32 + threadIdx.x;
    for (int i = threadIdx.y; i < 32; i += 8) {
        int y = blockIdx.y * 32 + i;
        t[i][threadIdx.x] = in[(size_t)y * EMB + x];
    }
    __syncthreads();
    for (int i = threadIdx.y; i < 32; i += 8) {
        int eo = blockIdx.x * 32 + i;
        int hd = blockIdx.y * 32 + threadIdx.x;
        float v = t[threadIdx.x][i];
        __nv_bfloat16 h = __float2bfloat16(v);
        __nv_bfloat16 l = __float2bfloat16(v - __bfloat162float(h));
        int hh = hd >> 7, d = hd & 127;
        size_t base = (size_t)eo * (NH * 3 * HD) + hh * 384 + d;
        out[base]       = h;
        out[base + 128] = h;
        out[base + 256] = l;
    }
}

// ============== HMMA bf16 GEMM (+split-K): C = A[M,K] @ B[N,K]^T ==============
#define GS 72
#define STAGE_ELTS (128 * GS)
#define HMMA_SMEM (3 * 2 * STAGE_ELTS * 2)

__global__ __launch_bounds__(256) void hmma_gemm(
    const __nv_bfloat16* __restrict__ A, const __nv_bfloat16* __restrict__ B,
    float* __restrict__ C, int M, int N, int K, int nsplit)
{
    extern __shared__ __align__(16) __nv_bfloat16 sm[];
    const int tid = threadIdx.x;
    const int wid = tid >> 5;
    const int lane = tid & 31;
    const int warp_m = wid >> 2;
    const int warp_n = wid & 3;
    const int bm = blockIdx.y * 128;
    const int bn = blockIdx.x * 128;
    const uint32_t sbase = smem_u32(sm);

    const int Kc = K / nsplit;
    const int kbeg = blockIdx.z * Kc;
    C += (size_t)blockIdx.z * M * N;
    const int nk = Kc >> 6;

    auto load_stage = [&](int stage, int k0) {
        __nv_bfloat16* As = sm + stage * 2 * STAGE_ELTS;
        __nv_bfloat16* Bs = As + STAGE_ELTS;
#pragma unroll
        for (int i = 0; i < 4; i++) {
            int c = tid + i * 256;
            int row = c >> 3;
            int col8 = (c & 7) * 8;
            CP_ASYNC16(smem_u32(As + row * GS + col8),
                       A + (size_t)(bm + row) * K + kbeg + k0 + col8);
            CP_ASYNC16(smem_u32(Bs + row * GS + col8),
                       B + (size_t)(bn + row) * K + kbeg + k0 + col8);
        }
    };

    float acc[4][4][4];
#pragma unroll
    for (int mi = 0; mi < 4; mi++)
#pragma unroll
        for (int ni = 0; ni < 4; ni++)
#pragma unroll
            for (int r = 0; r < 4; r++) acc[mi][ni][r] = 0.f;

    load_stage(0, 0); CP_COMMIT();
    if (nk > 1) { load_stage(1, 64); CP_COMMIT(); }

    const int a_row = (lane & 15);
    const int a_koff = (lane >> 4) * 8;
    const int b_row = (lane & 7) + ((lane >> 4) & 1) * 8;
    const int b_koff = ((lane >> 3) & 1) * 8;

    for (int it = 0; it < nk; it++) {
        CP_WAIT1();
        __syncthreads();
        if (it + 2 < nk) { load_stage((it + 2) % 3, (it + 2) * 64); CP_COMMIT(); }

        const int stage = it % 3;
        const uint32_t sA = sbase + (uint32_t)(stage * 2 * STAGE_ELTS) * 2;
        const uint32_t sB = sA + STAGE_ELTS * 2;

#pragma unroll
        for (int kk = 0; kk < 64; kk += 16) {
            uint32_t af[4][4];
#pragma unroll
            for (int mi = 0; mi < 4; mi++) {
                uint32_t addr = sA + ((warp_m * 64 + mi * 16 + a_row) * GS + kk + a_koff) * 2;
                ldmx4(af[mi][0], af[mi][1], af[mi][2], af[mi][3], addr);
            }
            uint32_t bf[4][2];
#pragma unroll
            for (int ni2 = 0; ni2 < 2; ni2++) {
                uint32_t addr = sB + ((warp_n * 32 + ni2 * 16 + b_row) * GS + kk + b_koff) * 2;
                uint32_t r0, r1, r2, r3;
                ldmx4(r0, r1, r2, r3, addr);
                bf[ni2 * 2 + 0][0] = r0; bf[ni2 * 2 + 0][1] = r1;
                bf[ni2 * 2 + 1][0] = r2; bf[ni2 * 2 + 1][1] = r3;
            }
#pragma unroll
            for (int mi = 0; mi < 4; mi++)
#pragma unroll
                for (int ni = 0; ni < 4; ni++)
                    mma16816(acc[mi][ni], af[mi], bf[ni]);
        }
        __syncthreads();
    }

    const int er = lane >> 2;
    const int ec = (lane & 3) * 2;
#pragma unroll
    for (int mi = 0; mi < 4; mi++) {
#pragma unroll
        for (int ni = 0; ni < 4; ni++) {
            int m0 = bm + warp_m * 64 + mi * 16 + er;
            int n0 = bn + warp_n * 32 + ni * 8 + ec;
            *(float2*)(C + (size_t)m0 * N + n0) = make_float2(acc[mi][ni][0], acc[mi][ni][1]);
            *(float2*)(C + (size_t)(m0 + 8) * N + n0) = make_float2(acc[mi][ni][2], acc[mi][ni][3]);
        }
    }
}

// ==== hmma_qlat: GEMM1 writing qlat3 A-layout [hi|lo|hi] split directly ====
// C = hid3[M,K] @ Wf13[N,K]^T ; N = 1024 (h*64+l); out row stride 192 per (t,h).
__global__ __launch_bounds__(256) void hmma_qlat(
    const __nv_bfloat16* __restrict__ A, const __nv_bfloat16* __restrict__ B,
    __nv_bfloat16* __restrict__ Q3, int K)
{
    extern __shared__ __align__(16) __nv_bfloat16 sm[];
    const int tid = threadIdx.x;
    const int wid = tid >> 5;
    const int lane = tid & 31;
    const int warp_m = wid >> 2;
    const int warp_n = wid & 3;
    const int bm = blockIdx.y * 128;
    const int bn = blockIdx.x * 128;
    const uint32_t sbase = smem_u32(sm);
    const int nk = K >> 6;

    auto load_stage = [&](int stage, int k0) {
        __nv_bfloat16* As = sm + stage * 2 * STAGE_ELTS;
        __nv_bfloat16* Bs = As + STAGE_ELTS;
#pragma unroll
        for (int i = 0; i < 4; i++) {
            int c = tid + i * 256;
            int row = c >> 3;
            int col8 = (c & 7) * 8;
            CP_ASYNC16(smem_u32(As + row * GS + col8),
                       A + (size_t)(bm + row) * K + k0 + col8);
            CP_ASYNC16(smem_u32(Bs + row * GS + col8),
                       B + (size_t)(bn + row) * K + k0 + col8);
        }
    };

    float acc[4][4][4];
#pragma unroll
    for (int mi = 0; mi < 4; mi++)
#pragma unroll
        for (int ni = 0; ni < 4; ni++)
#pragma unroll
            for (int r = 0; r < 4; r++) acc[mi][ni][r] = 0.f;

    load_stage(0, 0); CP_COMMIT();
    if (nk > 1) { load_stage(1, 64); CP_COMMIT(); }

    const int a_row = (lane & 15);
    const int a_koff = (lane >> 4) * 8;
    const int b_row = (lane & 7) + ((lane >> 4) & 1) * 8;
    const int b_koff = ((lane >> 3) & 1) * 8;

    for (int it = 0; it < nk; it++) {
        CP_WAIT1();
        __syncthreads();
        if (it + 2 < nk) { load_stage((it + 2) % 3, (it + 2) * 64); CP_COMMIT(); }

        const int stage = it % 3;
        const uint32_t sA = sbase + (uint32_t)(stage * 2 * STAGE_ELTS) * 2;
        const uint32_t sB = sA + STAGE_ELTS * 2;

#pragma unroll
        for (int kk = 0; kk < 64; kk += 16) {
            uint32_t af[4][4];
#pragma unroll
            for (int mi = 0; mi < 4; mi++) {
                uint32_t addr = sA + ((warp_m * 64 + mi * 16 + a_row) * GS + kk + a_koff) * 2;
                ldmx4(af[mi][0], af[mi][1], af[mi][2], af[mi][3], addr);
            }
            uint32_t bf[4][2];
#pragma unroll
            for (int ni2 = 0; ni2 < 2; ni2++) {
                uint32_t addr = sB + ((warp_n * 32 + ni2 * 16 + b_row) * GS + kk + b_koff) * 2;
                uint32_t r0, r1, r2, r3;
                ldmx4(r0, r1, r2, r3, addr);
                bf[ni2 * 2 + 0][0] = r0; bf[ni2 * 2 + 0][1] = r1;
                bf[ni2 * 2 + 1][0] = r2; bf[ni2 * 2 + 1][1] = r3;
            }
#pragma unroll
            for (int mi = 0; mi < 4; mi++)
#pragma unroll
                for (int ni = 0; ni < 4; ni++)
                    mma16816(acc[mi][ni], af[mi], bf[ni]);
        }
        __syncthreads();
    }

    const int er = lane >> 2;
    const int ec = (lane & 3) * 2;
#pragma unroll
    for (int mi = 0; mi < 4; mi++) {
#pragma unroll
        for (int ni = 0; ni < 4; ni++) {
            int n0 = bn + warp_n * 32 + ni * 8 + ec;
            int h = n0 >> 6, l = n0 & 63;
#pragma unroll
            for (int rr = 0; rr < 2; rr++) {
                int m0 = bm + warp_m * 64 + mi * 16 + er + rr * 8;
                float v0 = acc[mi][ni][rr * 2 + 0];
                float v1 = acc[mi][ni][rr * 2 + 1];
                __nv_bfloat16 h0 = __float2bfloat16(v0), h1 = __float2bfloat16(v1);
                __nv_bfloat162 hp; hp.x = h0; hp.y = h1;
                __nv_bfloat162 lp;
                lp.x = __float2bfloat16(v0 - __bfloat162float(h0));
                lp.y = __float2bfloat16(v1 - __bfloat162float(h1));
                size_t base = ((size_t)m0 * NH + h) * 192 + l;
                *(__nv_bfloat162*)(Q3 + base)       = hp;   // hi
                *(__nv_bfloat162*)(Q3 + base + 64)  = lp;   // lo
                *(__nv_bfloat162*)(Q3 + base + 128) = hp;   // hi
            }
        }
    }
}

// ==== HMMA fold GEMM: batched, strided operands, bf16 split-writing epilogue ====
__global__ __launch_bounds__(256) void hmma_fold(
    const __nv_bfloat16* __restrict__ A, const __nv_bfloat16* __restrict__ B,
    __nv_bfloat16* __restrict__ C3, int K, int lda, int ldb,
    long batchA, long batchB, long batchC,
    int ldc3, int offH2c, int offLc, int validM, int validN)
{
    extern __shared__ __align__(16) __nv_bfloat16 sm[];
    const int tid = threadIdx.x;
    const int wid = tid >> 5;
    const int lane = tid & 31;
    const int warp_m = wid >> 2;
    const int warp_n = wid & 3;
    const int bm = blockIdx.y * 128;
    const int bn = blockIdx.x * 128;
    const uint32_t sbase = smem_u32(sm);

    A  += (size_t)blockIdx.z * batchA;
    B  += (size_t)blockIdx.z * batchB;
    C3 += (size_t)blockIdx.z * batchC;
    const int nk = K >> 6;

    auto load_stage = [&](int stage, int k0) {
        __nv_bfloat16* As = sm + stage * 2 * STAGE_ELTS;
        __nv_bfloat16* Bs = As + STAGE_ELTS;
#pragma unroll
        for (int i = 0; i < 4; i++) {
            int c = tid + i * 256;
            int row = c >> 3;
            int col8 = (c & 7) * 8;
            CP_ASYNC16(smem_u32(As + row * GS + col8),
                       A + (size_t)(bm + row) * lda + k0 + col8);
            CP_ASYNC16(smem_u32(Bs + row * GS + col8),
                       B + (size_t)(bn + row) * ldb + k0 + col8);
        }
    };

    float acc[4][4][4];
#pragma unroll
    for (int mi = 0; mi < 4; mi++)
#pragma unroll
        for (int ni = 0; ni < 4; ni++)
#pragma unroll
            for (int r = 0; r < 4; r++) acc[mi][ni][r] = 0.f;

    load_stage(0, 0); CP_COMMIT();
    if (nk > 1) { load_stage(1, 64); CP_COMMIT(); }

    const int a_row = (lane & 15);
    const int a_koff = (lane >> 4) * 8;
    const int b_row = (lane & 7) + ((lane >> 4) & 1) * 8;
    const int b_koff = ((lane >> 3) & 1) * 8;

    for (int it = 0; it < nk; it++) {
        CP_WAIT1();
        __syncthreads();
        if (it + 2 < nk) { load_stage((it + 2) % 3, (it + 2) * 64); CP_COMMIT(); }

        const int stage = it % 3;
        const uint32_t sA = sbase + (uint32_t)(stage * 2 * STAGE_ELTS) * 2;
        const uint32_t sB = sA + STAGE_ELTS * 2;

#pragma unroll
        for (int kk = 0; kk < 64; kk += 16) {
            uint32_t af[4][4];
#pragma unroll
            for (int mi = 0; mi < 4; mi++) {
                uint32_t addr = sA + ((warp_m * 64 + mi * 16 + a_row) * GS + kk + a_koff) * 2;
                ldmx4(af[mi][0], af[mi][1], af[mi][2], af[mi][3], addr);
            }
            uint32_t bf[4][2];
#pragma unroll
            for (int ni2 = 0; ni2 < 2; ni2++) {
                uint32_t addr = sB + ((warp_n * 32 + ni2 * 16 + b_row) * GS + kk + b_koff) * 2;
                uint32_t r0, r1, r2, r3;
                ldmx4(r0, r1, r2, r3, addr);
                bf[ni2 * 2 + 0][0] = r0; bf[ni2 * 2 + 0][1] = r1;
                bf[ni2 * 2 + 1][0] = r2; bf[ni2 * 2 + 1][1] = r3;
            }
#pragma unroll
            for (int mi = 0; mi < 4; mi++)
#pragma unroll
                for (int ni = 0; ni < 4; ni++)
                    mma16816(acc[mi][ni], af[mi], bf[ni]);
        }
        __syncthreads();
    }

    const int er = lane >> 2;
    const int ec = (lane & 3) * 2;
#pragma unroll
    for (int mi = 0; mi < 4; mi++) {
#pragma unroll
        for (int ni = 0; ni < 4; ni++) {
            int n0 = bn + warp_n * 32 + ni * 8 + ec;
            if (n0 >= validN) continue;
#pragma unroll
            for (int rr = 0; rr < 2; rr++) {
                int m0 = bm + warp_m * 64 + mi * 16 + er + rr * 8;
                if (m0 >= validM) continue;
                float v0 = acc[mi][ni][rr * 2 + 0];
                float v1 = acc[mi][ni][rr * 2 + 1];
                __nv_bfloat16 h0 = __float2bfloat16(v0), h1 = __float2bfloat16(v1);
                __nv_bfloat162 hp; hp.x = h0; hp.y = h1;
                __nv_bfloat162 lp;
                lp.x = __float2bfloat16(v0 - __bfloat162float(h0));
                lp.y = __float2bfloat16(v1 - __bfloat162float(h1));
                size_t base = (size_t)m0 * ldc3 + n0;
                *(__nv_bfloat162*)(C3 + base)          = hp;
                *(__nv_bfloat162*)(C3 + base + offH2c) = hp;
                *(__nv_bfloat162*)(C3 + base + offLc)  = lp;
            }
        }
    }
}

// ---------------- batched tiled transpose (fp32) ----------------
__global__ void transpose_k(const float* __restrict__ in, float* __restrict__ out,
                            int R, int C, long bIn, long bOut)
{
    __shared__ float t[32][33];
    in  += (long)blockIdx.z * bIn;
    out += (long)blockIdx.z * bOut;
    int x = blockIdx.x * 32 + threadIdx.x;
    for (int i = threadIdx.y; i < 32; i += 8) {
        int y = blockIdx.y * 32 + i;
        if (y < R && x < C) t[i][threadIdx.x] = in[(size_t)y * C + x];
    }
    __syncthreads();
    int x2 = blockIdx.y * 32 + threadIdx.x;
    for (int i = threadIdx.y; i < 32; i += 8) {
        int y2 = blockIdx.x * 32 + i;
        if (y2 < C && x2 < R) out[(size_t)y2 * R + x2] = t[threadIdx.x][i];
    }
}

// ---- cvt_kv (fused split-K reduce): lpart[8][T][128] -> lk3, lvTh (f16), ksum ----
__global__ __launch_bounds__(256) void cvt_kv(
    const float* __restrict__ lpart, __nv_bfloat16* __restrict__ lk3,
    __half* __restrict__ lvTh, float* __restrict__ ksum)
{
    __shared__ __half vh[64][65];
    __shared__ float ksm[64][5];
    const int t0 = blockIdx.x * 64;
    const int tid = threadIdx.x;
    for (int i = tid; i < 64 * 64; i += 256) {
        int r = i >> 6, l = i & 63;
        size_t idx = (size_t)(t0 + r) * 128 + l;
        float kv = 0.f, vv = 0.f;
#pragma unroll
        for (int s = 0; s < 8; s++) {
            kv += lpart[(size_t)s * T_SEQ * 128 + idx];
            vv += lpart[(size_t)s * T_SEQ * 128 + idx + 64];
        }
        vh[l][r] = __float2half(vv);
        __nv_bfloat16 kh = __float2bfloat16(kv);
        __nv_bfloat16 kl = __float2bfloat16(kv - __bfloat162float(kh));
        lk3[(size_t)(t0 + r) * 192 + l]       = kh;
        lk3[(size_t)(t0 + r) * 192 + 64 + l]  = kh;
        lk3[(size_t)(t0 + r) * 192 + 128 + l] = kl;
    }
    __syncthreads();
    {
        int r = tid >> 2, q = tid & 3;
        float s = 0.f;
        size_t idx = (size_t)(t0 + r) * 128;
        for (int l = q * 16; l < q * 16 + 16; l++) {
            float kv = 0.f;
#pragma unroll
            for (int sp = 0; sp < 8; sp++)
                kv += lpart[(size_t)sp * T_SEQ * 128 + idx + l];
            s += kv;
        }
        ksm[r][q] = s;
    }
    __syncthreads();
    for (int i = tid; i < 64 * 64; i += 256) {
        int l = i >> 6, r = i & 63;
        lvTh[(size_t)l * T_SEQ + t0 + r] = vh[l][r];
    }
    if (tid < 64)
        ksum[t0 + tid] = ksm[tid][0] + ksm[tid][1] + ksm[tid][2] + ksm[tid][3];
}

// ---------------- qsum from qlat3 (hi + lo) ----------------
__global__ void qsum_kernel(const __nv_bfloat16* __restrict__ qlat3, float* __restrict__ qsum)
{
    int i = blockIdx.x * blockDim.x + threadIdx.x;
    if (i >= T_SEQ * NH) return;
    float s = 0.f;
#pragma unroll 8
    for (int l = 0; l < LAT; l++)
        s += __bfloat162float(qlat3[(size_t)i * 192 + l]) +
             __bfloat162float(qlat3[(size_t)i * 192 + 64 + l]);
    qsum[i] = s;
}

// ========== FA2-style HMMA flash, paired q-tiles, 1-term fp16 PV ==========
#define FQS 200
#define FVS 136
#define FLASH_SMEM ((128 * FQS + 2 * 64 * FQS + 2 * 80 * FVS) * 2)

__global__ __launch_bounds__(256) void flash_hmma(
    const __nv_bfloat16* __restrict__ qlat3, const __nv_bfloat16* __restrict__ lk3,
    const __half* __restrict__ lvTh,
    const float* __restrict__ qsum, const float* __restrict__ ksum,
    __nv_bfloat16* __restrict__ lctx3)
{
    extern __shared__ __align__(16) __nv_bfloat16 smb[];
    __nv_bfloat16* Qs = smb;
    __nv_bfloat16* Ks = Qs + 128 * FQS;
    __half* VT = (__half*)(Ks + 2 * 64 * FQS);
    __shared__ float kss[64];

    const int h = blockIdx.y;
    const int tid = threadIdx.x;
    const int lane = tid & 31;
    const int wid = tid >> 5;
    const int rm = wid * 16;

    const int a_row = lane & 15, a_koff = (lane >> 4) * 8;
    const int b_row = (lane & 7) + ((lane >> 4) & 1) * 8;
    const int b_koff = ((lane >> 3) & 1) * 8;
    const int er = lane >> 2, ec = (lane & 3) * 2;
    const float L2E = 1.4426950408889634f;

    // VT const rows 64..79: ones at row 64 (cols<64) -> row-sum column
    for (int i = tid; i < 2 * 16 * FVS; i += 256) {
        int buf = i / (16 * FVS);
        int rr = (i / FVS) % 16;
        int c = i % FVS;
        __half v = __ushort_as_half((unsigned short)0);
        if (rr == 0 && c < 64) v = __float2half(1.0f);
        VT[buf * 80 * FVS + (64 + rr) * FVS + c] = v;
    }

    auto load_kv = [&](int buf, int s0) {
        __nv_bfloat16* ks = Ks + buf * 64 * FQS;
        __half* vt = VT + buf * 80 * FVS;
        for (int i = tid; i < 64 * 24; i += 256) {
            int r = i / 24, c = i % 24;
            CP_ASYNC16(smem_u32(ks + r * FQS + c * 8),
                       lk3 + (size_t)(s0 + r) * 192 + c * 8);
        }
        for (int i = tid; i < 64 * 8; i += 256) {
            int r = i >> 3, c = i & 7;
            CP_ASYNC16(smem_u32(vt + r * FVS + c * 8),
                       lvTh + (size_t)r * T_SEQ + s0 + c * 8);
        }
    };

#pragma unroll 1
    for (int pass = 0; pass < 2; pass++) {
        const int qt = pass == 0 ? (15 - blockIdx.x) : blockIdx.x;
        const int q0 = qt * 128;
        __syncthreads();

        for (int i = tid; i < 128 * 24; i += 256) {
            int r = i / 24, c = i % 24;
            CP_ASYNC16(smem_u32(Qs + r * FQS + c * 8),
                       qlat3 + ((size_t)(q0 + r) * NH + h) * 192 + c * 8);
        }
        load_kv(0, 0); CP_COMMIT();

        const float qss0 = qsum[(size_t)(q0 + rm + er) * NH + h] * 0.0625f;
        const float qss1 = qsum[(size_t)(q0 + rm + er + 8) * NH + h] * 0.0625f;
        const int gi0 = q0 + rm + er, gi1 = gi0 + 8;

        float Oa[9][4];
#pragma unroll
        for (int ni = 0; ni < 9; ni++)
#pragma unroll
            for (int r = 0; r < 4; r++) Oa[ni][r] = 0.f;
        float m0 = -1e30f, m1 = -1e30f;

        const int nkb = 2 * qt + 2;
        for (int kb = 0; kb < nkb; kb++) {
            const int buf = kb & 1;
            const int s0 = kb * 64;
            if (kb + 1 < nkb) { load_kv(buf ^ 1, (kb + 1) * 64); CP_COMMIT(); CP_WAIT1(); }
            else              { CP_WAIT0(); }
            if (tid < 64) kss[tid] = ksum[s0 + tid];
            __syncthreads();

            // ---- S = Q3 @ K3^T (3-term bf16, K'=192) ----
            float sacc[8][4];
#pragma unroll
            for (int ni = 0; ni < 8; ni++)
#pragma unroll
                for (int r = 0; r < 4; r++) sacc[ni][r] = 0.f;
            const uint32_t aQrow = smem_u32(Qs) + ((rm + a_row) * FQS + a_koff) * 2;
            const uint32_t sKb = smem_u32(Ks) + (uint32_t)(buf * 64 * FQS) * 2;
#pragma unroll
            for (int kk = 0; kk < 192; kk += 16) {
                uint32_t af[4];
                ldmx4(af[0], af[1], af[2], af[3], aQrow + kk * 2);
                uint32_t bfr[8][2];
#pragma unroll
                for (int n4 = 0; n4 < 4; n4++) {
                    uint32_t r0, r1, r2, r3;
                    ldmx4(r0, r1, r2, r3, sKb + ((n4 * 16 + b_row) * FQS + kk + b_koff) * 2);
                    bfr[n4 * 2 + 0][0] = r0; bfr[n4 * 2 + 0][1] = r1;
                    bfr[n4 * 2 + 1][0] = r2; bfr[n4 * 2 + 1][1] = r3;
                }
#pragma unroll
                for (int ni = 0; ni < 8; ni++) mma16816(sacc[ni], af, bfr[ni]);
            }

            // ---- scale + causal mask + reciprocal band ----
#pragma unroll
            for (int ni = 0; ni < 8; ni++) {
#pragma unroll
                for (int cc = 0; cc < 2; cc++) {
                    int gj = s0 + ni * 8 + ec + cc;
                    float ksv = kss[ni * 8 + ec + cc];
                    float v = sacc[ni][cc] * 0.125f;
                    if (gi0 - gj <= 64) v += qss0 * ksv;
                    sacc[ni][cc] = (gj <= gi0) ? v : -1e30f;
                    float w = sacc[ni][2 + cc] * 0.125f;
                    if (gi1 - gj <= 64) w += qss1 * ksv;
                    sacc[ni][2 + cc] = (gj <= gi1) ? w : -1e30f;
                }
            }

            // ---- online softmax on registers ----
            float mx0 = -1e30f, mx1 = -1e30f;
#pragma unroll
            for (int ni = 0; ni < 8; ni++) {
                mx0 = fmaxf(mx0, fmaxf(sacc[ni][0], sacc[ni][1]));
                mx1 = fmaxf(mx1, fmaxf(sacc[ni][2], sacc[ni][3]));
            }
            mx0 = fmaxf(mx0, __shfl_xor_sync(0xffffffffu, mx0, 1));
            mx0 = fmaxf(mx0, __shfl_xor_sync(0xffffffffu, mx0, 2));
            mx1 = fmaxf(mx1, __shfl_xor_sync(0xffffffffu, mx1, 1));
            mx1 = fmaxf(mx1, __shfl_xor_sync(0xffffffffu, mx1, 2));
            float mn0 = fmaxf(m0, mx0), mn1 = fmaxf(m1, mx1);
            float al0 = exp2f((m0 - mn0) * L2E);
            float al1 = exp2f((m1 - mn1) * L2E);
            m0 = mn0; m1 = mn1;
#pragma unroll
            for (int ni = 0; ni < 9; ni++) {
                Oa[ni][0] *= al0; Oa[ni][1] *= al0;
                Oa[ni][2] *= al1; Oa[ni][3] *= al1;
            }
            uint32_t p01[8], p23[8];
#pragma unroll
            for (int ni = 0; ni < 8; ni++) {
                float x0 = (sacc[ni][0] - mn0) * L2E;
                float x1 = (sacc[ni][1] - mn0) * L2E;
                float x2 = (sacc[ni][2] - mn1) * L2E;
                float x3 = (sacc[ni][3] - mn1) * L2E;
                uint32_t hx;
                asm("cvt.rn.f16x2.f32 %0, %1, %2;" : "=r"(hx) : "f"(x1), "f"(x0));
                asm("ex2.approx.f16x2 %0, %1;" : "=r"(p01[ni]) : "r"(hx));
                asm("cvt.rn.f16x2.f32 %0, %1, %2;" : "=r"(hx) : "f"(x3), "f"(x2));
                asm("ex2.approx.f16x2 %0, %1;" : "=r"(p23[ni]) : "r"(hx));
            }

            // ---- O += P @ V^T (fp16 single term; col 64 = ones -> row sum) ----
            const uint32_t sVb = smem_u32(VT) + (uint32_t)(buf * 80 * FVS) * 2;
#pragma unroll
            for (int kk = 0; kk < 64; kk += 16) {
                int f = kk >> 3;
                uint32_t af[4] = { p01[f], p23[f], p01[f + 1], p23[f + 1] };
                uint32_t bfr[10][2];
#pragma unroll
                for (int n4 = 0; n4 < 5; n4++) {
                    uint32_t r0, r1, r2, r3;
                    ldmx4(r0, r1, r2, r3,
                          sVb + ((n4 * 16 + b_row) * FVS + kk + b_koff) * 2);
                    bfr[n4 * 2 + 0][0] = r0; bfr[n4 * 2 + 0][1] = r1;
                    bfr[n4 * 2 + 1][0] = r2; bfr[n4 * 2 + 1][1] = r3;
                }
#pragma unroll
                for (int ni = 0; ni < 9; ni++) mma16816h(Oa[ni], af, bfr[ni]);
            }
            __syncthreads();
        }

        // ---- epilogue ----
        float ls0 = __shfl_sync(0xffffffffu, Oa[8][0], lane & ~3);
        float ls1 = __shfl_sync(0xffffffffu, Oa[8][2], lane & ~3);
        float li0 = 1.f / ls0, li1 = 1.f / ls1;
        const int t0 = q0 + rm + er, t1 = t0 + 8;
#pragma unroll
        for (int ni = 0; ni < 8; ni++) {
            int c0 = ni * 8 + ec;
            float v0 = Oa[ni][0] * li0, v1 = Oa[ni][1] * li0;
            float v2 = Oa[ni][2] * li1, v3 = Oa[ni][3] * li1;
            __nv_bfloat16 h0 = __float2bfloat16(v0), h1 = __float2bfloat16(v1);
            __nv_bfloat162 hp0; hp0.x = h0; hp0.y = h1;
            __nv_bfloat162 lp0;
            lp0.x = __float2bfloat16(v0 - __bfloat162float(h0));
            lp0.y = __float2bfloat16(v1 - __bfloat162float(h1));
            size_t b0 = (size_t)t0 * 3072 + h * 64 + c0;
            *(__nv_bfloat162*)(lctx3 + b0)        = hp0;
            *(__nv_bfloat162*)(lctx3 + b0 + 1024) = lp0;
            *(__nv_bfloat162*)(lctx3 + b0 + 2048) = hp0;
            __nv_bfloat16 h2 = __float2bfloat16(v2), h3 = __float2bfloat16(v3);
            __nv_bfloat162 hp1; hp1.x = h2; hp1.y = h3;
            __nv_bfloat162 lp1;
            lp1.x = __float2bfloat16(v2 - __bfloat162float(h2));
            lp1.y = __float2bfloat16(v3 - __bfloat162float(h3));
            size_t b1 = (size_t)t1 * 3072 + h * 64 + c0;
            *(__nv_bfloat162*)(lctx3 + b1)        = hp1;
            *(__nv_bfloat162*)(lctx3 + b1 + 1024) = lp1;
            *(__nv_bfloat162*)(lctx3 + b1 + 2048) = hp1;
        }
    }
}

// ---------------- host launcher ----------------
extern "C" void kernel_launch(void* const* d_in, const int* in_sizes, int n_in,
                              void* d_out, int out_size)
{
    const float* hidden = (const float*)d_in[0];
    const float* Wq  = (const float*)d_in[1];
    const float* Wk  = (const float*)d_in[2];
    const float* Wv  = (const float*)d_in[3];
    const float* q2l = (const float*)d_in[4];
    const float* vup = (const float*)d_in[5];
    const float* Wo  = (const float*)d_in[6];
    float* out = (float*)d_out;

    float *q2lT, *lpart, *qs, *ks;
    __nv_bfloat16 *hid3, *WqT3, *Wo3, *q2l3p, *vup3p, *Wf13, *Wf23, *Wkv3, *qlat3, *lk3, *lctx3;
    __half *lvTh;
    cudaGetSymbolAddress((void**)&q2lT,  g_q2lT);
    cudaGetSymbolAddress((void**)&lpart, g_lpart);
    cudaGetSymbolAddress((void**)&qs,    g_qsum);
    cudaGetSymbolAddress((void**)&ks,    g_ksum);
    cudaGetSymbolAddress((void**)&hid3,  g_hid3);
    cudaGetSymbolAddress((void**)&WqT3,  g_WqT3);
    cudaGetSymbolAddress((void**)&Wo3,   g_Wo3);
    cudaGetSymbolAddress((void**)&q2l3p, g_q2l3p);
    cudaGetSymbolAddress((void**)&vup3p, g_vup3p);
    cudaGetSymbolAddress((void**)&Wf13,  g_Wf13);
    cudaGetSymbolAddress((void**)&Wf23,  g_Wf23);
    cudaGetSymbolAddress((void**)&Wkv3,  g_Wkv3);
    cudaGetSymbolAddress((void**)&qlat3, g_qlat3);
    cudaGetSymbolAddress((void**)&lk3,   g_lk3);
    cudaGetSymbolAddress((void**)&lvTh,  g_lvTh);
    cudaGetSymbolAddress((void**)&lctx3, g_lctx3);

    cudaFuncSetAttribute(hmma_gemm,
                         cudaFuncAttributeMaxDynamicSharedMemorySize, HMMA_SMEM);
    cudaFuncSetAttribute(hmma_qlat,
                         cudaFuncAttributeMaxDynamicSharedMemorySize, HMMA_SMEM);
    cudaFuncSetAttribute(hmma_fold,
                         cudaFuncAttributeMaxDynamicSharedMemorySize, HMMA_SMEM);
    cudaFuncSetAttribute(flash_hmma,
                         cudaFuncAttributeMaxDynamicSharedMemorySize, FLASH_SMEM);

    // --- weight preprocessing ---
    transpose_k<<<dim3(2, 4, NH), dim3(32, 8)>>>(q2l, q2lT, HD, LAT,
                                                 (long)HD * LAT, (long)LAT * HD);
    transpose_split3<<<dim3(64, 64), dim3(32, 8)>>>(Wq, WqT3);
    cvt_split3<<<(EMB * EMB / 4 + 255) / 256, 256>>>(
        Wo, Wo3, EMB * EMB, HD, 2 * HD, HD);
    cvt_split3_pad<<<(NH * HD * HD / 4 + 255) / 256, 256>>>(
        q2lT, q2l3p, NH, LAT, HD, HD, 2 * HD, HD);
    cvt_split3_pad<<<(NH * HD * HD / 4 + 255) / 256, 256>>>(
        vup, vup3p, NH, LAT, HD, HD, HD, 2 * HD);

    // --- folds on tensor cores ---
    hmma_fold<<<dim3(16, 1, NH), 256, HMMA_SMEM>>>(
        q2l3p, WqT3, Wf13, 3 * HD, 3 * HD, NH * 3 * HD,
        (long)HD * 3 * HD, (long)3 * HD, (long)LAT * 3 * EMB,
        3 * EMB, EMB, 2 * EMB, LAT, EMB);
    hmma_fold<<<dim3(1, 16, NH), 256, HMMA_SMEM>>>(
        Wo3, vup3p, Wf23, 3 * HD, NH * 3 * HD, 3 * HD,
        (long)3 * HD, (long)HD * 3 * HD, (long)LAT,
        3 * NH * LAT, NH * LAT, 2 * NH * LAT, EMB, LAT);

    // --- input splits ---
    cvt_split3<<<(T_SEQ * EMB / 4 + 255) / 256, 256>>>(
        hidden, hid3, T_SEQ * EMB, EMB, 2 * EMB, EMB);
    cvt_split3<<<(LAT * EMB / 4 + 255) / 256, 256>>>(
        Wk, Wkv3, LAT * EMB, EMB, EMB, 2 * EMB);
    cvt_split3<<<(LAT * EMB / 4 + 255) / 256, 256>>>(
        Wv, Wkv3 + (size_t)LAT * 3 * EMB, LAT * EMB, EMB, EMB, 2 * EMB);

    // --- lkv split-K x8; reduce+convert fused in cvt_kv ---
    hmma_gemm<<<dim3(1, 16, 8), 256, HMMA_SMEM>>>(hid3, Wkv3, lpart,
                                                  T_SEQ, 2 * LAT, 3 * EMB, 8);
    cvt_kv<<<32, 256>>>(lpart, lk3, lvTh, ks);

    // --- q_latent -> qlat3 split directly (HMMA) ---
    hmma_qlat<<<dim3(8, 16), 256, HMMA_SMEM>>>(hid3, Wf13, qlat3, 3 * EMB);
    qsum_kernel<<<(T_SEQ * NH + 255) / 256, 256>>>(qlat3, qs);

    // --- flash attention ---
    flash_hmma<<<dim3(8, NH), 256, FLASH_SMEM>>>(qlat3, lk3, lvTh, qs, ks, lctx3);

    // --- out = lctx @ Wf2T^T (HMMA) ---
    hmma_gemm<<<dim3(16, 16, 1), 256, HMMA_SMEM>>>(lctx3, Wf23, out,
                                                   T_SEQ, EMB, 3 * NH * LAT, 1);
}

// round 12
// speedup vs baseline: 5.4712x; 1.0505x over previous
#include <cuda_runtime.h>
#include <cuda_bf16.h>
#include <cuda_fp16.h>
#include <cstdint>

#define T_SEQ 2048
#define EMB   2048
#define NH    16
#define HD    128
#define LAT   64

// ---------------- scratch (static device globals; no allocation) ----------------
__device__ float g_q2lT[NH * LAT * HD];
__device__ float g_lpart[8 * T_SEQ * 2 * LAT];
__device__ float g_qsum[T_SEQ * NH];
__device__ float g_ksum[T_SEQ];
// bf16 [hi|lo] split buffers (phase-mapped at load time)
__device__ __align__(16) __nv_bfloat16 g_hid2 [T_SEQ * 2 * EMB];        // A-type
__device__ __align__(16) __nv_bfloat16 g_WqT2 [EMB * NH * 2 * HD];      // B-type per (e,h)
__device__ __align__(16) __nv_bfloat16 g_Wo2  [EMB * NH * 2 * HD];      // A-type per (e,h)
__device__ __align__(16) __nv_bfloat16 g_q2l2p[NH * HD * 2 * HD];       // A-type, padded rows
__device__ __align__(16) __nv_bfloat16 g_vup2p[NH * HD * 2 * HD];       // B-type, padded rows
__device__ __align__(16) __nv_bfloat16 g_Wf12 [NH * LAT * 2 * EMB];     // B-type
__device__ __align__(16) __nv_bfloat16 g_Wf22 [EMB * 2 * NH * LAT];     // B-type
__device__ __align__(16) __nv_bfloat16 g_Wkv2 [2 * LAT * 2 * EMB];      // B-type
__device__ __align__(16) __nv_bfloat16 g_qlat2[T_SEQ * NH * 2 * LAT];   // A-type
__device__ __align__(16) __nv_bfloat16 g_lk2  [T_SEQ * 2 * LAT];        // B-type
__device__ __align__(16) __half        g_lvTh [LAT * T_SEQ];            // V^T (fp16)
__device__ __align__(16) __nv_bfloat16 g_lctx2[T_SEQ * 2 * NH * LAT];   // A-type

// ================= PTX helpers =================
__device__ __forceinline__ uint32_t smem_u32(const void* p) {
    uint32_t a;
    asm("{ .reg .u64 t; cvta.to.shared.u64 t, %1; cvt.u32.u64 %0, t; }" : "=r"(a) : "l"(p));
    return a;
}
#define CP_ASYNC16(dst, src) \
    asm volatile("cp.async.cg.shared.global [%0], [%1], 16;" :: "r"(dst), "l"(src))
#define CP_COMMIT() asm volatile("cp.async.commit_group;")
#define CP_WAIT1()  asm volatile("cp.async.wait_group 1;")
#define CP_WAIT0()  asm volatile("cp.async.wait_group 0;")

__device__ __forceinline__ void ldmx4(uint32_t& r0, uint32_t& r1, uint32_t& r2, uint32_t& r3,
                                      uint32_t addr) {
    asm volatile("ldmatrix.sync.aligned.m8n8.x4.shared.b16 {%0,%1,%2,%3}, [%4];"
                 : "=r"(r0), "=r"(r1), "=r"(r2), "=r"(r3) : "r"(addr));
}
__device__ __forceinline__ void mma16816(float* d, const uint32_t* a, const uint32_t* b) {
    asm volatile("mma.sync.aligned.m16n8k16.row.col.f32.bf16.bf16.f32 "
                 "{%0,%1,%2,%3}, {%4,%5,%6,%7}, {%8,%9}, {%0,%1,%2,%3};"
                 : "+f"(d[0]), "+f"(d[1]), "+f"(d[2]), "+f"(d[3])
                 : "r"(a[0]), "r"(a[1]), "r"(a[2]), "r"(a[3]), "r"(b[0]), "r"(b[1]));
}
__device__ __forceinline__ void mma16816h(float* d, const uint32_t* a, const uint32_t* b) {
    asm volatile("mma.sync.aligned.m16n8k16.row.col.f32.f16.f16.f32 "
                 "{%0,%1,%2,%3}, {%4,%5,%6,%7}, {%8,%9}, {%0,%1,%2,%3};"
                 : "+f"(d[0]), "+f"(d[1]), "+f"(d[2]), "+f"(d[3])
                 : "r"(a[0]), "r"(a[1]), "r"(a[2]), "r"(a[3]), "r"(b[0]), "r"(b[1]));
}

// ---------------- fp32 -> [hi|lo] bf16 split (row stride 2K) ----------------
__global__ void cvt_split2(const float* __restrict__ x, __nv_bfloat16* __restrict__ out,
                           int total, int K, int offL)
{
    int i = (blockIdx.x * blockDim.x + threadIdx.x) * 4;
    if (i >= total) return;
    float4 v = *(const float4*)(x + i);
    float vv[4] = {v.x, v.y, v.z, v.w};
    __nv_bfloat16 hb[4], lb[4];
#pragma unroll
    for (int k = 0; k < 4; k++) {
        hb[k] = __float2bfloat16(vv[k]);
        lb[k] = __float2bfloat16(vv[k] - __bfloat162float(hb[k]));
    }
    int r = i / K, c = i - r * K;
    size_t base = (size_t)r * 2 * K + c;
    *(uint2*)(out + base)        = *(uint2*)hb;
    *(uint2*)(out + base + offL) = *(uint2*)lb;
}

// ---- padded batched variant ----
__global__ void cvt_split2_pad(const float* __restrict__ x, __nv_bfloat16* __restrict__ out,
                               int nb, int rows, int K, int padRows, int offL)
{
    int i = (blockIdx.x * blockDim.x + threadIdx.x) * 4;
    int total = nb * padRows * K;
    if (i >= total) return;
    int b = i / (padRows * K);
    int rem = i - b * (padRows * K);
    int r = rem / K, c = rem - r * K;
    float vv[4] = {0.f, 0.f, 0.f, 0.f};
    if (r < rows) {
        float4 v = *(const float4*)(x + (size_t)b * rows * K + (size_t)r * K + c);
        vv[0] = v.x; vv[1] = v.y; vv[2] = v.z; vv[3] = v.w;
    }
    __nv_bfloat16 hb[4], lb[4];
#pragma unroll
    for (int k = 0; k < 4; k++) {
        hb[k] = __float2bfloat16(vv[k]);
        lb[k] = __float2bfloat16(vv[k] - __bfloat162float(hb[k]));
    }
    size_t base = (size_t)b * padRows * 2 * K + (size_t)r * 2 * K + c;
    *(uint2*)(out + base)        = *(uint2*)hb;
    *(uint2*)(out + base + offL) = *(uint2*)lb;
}

// ---- fused transpose + split: Wq [hd][e] -> WqT2 [e][h][256] (hi at d, lo at 128+d)
__global__ void transpose_split2(const float* __restrict__ in, __nv_bfloat16* __restrict__ out)
{
    __shared__ float t[32][33];
    int x = blockIdx.x * 32 + threadIdx.x;
    for (int i = threadIdx.y; i < 32; i += 8) {
        int y = blockIdx.y * 32 + i;
        t[i][threadIdx.x] = in[(size_t)y * EMB + x];
    }
    __syncthreads();
    for (int i = threadIdx.y; i < 32; i += 8) {
        int eo = blockIdx.x * 32 + i;
        int hd = blockIdx.y * 32 + threadIdx.x;
        float v = t[threadIdx.x][i];
        __nv_bfloat16 h = __float2bfloat16(v);
        __nv_bfloat16 l = __float2bfloat16(v - __bfloat162float(h));
        int hh = hd >> 7, d = hd & 127;
        size_t base = (size_t)eo * (NH * 2 * HD) + hh * 256 + d;
        out[base]       = h;
        out[base + 128] = l;
    }
}

// ============== HMMA bf16x3 GEMM (phase-mapped [hi|lo] operands) ==============
// logical K' = 3*Ka; chunk phase p: A seg = (p==1)?lo:hi, B seg = (p==2)?lo:hi.
#define GS 72
#define STAGE_ELTS (128 * GS)
#define HMMA_SMEM (3 * 2 * STAGE_ELTS * 2)

__global__ __launch_bounds__(256) void hmma_gemm(
    const __nv_bfloat16* __restrict__ A, const __nv_bfloat16* __restrict__ B,
    float* __restrict__ C, int M, int N, int Ka, int nsplit)
{
    extern __shared__ __align__(16) __nv_bfloat16 sm[];
    const int tid = threadIdx.x;
    const int wid = tid >> 5;
    const int lane = tid & 31;
    const int warp_m = wid >> 2;
    const int warp_n = wid & 3;
    const int bm = blockIdx.y * 128;
    const int bn = blockIdx.x * 128;
    const uint32_t sbase = smem_u32(sm);
    const int lda = 2 * Ka, ldb = 2 * Ka;

    const int Ktot = 3 * Ka;
    const int Kc = Ktot / nsplit;
    const int kbeg = blockIdx.z * Kc;
    C += (size_t)blockIdx.z * M * N;
    const int nk = Kc >> 6;

    auto load_stage = [&](int stage, int k0) {
        __nv_bfloat16* As = sm + stage * 2 * STAGE_ELTS;
        __nv_bfloat16* Bs = As + STAGE_ELTS;
        int kg = kbeg + k0;
        int p = (kg >= 2 * Ka) ? 2 : (kg >= Ka ? 1 : 0);
        int kloc = kg - p * Ka;
        const __nv_bfloat16* Ap = A + ((p == 1) ? Ka : 0) + kloc;
        const __nv_bfloat16* Bp = B + ((p == 2) ? Ka : 0) + kloc;
#pragma unroll
        for (int i = 0; i < 4; i++) {
            int c = tid + i * 256;
            int row = c >> 3;
            int col8 = (c & 7) * 8;
            CP_ASYNC16(smem_u32(As + row * GS + col8), Ap + (size_t)(bm + row) * lda + col8);
            CP_ASYNC16(smem_u32(Bs + row * GS + col8), Bp + (size_t)(bn + row) * ldb + col8);
        }
    };

    float acc[4][4][4];
#pragma unroll
    for (int mi = 0; mi < 4; mi++)
#pragma unroll
        for (int ni = 0; ni < 4; ni++)
#pragma unroll
            for (int r = 0; r < 4; r++) acc[mi][ni][r] = 0.f;

    load_stage(0, 0); CP_COMMIT();
    if (nk > 1) { load_stage(1, 64); CP_COMMIT(); }

    const int a_row = (lane & 15);
    const int a_koff = (lane >> 4) * 8;
    const int b_row = (lane & 7) + ((lane >> 4) & 1) * 8;
    const int b_koff = ((lane >> 3) & 1) * 8;

    for (int it = 0; it < nk; it++) {
        CP_WAIT1();
        __syncthreads();
        if (it + 2 < nk) { load_stage((it + 2) % 3, (it + 2) * 64); CP_COMMIT(); }

        const int stage = it % 3;
        const uint32_t sA = sbase + (uint32_t)(stage * 2 * STAGE_ELTS) * 2;
        const uint32_t sB = sA + STAGE_ELTS * 2;

#pragma unroll
        for (int kk = 0; kk < 64; kk += 16) {
            uint32_t af[4][4];
#pragma unroll
            for (int mi = 0; mi < 4; mi++) {
                uint32_t addr = sA + ((warp_m * 64 + mi * 16 + a_row) * GS + kk + a_koff) * 2;
                ldmx4(af[mi][0], af[mi][1], af[mi][2], af[mi][3], addr);
            }
            uint32_t bf[4][2];
#pragma unroll
            for (int ni2 = 0; ni2 < 2; ni2++) {
                uint32_t addr = sB + ((warp_n * 32 + ni2 * 16 + b_row) * GS + kk + b_koff) * 2;
                uint32_t r0, r1, r2, r3;
                ldmx4(r0, r1, r2, r3, addr);
                bf[ni2 * 2 + 0][0] = r0; bf[ni2 * 2 + 0][1] = r1;
                bf[ni2 * 2 + 1][0] = r2; bf[ni2 * 2 + 1][1] = r3;
            }
#pragma unroll
            for (int mi = 0; mi < 4; mi++)
#pragma unroll
                for (int ni = 0; ni < 4; ni++)
                    mma16816(acc[mi][ni], af[mi], bf[ni]);
        }
        __syncthreads();
    }

    const int er = lane >> 2;
    const int ec = (lane & 3) * 2;
#pragma unroll
    for (int mi = 0; mi < 4; mi++) {
#pragma unroll
        for (int ni = 0; ni < 4; ni++) {
            int m0 = bm + warp_m * 64 + mi * 16 + er;
            int n0 = bn + warp_n * 32 + ni * 8 + ec;
            *(float2*)(C + (size_t)m0 * N + n0) = make_float2(acc[mi][ni][0], acc[mi][ni][1]);
            *(float2*)(C + (size_t)(m0 + 8) * N + n0) = make_float2(acc[mi][ni][2], acc[mi][ni][3]);
        }
    }
}

// ==== hmma_qlat: GEMM1 writing qlat2 A-type [hi|lo] directly ====
__global__ __launch_bounds__(256) void hmma_qlat(
    const __nv_bfloat16* __restrict__ A, const __nv_bfloat16* __restrict__ B,
    __nv_bfloat16* __restrict__ Q2, int Ka)
{
    extern __shared__ __align__(16) __nv_bfloat16 sm[];
    const int tid = threadIdx.x;
    const int wid = tid >> 5;
    const int lane = tid & 31;
    const int warp_m = wid >> 2;
    const int warp_n = wid & 3;
    const int bm = blockIdx.y * 128;
    const int bn = blockIdx.x * 128;
    const uint32_t sbase = smem_u32(sm);
    const int lda = 2 * Ka;
    const int nk = (3 * Ka) >> 6;

    auto load_stage = [&](int stage, int k0) {
        __nv_bfloat16* As = sm + stage * 2 * STAGE_ELTS;
        __nv_bfloat16* Bs = As + STAGE_ELTS;
        int p = (k0 >= 2 * Ka) ? 2 : (k0 >= Ka ? 1 : 0);
        int kloc = k0 - p * Ka;
        const __nv_bfloat16* Ap = A + ((p == 1) ? Ka : 0) + kloc;
        const __nv_bfloat16* Bp = B + ((p == 2) ? Ka : 0) + kloc;
#pragma unroll
        for (int i = 0; i < 4; i++) {
            int c = tid + i * 256;
            int row = c >> 3;
            int col8 = (c & 7) * 8;
            CP_ASYNC16(smem_u32(As + row * GS + col8), Ap + (size_t)(bm + row) * lda + col8);
            CP_ASYNC16(smem_u32(Bs + row * GS + col8), Bp + (size_t)(bn + row) * lda + col8);
        }
    };

    float acc[4][4][4];
#pragma unroll
    for (int mi = 0; mi < 4; mi++)
#pragma unroll
        for (int ni = 0; ni < 4; ni++)
#pragma unroll
            for (int r = 0; r < 4; r++) acc[mi][ni][r] = 0.f;

    load_stage(0, 0); CP_COMMIT();
    if (nk > 1) { load_stage(1, 64); CP_COMMIT(); }

    const int a_row = (lane & 15);
    const int a_koff = (lane >> 4) * 8;
    const int b_row = (lane & 7) + ((lane >> 4) & 1) * 8;
    const int b_koff = ((lane >> 3) & 1) * 8;

    for (int it = 0; it < nk; it++) {
        CP_WAIT1();
        __syncthreads();
        if (it + 2 < nk) { load_stage((it + 2) % 3, (it + 2) * 64); CP_COMMIT(); }

        const int stage = it % 3;
        const uint32_t sA = sbase + (uint32_t)(stage * 2 * STAGE_ELTS) * 2;
        const uint32_t sB = sA + STAGE_ELTS * 2;

#pragma unroll
        for (int kk = 0; kk < 64; kk += 16) {
            uint32_t af[4][4];
#pragma unroll
            for (int mi = 0; mi < 4; mi++) {
                uint32_t addr = sA + ((warp_m * 64 + mi * 16 + a_row) * GS + kk + a_koff) * 2;
                ldmx4(af[mi][0], af[mi][1], af[mi][2], af[mi][3], addr);
            }
            uint32_t bf[4][2];
#pragma unroll
            for (int ni2 = 0; ni2 < 2; ni2++) {
                uint32_t addr = sB + ((warp_n * 32 + ni2 * 16 + b_row) * GS + kk + b_koff) * 2;
                uint32_t r0, r1, r2, r3;
                ldmx4(r0, r1, r2, r3, addr);
                bf[ni2 * 2 + 0][0] = r0; bf[ni2 * 2 + 0][1] = r1;
                bf[ni2 * 2 + 1][0] = r2; bf[ni2 * 2 + 1][1] = r3;
            }
#pragma unroll
            for (int mi = 0; mi < 4; mi++)
#pragma unroll
                for (int ni = 0; ni < 4; ni++)
                    mma16816(acc[mi][ni], af[mi], bf[ni]);
        }
        __syncthreads();
    }

    const int er = lane >> 2;
    const int ec = (lane & 3) * 2;
#pragma unroll
    for (int mi = 0; mi < 4; mi++) {
#pragma unroll
        for (int ni = 0; ni < 4; ni++) {
            int n0 = bn + warp_n * 32 + ni * 8 + ec;
            int h = n0 >> 6, l = n0 & 63;
#pragma unroll
            for (int rr = 0; rr < 2; rr++) {
                int m0 = bm + warp_m * 64 + mi * 16 + er + rr * 8;
                float v0 = acc[mi][ni][rr * 2 + 0];
                float v1 = acc[mi][ni][rr * 2 + 1];
                __nv_bfloat16 h0 = __float2bfloat16(v0), h1 = __float2bfloat16(v1);
                __nv_bfloat162 hp; hp.x = h0; hp.y = h1;
                __nv_bfloat162 lp;
                lp.x = __float2bfloat16(v0 - __bfloat162float(h0));
                lp.y = __float2bfloat16(v1 - __bfloat162float(h1));
                size_t base = ((size_t)m0 * NH + h) * 128 + l;
                *(__nv_bfloat162*)(Q2 + base)      = hp;
                *(__nv_bfloat162*)(Q2 + base + 64) = lp;
            }
        }
    }
}

// ==== HMMA fold GEMM: batched, phase-mapped, [hi|lo] split epilogue ====
__global__ __launch_bounds__(256) void hmma_fold(
    const __nv_bfloat16* __restrict__ A, const __nv_bfloat16* __restrict__ B,
    __nv_bfloat16* __restrict__ C2, int Ka, int lda, int ldb,
    long batchA, long batchB, long batchC,
    int ldc2, int offLc, int validM, int validN)
{
    extern __shared__ __align__(16) __nv_bfloat16 sm[];
    const int tid = threadIdx.x;
    const int wid = tid >> 5;
    const int lane = tid & 31;
    const int warp_m = wid >> 2;
    const int warp_n = wid & 3;
    const int bm = blockIdx.y * 128;
    const int bn = blockIdx.x * 128;
    const uint32_t sbase = smem_u32(sm);

    A  += (size_t)blockIdx.z * batchA;
    B  += (size_t)blockIdx.z * batchB;
    C2 += (size_t)blockIdx.z * batchC;
    const int nk = (3 * Ka) >> 6;

    auto load_stage = [&](int stage, int k0) {
        __nv_bfloat16* As = sm + stage * 2 * STAGE_ELTS;
        __nv_bfloat16* Bs = As + STAGE_ELTS;
        int p = (k0 >= 2 * Ka) ? 2 : (k0 >= Ka ? 1 : 0);
        int kloc = k0 - p * Ka;
        const __nv_bfloat16* Ap = A + ((p == 1) ? Ka : 0) + kloc;
        const __nv_bfloat16* Bp = B + ((p == 2) ? Ka : 0) + kloc;
#pragma unroll
        for (int i = 0; i < 4; i++) {
            int c = tid + i * 256;
            int row = c >> 3;
            int col8 = (c & 7) * 8;
            CP_ASYNC16(smem_u32(As + row * GS + col8), Ap + (size_t)(bm + row) * lda + col8);
            CP_ASYNC16(smem_u32(Bs + row * GS + col8), Bp + (size_t)(bn + row) * ldb + col8);
        }
    };

    float acc[4][4][4];
#pragma unroll
    for (int mi = 0; mi < 4; mi++)
#pragma unroll
        for (int ni = 0; ni < 4; ni++)
#pragma unroll
            for (int r = 0; r < 4; r++) acc[mi][ni][r] = 0.f;

    load_stage(0, 0); CP_COMMIT();
    if (nk > 1) { load_stage(1, 64); CP_COMMIT(); }

    const int a_row = (lane & 15);
    const int a_koff = (lane >> 4) * 8;
    const int b_row = (lane & 7) + ((lane >> 4) & 1) * 8;
    const int b_koff = ((lane >> 3) & 1) * 8;

    for (int it = 0; it < nk; it++) {
        CP_WAIT1();
        __syncthreads();
        if (it + 2 < nk) { load_stage((it + 2) % 3, (it + 2) * 64); CP_COMMIT(); }

        const int stage = it % 3;
        const uint32_t sA = sbase + (uint32_t)(stage * 2 * STAGE_ELTS) * 2;
        const uint32_t sB = sA + STAGE_ELTS * 2;

#pragma unroll
        for (int kk = 0; kk < 64; kk += 16) {
            uint32_t af[4][4];
#pragma unroll
            for (int mi = 0; mi < 4; mi++) {
                uint32_t addr = sA + ((warp_m * 64 + mi * 16 + a_row) * GS + kk + a_koff) * 2;
                ldmx4(af[mi][0], af[mi][1], af[mi][2], af[mi][3], addr);
            }
            uint32_t bf[4][2];
#pragma unroll
            for (int ni2 = 0; ni2 < 2; ni2++) {
                uint32_t addr = sB + ((warp_n * 32 + ni2 * 16 + b_row) * GS + kk + b_koff) * 2;
                uint32_t r0, r1, r2, r3;
                ldmx4(r0, r1, r2, r3, addr);
                bf[ni2 * 2 + 0][0] = r0; bf[ni2 * 2 + 0][1] = r1;
                bf[ni2 * 2 + 1][0] = r2; bf[ni2 * 2 + 1][1] = r3;
            }
#pragma unroll
            for (int mi = 0; mi < 4; mi++)
#pragma unroll
                for (int ni = 0; ni < 4; ni++)
                    mma16816(acc[mi][ni], af[mi], bf[ni]);
        }
        __syncthreads();
    }

    const int er = lane >> 2;
    const int ec = (lane & 3) * 2;
#pragma unroll
    for (int mi = 0; mi < 4; mi++) {
#pragma unroll
        for (int ni = 0; ni < 4; ni++) {
            int n0 = bn + warp_n * 32 + ni * 8 + ec;
            if (n0 >= validN) continue;
#pragma unroll
            for (int rr = 0; rr < 2; rr++) {
                int m0 = bm + warp_m * 64 + mi * 16 + er + rr * 8;
                if (m0 >= validM) continue;
                float v0 = acc[mi][ni][rr * 2 + 0];
                float v1 = acc[mi][ni][rr * 2 + 1];
                __nv_bfloat16 h0 = __float2bfloat16(v0), h1 = __float2bfloat16(v1);
                __nv_bfloat162 hp; hp.x = h0; hp.y = h1;
                __nv_bfloat162 lp;
                lp.x = __float2bfloat16(v0 - __bfloat162float(h0));
                lp.y = __float2bfloat16(v1 - __bfloat162float(h1));
                size_t base = (size_t)m0 * ldc2 + n0;
                *(__nv_bfloat162*)(C2 + base)         = hp;
                *(__nv_bfloat162*)(C2 + base + offLc) = lp;
            }
        }
    }
}

// ---------------- batched tiled transpose (fp32) ----------------
__global__ void transpose_k(const float* __restrict__ in, float* __restrict__ out,
                            int R, int C, long bIn, long bOut)
{
    __shared__ float t[32][33];
    in  += (long)blockIdx.z * bIn;
    out += (long)blockIdx.z * bOut;
    int x = blockIdx.x * 32 + threadIdx.x;
    for (int i = threadIdx.y; i < 32; i += 8) {
        int y = blockIdx.y * 32 + i;
        if (y < R && x < C) t[i][threadIdx.x] = in[(size_t)y * C + x];
    }
    __syncthreads();
    int x2 = blockIdx.y * 32 + threadIdx.x;
    for (int i = threadIdx.y; i < 32; i += 8) {
        int y2 = blockIdx.x * 32 + i;
        if (y2 < C && x2 < R) out[(size_t)y2 * R + x2] = t[threadIdx.x][i];
    }
}

// ---- cvt_kv: lpart[8][T][128] -> lk2 [T][128], lvTh [64][T], ksum (no re-read) ----
__global__ __launch_bounds__(256) void cvt_kv(
    const float* __restrict__ lpart, __nv_bfloat16* __restrict__ lk2,
    __half* __restrict__ lvTh, float* __restrict__ ksum)
{
    __shared__ __half vh[64][65];
    __shared__ float kvs[64][65];
    const int t0 = blockIdx.x * 64;
    const int tid = threadIdx.x;
    for (int i = tid; i < 64 * 64; i += 256) {
        int r = i >> 6, l = i & 63;
        size_t idx = (size_t)(t0 + r) * 128 + l;
        float kv = 0.f, vv = 0.f;
#pragma unroll
        for (int s = 0; s < 8; s++) {
            kv += lpart[(size_t)s * T_SEQ * 128 + idx];
            vv += lpart[(size_t)s * T_SEQ * 128 + idx + 64];
        }
        vh[l][r] = __float2half(vv);
        kvs[r][l] = kv;
        __nv_bfloat16 kh = __float2bfloat16(kv);
        __nv_bfloat16 kl = __float2bfloat16(kv - __bfloat162float(kh));
        lk2[(size_t)(t0 + r) * 128 + l]      = kh;
        lk2[(size_t)(t0 + r) * 128 + 64 + l] = kl;
    }
    __syncthreads();
    for (int i = tid; i < 64 * 64; i += 256) {
        int l = i >> 6, r = i & 63;
        lvTh[(size_t)l * T_SEQ + t0 + r] = vh[l][r];
    }
    if (tid < 64) {
        float s = 0.f;
#pragma unroll 8
        for (int l = 0; l < 64; l++) s += kvs[tid][l];
        ksum[t0 + tid] = s;
    }
}

// ---------------- qsum from qlat2 (hi + lo) ----------------
__global__ void qsum_kernel(const __nv_bfloat16* __restrict__ qlat2, float* __restrict__ qsum)
{
    int i = blockIdx.x * blockDim.x + threadIdx.x;
    if (i >= T_SEQ * NH) return;
    float s = 0.f;
#pragma unroll 8
    for (int l = 0; l < LAT; l++)
        s += __bfloat162float(qlat2[(size_t)i * 128 + l]) +
             __bfloat162float(qlat2[(size_t)i * 128 + 64 + l]);
    qsum[i] = s;
}

// ========== FA2-style HMMA flash, paired q-tiles, phase-mapped loads ==========
#define FQS 200
#define FVS 136
#define FLASH_SMEM ((128 * FQS + 2 * 64 * FQS + 2 * 80 * FVS) * 2)

__global__ __launch_bounds__(256) void flash_hmma(
    const __nv_bfloat16* __restrict__ qlat2, const __nv_bfloat16* __restrict__ lk2,
    const __half* __restrict__ lvTh,
    const float* __restrict__ qsum, const float* __restrict__ ksum,
    __nv_bfloat16* __restrict__ lctx2)
{
    extern __shared__ __align__(16) __nv_bfloat16 smb[];
    __nv_bfloat16* Qs = smb;
    __nv_bfloat16* Ks = Qs + 128 * FQS;
    __half* VT = (__half*)(Ks + 2 * 64 * FQS);
    __shared__ float kss[64];

    const int h = blockIdx.y;
    const int tid = threadIdx.x;
    const int lane = tid & 31;
    const int wid = tid >> 5;
    const int rm = wid * 16;

    const int a_row = lane & 15, a_koff = (lane >> 4) * 8;
    const int b_row = (lane & 7) + ((lane >> 4) & 1) * 8;
    const int b_koff = ((lane >> 3) & 1) * 8;
    const int er = lane >> 2, ec = (lane & 3) * 2;
    const float L2E = 1.4426950408889634f;

    // VT const rows 64..79: ones at row 64 (cols<64) -> row-sum column
    for (int i = tid; i < 2 * 16 * FVS; i += 256) {
        int buf = i / (16 * FVS);
        int rr = (i / FVS) % 16;
        int c = i % FVS;
        __half v = __ushort_as_half((unsigned short)0);
        if (rr == 0 && c < 64) v = __float2half(1.0f);
        VT[buf * 80 * FVS + (64 + rr) * FVS + c] = v;
    }

    // smem col group g (0..2): Q src seg = (g==1)?lo:hi, K src seg = (g==2)?lo:hi
    auto load_kv = [&](int buf, int s0) {
        __nv_bfloat16* ks = Ks + buf * 64 * FQS;
        __half* vt = VT + buf * 80 * FVS;
        for (int i = tid; i < 64 * 24; i += 256) {
            int r = i / 24, c = i % 24;
            int g = c >> 3, c8 = (c & 7) * 8;
            int kcol = ((g == 2) ? 64 : 0) + c8;
            CP_ASYNC16(smem_u32(ks + r * FQS + c * 8),
                       lk2 + (size_t)(s0 + r) * 128 + kcol);
        }
        for (int i = tid; i < 64 * 8; i += 256) {
            int r = i >> 3, c = i & 7;
            CP_ASYNC16(smem_u32(vt + r * FVS + c * 8),
                       lvTh + (size_t)r * T_SEQ + s0 + c * 8);
        }
    };

#pragma unroll 1
    for (int pass = 0; pass < 2; pass++) {
        const int qt = pass == 0 ? (15 - blockIdx.x) : blockIdx.x;
        const int q0 = qt * 128;
        __syncthreads();

        for (int i = tid; i < 128 * 24; i += 256) {
            int r = i / 24, c = i % 24;
            int g = c >> 3, c8 = (c & 7) * 8;
            int qcol = ((g == 1) ? 64 : 0) + c8;
            CP_ASYNC16(smem_u32(Qs + r * FQS + c * 8),
                       qlat2 + ((size_t)(q0 + r) * NH + h) * 128 + qcol);
        }
        load_kv(0, 0); CP_COMMIT();

        const float qss0 = qsum[(size_t)(q0 + rm + er) * NH + h] * 0.0625f;
        const float qss1 = qsum[(size_t)(q0 + rm + er + 8) * NH + h] * 0.0625f;
        const int gi0 = q0 + rm + er, gi1 = gi0 + 8;

        float Oa[9][4];
#pragma unroll
        for (int ni = 0; ni < 9; ni++)
#pragma unroll
            for (int r = 0; r < 4; r++) Oa[ni][r] = 0.f;
        float m0 = -1e30f, m1 = -1e30f;

        const int nkb = 2 * qt + 2;
        for (int kb = 0; kb < nkb; kb++) {
            const int buf = kb & 1;
            const int s0 = kb * 64;
            if (kb + 1 < nkb) { load_kv(buf ^ 1, (kb + 1) * 64); CP_COMMIT(); CP_WAIT1(); }
            else              { CP_WAIT0(); }
            if (tid < 64) kss[tid] = ksum[s0 + tid];
            __syncthreads();

            // ---- S = Q3 @ K3^T (3-term bf16, K'=192) ----
            float sacc[8][4];
#pragma unroll
            for (int ni = 0; ni < 8; ni++)
#pragma unroll
                for (int r = 0; r < 4; r++) sacc[ni][r] = 0.f;
            const uint32_t aQrow = smem_u32(Qs) + ((rm + a_row) * FQS + a_koff) * 2;
            const uint32_t sKb = smem_u32(Ks) + (uint32_t)(buf * 64 * FQS) * 2;
#pragma unroll
            for (int kk = 0; kk < 192; kk += 16) {
                uint32_t af[4];
                ldmx4(af[0], af[1], af[2], af[3], aQrow + kk * 2);
                uint32_t bfr[8][2];
#pragma unroll
                for (int n4 = 0; n4 < 4; n4++) {
                    uint32_t r0, r1, r2, r3;
                    ldmx4(r0, r1, r2, r3, sKb + ((n4 * 16 + b_row) * FQS + kk + b_koff) * 2);
                    bfr[n4 * 2 + 0][0] = r0; bfr[n4 * 2 + 0][1] = r1;
                    bfr[n4 * 2 + 1][0] = r2; bfr[n4 * 2 + 1][1] = r3;
                }
#pragma unroll
                for (int ni = 0; ni < 8; ni++) mma16816(sacc[ni], af, bfr[ni]);
            }

            // ---- scale + causal mask + reciprocal band ----
#pragma unroll
            for (int ni = 0; ni < 8; ni++) {
#pragma unroll
                for (int cc = 0; cc < 2; cc++) {
                    int gj = s0 + ni * 8 + ec + cc;
                    float ksv = kss[ni * 8 + ec + cc];
                    float v = sacc[ni][cc] * 0.125f;
                    if (gi0 - gj <= 64) v += qss0 * ksv;
                    sacc[ni][cc] = (gj <= gi0) ? v : -1e30f;
                    float w = sacc[ni][2 + cc] * 0.125f;
                    if (gi1 - gj <= 64) w += qss1 * ksv;
                    sacc[ni][2 + cc] = (gj <= gi1) ? w : -1e30f;
                }
            }

            // ---- online softmax on registers ----
            float mx0 = -1e30f, mx1 = -1e30f;
#pragma unroll
            for (int ni = 0; ni < 8; ni++) {
                mx0 = fmaxf(mx0, fmaxf(sacc[ni][0], sacc[ni][1]));
                mx1 = fmaxf(mx1, fmaxf(sacc[ni][2], sacc[ni][3]));
            }
            mx0 = fmaxf(mx0, __shfl_xor_sync(0xffffffffu, mx0, 1));
            mx0 = fmaxf(mx0, __shfl_xor_sync(0xffffffffu, mx0, 2));
            mx1 = fmaxf(mx1, __shfl_xor_sync(0xffffffffu, mx1, 1));
            mx1 = fmaxf(mx1, __shfl_xor_sync(0xffffffffu, mx1, 2));
            float mn0 = fmaxf(m0, mx0), mn1 = fmaxf(m1, mx1);
            float al0 = exp2f((m0 - mn0) * L2E);
            float al1 = exp2f((m1 - mn1) * L2E);
            m0 = mn0; m1 = mn1;
#pragma unroll
            for (int ni = 0; ni < 9; ni++) {
                Oa[ni][0] *= al0; Oa[ni][1] *= al0;
                Oa[ni][2] *= al1; Oa[ni][3] *= al1;
            }
            uint32_t p01[8], p23[8];
#pragma unroll
            for (int ni = 0; ni < 8; ni++) {
                float x0 = (sacc[ni][0] - mn0) * L2E;
                float x1 = (sacc[ni][1] - mn0) * L2E;
                float x2 = (sacc[ni][2] - mn1) * L2E;
                float x3 = (sacc[ni][3] - mn1) * L2E;
                uint32_t hx;
                asm("cvt.rn.f16x2.f32 %0, %1, %2;" : "=r"(hx) : "f"(x1), "f"(x0));
                asm("ex2.approx.f16x2 %0, %1;" : "=r"(p01[ni]) : "r"(hx));
                asm("cvt.rn.f16x2.f32 %0, %1, %2;" : "=r"(hx) : "f"(x3), "f"(x2));
                asm("ex2.approx.f16x2 %0, %1;" : "=r"(p23[ni]) : "r"(hx));
            }

            // ---- O += P @ V^T (fp16; col 64 = ones -> row sum) ----
            const uint32_t sVb = smem_u32(VT) + (uint32_t)(buf * 80 * FVS) * 2;
#pragma unroll
            for (int kk = 0; kk < 64; kk += 16) {
                int f = kk >> 3;
                uint32_t af[4] = { p01[f], p23[f], p01[f + 1], p23[f + 1] };
                uint32_t bfr[10][2];
#pragma unroll
                for (int n4 = 0; n4 < 5; n4++) {
                    uint32_t r0, r1, r2, r3;
                    ldmx4(r0, r1, r2, r3,
                          sVb + ((n4 * 16 + b_row) * FVS + kk + b_koff) * 2);
                    bfr[n4 * 2 + 0][0] = r0; bfr[n4 * 2 + 0][1] = r1;
                    bfr[n4 * 2 + 1][0] = r2; bfr[n4 * 2 + 1][1] = r3;
                }
#pragma unroll
                for (int ni = 0; ni < 9; ni++) mma16816h(Oa[ni], af, bfr[ni]);
            }
            __syncthreads();
        }

        // ---- epilogue ----
        float ls0 = __shfl_sync(0xffffffffu, Oa[8][0], lane & ~3);
        float ls1 = __shfl_sync(0xffffffffu, Oa[8][2], lane & ~3);
        float li0 = 1.f / ls0, li1 = 1.f / ls1;
        const int t0 = q0 + rm + er, t1 = t0 + 8;
#pragma unroll
        for (int ni = 0; ni < 8; ni++) {
            int c0 = ni * 8 + ec;
            float v0 = Oa[ni][0] * li0, v1 = Oa[ni][1] * li0;
            float v2 = Oa[ni][2] * li1, v3 = Oa[ni][3] * li1;
            __nv_bfloat16 h0 = __float2bfloat16(v0), h1 = __float2bfloat16(v1);
            __nv_bfloat162 hp0; hp0.x = h0; hp0.y = h1;
            __nv_bfloat162 lp0;
            lp0.x = __float2bfloat16(v0 - __bfloat162float(h0));
            lp0.y = __float2bfloat16(v1 - __bfloat162float(h1));
            size_t b0 = (size_t)t0 * 2048 + h * 64 + c0;
            *(__nv_bfloat162*)(lctx2 + b0)        = hp0;
            *(__nv_bfloat162*)(lctx2 + b0 + 1024) = lp0;
            __nv_bfloat16 h2 = __float2bfloat16(v2), h3 = __float2bfloat16(v3);
            __nv_bfloat162 hp1; hp1.x = h2; hp1.y = h3;
            __nv_bfloat162 lp1;
            lp1.x = __float2bfloat16(v2 - __bfloat162float(h2));
            lp1.y = __float2bfloat16(v3 - __bfloat162float(h3));
            size_t b1 = (size_t)t1 * 2048 + h * 64 + c0;
            *(__nv_bfloat162*)(lctx2 + b1)        = hp1;
            *(__nv_bfloat162*)(lctx2 + b1 + 1024) = lp1;
        }
    }
}

// ---------------- host launcher ----------------
extern "C" void kernel_launch(void* const* d_in, const int* in_sizes, int n_in,
                              void* d_out, int out_size)
{
    const float* hidden = (const float*)d_in[0];
    const float* Wq  = (const float*)d_in[1];
    const float* Wk  = (const float*)d_in[2];
    const float* Wv  = (const float*)d_in[3];
    const float* q2l = (const float*)d_in[4];
    const float* vup = (const float*)d_in[5];
    const float* Wo  = (const float*)d_in[6];
    float* out = (float*)d_out;

    float *q2lT, *lpart, *qs, *ks;
    __nv_bfloat16 *hid2, *WqT2, *Wo2, *q2l2p, *vup2p, *Wf12, *Wf22, *Wkv2, *qlat2, *lk2, *lctx2;
    __half *lvTh;
    cudaGetSymbolAddress((void**)&q2lT,  g_q2lT);
    cudaGetSymbolAddress((void**)&lpart, g_lpart);
    cudaGetSymbolAddress((void**)&qs,    g_qsum);
    cudaGetSymbolAddress((void**)&ks,    g_ksum);
    cudaGetSymbolAddress((void**)&hid2,  g_hid2);
    cudaGetSymbolAddress((void**)&WqT2,  g_WqT2);
    cudaGetSymbolAddress((void**)&Wo2,   g_Wo2);
    cudaGetSymbolAddress((void**)&q2l2p, g_q2l2p);
    cudaGetSymbolAddress((void**)&vup2p, g_vup2p);
    cudaGetSymbolAddress((void**)&Wf12,  g_Wf12);
    cudaGetSymbolAddress((void**)&Wf22,  g_Wf22);
    cudaGetSymbolAddress((void**)&Wkv2,  g_Wkv2);
    cudaGetSymbolAddress((void**)&qlat2, g_qlat2);
    cudaGetSymbolAddress((void**)&lk2,   g_lk2);
    cudaGetSymbolAddress((void**)&lvTh,  g_lvTh);
    cudaGetSymbolAddress((void**)&lctx2, g_lctx2);

    cudaFuncSetAttribute(hmma_gemm,
                         cudaFuncAttributeMaxDynamicSharedMemorySize, HMMA_SMEM);
    cudaFuncSetAttribute(hmma_qlat,
                         cudaFuncAttributeMaxDynamicSharedMemorySize, HMMA_SMEM);
    cudaFuncSetAttribute(hmma_fold,
                         cudaFuncAttributeMaxDynamicSharedMemorySize, HMMA_SMEM);
    cudaFuncSetAttribute(flash_hmma,
                         cudaFuncAttributeMaxDynamicSharedMemorySize, FLASH_SMEM);

    // --- weight preprocessing ---
    transpose_k<<<dim3(2, 4, NH), dim3(32, 8)>>>(q2l, q2lT, HD, LAT,
                                                 (long)HD * LAT, (long)LAT * HD);
    transpose_split2<<<dim3(64, 64), dim3(32, 8)>>>(Wq, WqT2);
    cvt_split2<<<(EMB * EMB / 4 + 255) / 256, 256>>>(
        Wo, Wo2, EMB * EMB, HD, HD);                            // per-(e,h) [hi|lo]
    cvt_split2_pad<<<(NH * HD * HD / 4 + 255) / 256, 256>>>(
        q2lT, q2l2p, NH, LAT, HD, HD, HD);
    cvt_split2_pad<<<(NH * HD * HD / 4 + 255) / 256, 256>>>(
        vup, vup2p, NH, LAT, HD, HD, HD);

    // --- folds on tensor cores ([hi|lo] outputs) ---
    hmma_fold<<<dim3(16, 1, NH), 256, HMMA_SMEM>>>(
        q2l2p, WqT2, Wf12, HD, 2 * HD, NH * 2 * HD,
        (long)HD * 2 * HD, (long)2 * HD, (long)LAT * 2 * EMB,
        2 * EMB, EMB, LAT, EMB);
    hmma_fold<<<dim3(1, 16, NH), 256, HMMA_SMEM>>>(
        Wo2, vup2p, Wf22, HD, NH * 2 * HD, 2 * HD,
        (long)2 * HD, (long)HD * 2 * HD, (long)LAT,
        2 * NH * LAT, NH * LAT, EMB, LAT);

    // --- input splits ---
    cvt_split2<<<(T_SEQ * EMB / 4 + 255) / 256, 256>>>(
        hidden, hid2, T_SEQ * EMB, EMB, EMB);
    cvt_split2<<<(LAT * EMB / 4 + 255) / 256, 256>>>(
        Wk, Wkv2, LAT * EMB, EMB, EMB);
    cvt_split2<<<(LAT * EMB / 4 + 255) / 256, 256>>>(
        Wv, Wkv2 + (size_t)LAT * 2 * EMB, LAT * EMB, EMB, EMB);

    // --- lkv split-K x8; reduce+convert fused in cvt_kv ---
    hmma_gemm<<<dim3(1, 16, 8), 256, HMMA_SMEM>>>(hid2, Wkv2, lpart,
                                                  T_SEQ, 2 * LAT, EMB, 8);
    cvt_kv<<<32, 256>>>(lpart, lk2, lvTh, ks);

    // --- q_latent -> qlat2 [hi|lo] directly (HMMA) ---
    hmma_qlat<<<dim3(8, 16), 256, HMMA_SMEM>>>(hid2, Wf12, qlat2, EMB);
    qsum_kernel<<<(T_SEQ * NH + 255) / 256, 256>>>(qlat2, qs);

    // --- flash attention ---
    flash_hmma<<<dim3(8, NH), 256, FLASH_SMEM>>>(qlat2, lk2, lvTh, qs, ks, lctx2);

    // --- out = lctx @ Wf2T^T (HMMA) ---
    hmma_gemm<<<dim3(16, 16, 1), 256, HMMA_SMEM>>>(lctx2, Wf22, out,
                                                   T_SEQ, EMB, NH * LAT, 1);
}

// round 13
// speedup vs baseline: 9.7144x; 1.7755x over previous
#include <cuda_runtime.h>
#include <cuda_bf16.h>
#include <cuda_fp16.h>
#include <cstdint>

#define T_SEQ 2048
#define EMB   2048
#define NH    16
#define HD    128
#define LAT   64

// ---------------- scratch (static device globals; no allocation) ----------------
__device__ float g_q2lT[NH * LAT * HD];
__device__ float g_lpart[8 * T_SEQ * 2 * LAT];
__device__ float g_qsum[T_SEQ * NH];
__device__ float g_ksum[T_SEQ];
// fold inputs: bf16 [hi|lo] (kept high-precision; tiny)
__device__ __align__(16) __nv_bfloat16 g_WqT2 [EMB * NH * 2 * HD];
__device__ __align__(16) __nv_bfloat16 g_Wo2  [EMB * NH * 2 * HD];
__device__ __align__(16) __nv_bfloat16 g_q2l2p[NH * HD * 2 * HD];
__device__ __align__(16) __nv_bfloat16 g_vup2p[NH * HD * 2 * HD];
// fp16 single-precision activation path
__device__ __align__(16) __half g_hidh [T_SEQ * EMB];        // 8 MB
__device__ __align__(16) __half g_Wkvh [2 * LAT * EMB];      // 0.5 MB
__device__ __align__(16) __half g_Wf1h [NH * LAT * EMB];     // 4 MB
__device__ __align__(16) __half g_Wf2h [EMB * NH * LAT];     // 4 MB
__device__ __align__(16) __half g_qlath[T_SEQ * NH * LAT];   // 4 MB
__device__ __align__(16) __half g_lkh  [T_SEQ * LAT];        // 0.25 MB
__device__ __align__(16) __half g_lvTh [LAT * T_SEQ];        // V^T
__device__ __align__(16) __half g_lctxh[T_SEQ * NH * LAT];   // 4 MB

// ================= PTX helpers =================
__device__ __forceinline__ uint32_t smem_u32(const void* p) {
    uint32_t a;
    asm("{ .reg .u64 t; cvta.to.shared.u64 t, %1; cvt.u32.u64 %0, t; }" : "=r"(a) : "l"(p));
    return a;
}
#define CP_ASYNC16(dst, src) \
    asm volatile("cp.async.cg.shared.global [%0], [%1], 16;" :: "r"(dst), "l"(src))
#define CP_COMMIT() asm volatile("cp.async.commit_group;")
#define CP_WAIT1()  asm volatile("cp.async.wait_group 1;")
#define CP_WAIT0()  asm volatile("cp.async.wait_group 0;")

__device__ __forceinline__ void ldmx4(uint32_t& r0, uint32_t& r1, uint32_t& r2, uint32_t& r3,
                                      uint32_t addr) {
    asm volatile("ldmatrix.sync.aligned.m8n8.x4.shared.b16 {%0,%1,%2,%3}, [%4];"
                 : "=r"(r0), "=r"(r1), "=r"(r2), "=r"(r3) : "r"(addr));
}
__device__ __forceinline__ void mma16816(float* d, const uint32_t* a, const uint32_t* b) {
    asm volatile("mma.sync.aligned.m16n8k16.row.col.f32.bf16.bf16.f32 "
                 "{%0,%1,%2,%3}, {%4,%5,%6,%7}, {%8,%9}, {%0,%1,%2,%3};"
                 : "+f"(d[0]), "+f"(d[1]), "+f"(d[2]), "+f"(d[3])
                 : "r"(a[0]), "r"(a[1]), "r"(a[2]), "r"(a[3]), "r"(b[0]), "r"(b[1]));
}
__device__ __forceinline__ void mma16816h(float* d, const uint32_t* a, const uint32_t* b) {
    asm volatile("mma.sync.aligned.m16n8k16.row.col.f32.f16.f16.f32 "
                 "{%0,%1,%2,%3}, {%4,%5,%6,%7}, {%8,%9}, {%0,%1,%2,%3};"
                 : "+f"(d[0]), "+f"(d[1]), "+f"(d[2]), "+f"(d[3])
                 : "r"(a[0]), "r"(a[1]), "r"(a[2]), "r"(a[3]), "r"(b[0]), "r"(b[1]));
}

// ---------------- fp32 -> fp16 convert ----------------
__global__ void cvt_f16(const float* __restrict__ x, __half* __restrict__ out, int n)
{
    int i = (blockIdx.x * blockDim.x + threadIdx.x) * 4;
    if (i >= n) return;
    float4 v = *(const float4*)(x + i);
    __half2 a = __floats2half2_rn(v.x, v.y);
    __half2 b = __floats2half2_rn(v.z, v.w);
    uint2 pk;
    pk.x = *(uint32_t*)&a; pk.y = *(uint32_t*)&b;
    *(uint2*)(out + i) = pk;
}

// ---------------- fp32 -> [hi|lo] bf16 split (fold inputs) ----------------
__global__ void cvt_split2(const float* __restrict__ x, __nv_bfloat16* __restrict__ out,
                           int total, int K, int offL)
{
    int i = (blockIdx.x * blockDim.x + threadIdx.x) * 4;
    if (i >= total) return;
    float4 v = *(const float4*)(x + i);
    float vv[4] = {v.x, v.y, v.z, v.w};
    __nv_bfloat16 hb[4], lb[4];
#pragma unroll
    for (int k = 0; k < 4; k++) {
        hb[k] = __float2bfloat16(vv[k]);
        lb[k] = __float2bfloat16(vv[k] - __bfloat162float(hb[k]));
    }
    int r = i / K, c = i - r * K;
    size_t base = (size_t)r * 2 * K + c;
    *(uint2*)(out + base)        = *(uint2*)hb;
    *(uint2*)(out + base + offL) = *(uint2*)lb;
}

__global__ void cvt_split2_pad(const float* __restrict__ x, __nv_bfloat16* __restrict__ out,
                               int nb, int rows, int K, int padRows, int offL)
{
    int i = (blockIdx.x * blockDim.x + threadIdx.x) * 4;
    int total = nb * padRows * K;
    if (i >= total) return;
    int b = i / (padRows * K);
    int rem = i - b * (padRows * K);
    int r = rem / K, c = rem - r * K;
    float vv[4] = {0.f, 0.f, 0.f, 0.f};
    if (r < rows) {
        float4 v = *(const float4*)(x + (size_t)b * rows * K + (size_t)r * K + c);
        vv[0] = v.x; vv[1] = v.y; vv[2] = v.z; vv[3] = v.w;
    }
    __nv_bfloat16 hb[4], lb[4];
#pragma unroll
    for (int k = 0; k < 4; k++) {
        hb[k] = __float2bfloat16(vv[k]);
        lb[k] = __float2bfloat16(vv[k] - __bfloat162float(hb[k]));
    }
    size_t base = (size_t)b * padRows * 2 * K + (size_t)r * 2 * K + c;
    *(uint2*)(out + base)        = *(uint2*)hb;
    *(uint2*)(out + base + offL) = *(uint2*)lb;
}

// ---- fused transpose + split: Wq [hd][e] -> WqT2 [e][h][256] ([hi|lo]) ----
__global__ void transpose_split2(const float* __restrict__ in, __nv_bfloat16* __restrict__ out)
{
    __shared__ float t[32][33];
    int x = blockIdx.x * 32 + threadIdx.x;
    for (int i = threadIdx.y; i < 32; i += 8) {
        int y = blockIdx.y * 32 + i;
        t[i][threadIdx.x] = in[(size_t)y * EMB + x];
    }
    __syncthreads();
    for (int i = threadIdx.y; i < 32; i += 8) {
        int eo = blockIdx.x * 32 + i;
        int hd = blockIdx.y * 32 + threadIdx.x;
        float v = t[threadIdx.x][i];
        __nv_bfloat16 h = __float2bfloat16(v);
        __nv_bfloat16 l = __float2bfloat16(v - __bfloat162float(h));
        int hh = hd >> 7, d = hd & 127;
        size_t base = (size_t)eo * (NH * 2 * HD) + hh * 256 + d;
        out[base]       = h;
        out[base + 128] = l;
    }
}

// ---------------- batched tiled transpose (fp32) ----------------
__global__ void transpose_k(const float* __restrict__ in, float* __restrict__ out,
                            int R, int C, long bIn, long bOut)
{
    __shared__ float t[32][33];
    in  += (long)blockIdx.z * bIn;
    out += (long)blockIdx.z * bOut;
    int x = blockIdx.x * 32 + threadIdx.x;
    for (int i = threadIdx.y; i < 32; i += 8) {
        int y = blockIdx.y * 32 + i;
        if (y < R && x < C) t[i][threadIdx.x] = in[(size_t)y * C + x];
    }
    __syncthreads();
    for (int i = threadIdx.y; i < 32; i += 8) {
        int y2 = blockIdx.x * 32 + i;
        int x2 = blockIdx.y * 32 + threadIdx.x;
        if (y2 < C && x2 < R) out[(size_t)y2 * R + x2] = t[threadIdx.x][i];
    }
}

#define GS 72
#define STAGE_ELTS (128 * GS)
#define HMMA_SMEM (3 * 2 * STAGE_ELTS * 2)

// ==== HMMA fold GEMM (bf16x3 phase-mapped) -> single fp16 output ====
__global__ __launch_bounds__(256) void hmma_fold(
    const __nv_bfloat16* __restrict__ A, const __nv_bfloat16* __restrict__ B,
    __half* __restrict__ Ch, int Ka, int lda, int ldb,
    long batchA, long batchB, long batchC,
    int ldc, int validM, int validN)
{
    extern __shared__ __align__(16) __nv_bfloat16 sm[];
    const int tid = threadIdx.x;
    const int wid = tid >> 5;
    const int lane = tid & 31;
    const int warp_m = wid >> 2;
    const int warp_n = wid & 3;
    const int bm = blockIdx.y * 128;
    const int bn = blockIdx.x * 128;
    const uint32_t sbase = smem_u32(sm);

    A  += (size_t)blockIdx.z * batchA;
    B  += (size_t)blockIdx.z * batchB;
    Ch += (size_t)blockIdx.z * batchC;
    const int nk = (3 * Ka) >> 6;

    auto load_stage = [&](int stage, int k0) {
        __nv_bfloat16* As = sm + stage * 2 * STAGE_ELTS;
        __nv_bfloat16* Bs = As + STAGE_ELTS;
        int p = (k0 >= 2 * Ka) ? 2 : (k0 >= Ka ? 1 : 0);
        int kloc = k0 - p * Ka;
        const __nv_bfloat16* Ap = A + ((p == 1) ? Ka : 0) + kloc;
        const __nv_bfloat16* Bp = B + ((p == 2) ? Ka : 0) + kloc;
#pragma unroll
        for (int i = 0; i < 4; i++) {
            int c = tid + i * 256;
            int row = c >> 3;
            int col8 = (c & 7) * 8;
            CP_ASYNC16(smem_u32(As + row * GS + col8), Ap + (size_t)(bm + row) * lda + col8);
            CP_ASYNC16(smem_u32(Bs + row * GS + col8), Bp + (size_t)(bn + row) * ldb + col8);
        }
    };

    float acc[4][4][4];
#pragma unroll
    for (int mi = 0; mi < 4; mi++)
#pragma unroll
        for (int ni = 0; ni < 4; ni++)
#pragma unroll
            for (int r = 0; r < 4; r++) acc[mi][ni][r] = 0.f;

    load_stage(0, 0); CP_COMMIT();
    if (nk > 1) { load_stage(1, 64); CP_COMMIT(); }

    const int a_row = (lane & 15);
    const int a_koff = (lane >> 4) * 8;
    const int b_row = (lane & 7) + ((lane >> 4) & 1) * 8;
    const int b_koff = ((lane >> 3) & 1) * 8;

    for (int it = 0; it < nk; it++) {
        CP_WAIT1();
        __syncthreads();
        if (it + 2 < nk) { load_stage((it + 2) % 3, (it + 2) * 64); CP_COMMIT(); }

        const int stage = it % 3;
        const uint32_t sA = sbase + (uint32_t)(stage * 2 * STAGE_ELTS) * 2;
        const uint32_t sB = sA + STAGE_ELTS * 2;

#pragma unroll
        for (int kk = 0; kk < 64; kk += 16) {
            uint32_t af[4][4];
#pragma unroll
            for (int mi = 0; mi < 4; mi++) {
                uint32_t addr = sA + ((warp_m * 64 + mi * 16 + a_row) * GS + kk + a_koff) * 2;
                ldmx4(af[mi][0], af[mi][1], af[mi][2], af[mi][3], addr);
            }
            uint32_t bf[4][2];
#pragma unroll
            for (int ni2 = 0; ni2 < 2; ni2++) {
                uint32_t addr = sB + ((warp_n * 32 + ni2 * 16 + b_row) * GS + kk + b_koff) * 2;
                uint32_t r0, r1, r2, r3;
                ldmx4(r0, r1, r2, r3, addr);
                bf[ni2 * 2 + 0][0] = r0; bf[ni2 * 2 + 0][1] = r1;
                bf[ni2 * 2 + 1][0] = r2; bf[ni2 * 2 + 1][1] = r3;
            }
#pragma unroll
            for (int mi = 0; mi < 4; mi++)
#pragma unroll
                for (int ni = 0; ni < 4; ni++)
                    mma16816(acc[mi][ni], af[mi], bf[ni]);
        }
        __syncthreads();
    }

    const int er = lane >> 2;
    const int ec = (lane & 3) * 2;
#pragma unroll
    for (int mi = 0; mi < 4; mi++) {
#pragma unroll
        for (int ni = 0; ni < 4; ni++) {
            int n0 = bn + warp_n * 32 + ni * 8 + ec;
            if (n0 >= validN) continue;
#pragma unroll
            for (int rr = 0; rr < 2; rr++) {
                int m0 = bm + warp_m * 64 + mi * 16 + er + rr * 8;
                if (m0 >= validM) continue;
                __half2 hp = __floats2half2_rn(acc[mi][ni][rr * 2 + 0],
                                               acc[mi][ni][rr * 2 + 1]);
                *(__half2*)(Ch + (size_t)m0 * ldc + n0) = hp;
            }
        }
    }
}

// ============== plain fp16 HMMA GEMM (+split-K): C fp32 = A @ B^T ==============
__global__ __launch_bounds__(256) void hmma_gemm_f16(
    const __half* __restrict__ A, const __half* __restrict__ B,
    float* __restrict__ C, int M, int N, int K, int nsplit)
{
    extern __shared__ __align__(16) __half smh[];
    const int tid = threadIdx.x;
    const int wid = tid >> 5;
    const int lane = tid & 31;
    const int warp_m = wid >> 2;
    const int warp_n = wid & 3;
    const int bm = blockIdx.y * 128;
    const int bn = blockIdx.x * 128;
    const uint32_t sbase = smem_u32(smh);

    const int Kc = K / nsplit;
    const int kbeg = blockIdx.z * Kc;
    C += (size_t)blockIdx.z * M * N;
    const int nk = Kc >> 6;

    auto load_stage = [&](int stage, int k0) {
        __half* As = smh + stage * 2 * STAGE_ELTS;
        __half* Bs = As + STAGE_ELTS;
#pragma unroll
        for (int i = 0; i < 4; i++) {
            int c = tid + i * 256;
            int row = c >> 3;
            int col8 = (c & 7) * 8;
            CP_ASYNC16(smem_u32(As + row * GS + col8),
                       A + (size_t)(bm + row) * K + kbeg + k0 + col8);
            CP_ASYNC16(smem_u32(Bs + row * GS + col8),
                       B + (size_t)(bn + row) * K + kbeg + k0 + col8);
        }
    };

    float acc[4][4][4];
#pragma unroll
    for (int mi = 0; mi < 4; mi++)
#pragma unroll
        for (int ni = 0; ni < 4; ni++)
#pragma unroll
            for (int r = 0; r < 4; r++) acc[mi][ni][r] = 0.f;

    load_stage(0, 0); CP_COMMIT();
    if (nk > 1) { load_stage(1, 64); CP_COMMIT(); }

    const int a_row = (lane & 15);
    const int a_koff = (lane >> 4) * 8;
    const int b_row = (lane & 7) + ((lane >> 4) & 1) * 8;
    const int b_koff = ((lane >> 3) & 1) * 8;

    for (int it = 0; it < nk; it++) {
        CP_WAIT1();
        __syncthreads();
        if (it + 2 < nk) { load_stage((it + 2) % 3, (it + 2) * 64); CP_COMMIT(); }

        const int stage = it % 3;
        const uint32_t sA = sbase + (uint32_t)(stage * 2 * STAGE_ELTS) * 2;
        const uint32_t sB = sA + STAGE_ELTS * 2;

#pragma unroll
        for (int kk = 0; kk < 64; kk += 16) {
            uint32_t af[4][4];
#pragma unroll
            for (int mi = 0; mi < 4; mi++) {
                uint32_t addr = sA + ((warp_m * 64 + mi * 16 + a_row) * GS + kk + a_koff) * 2;
                ldmx4(af[mi][0], af[mi][1], af[mi][2], af[mi][3], addr);
            }
            uint32_t bf[4][2];
#pragma unroll
            for (int ni2 = 0; ni2 < 2; ni2++) {
                uint32_t addr = sB + ((warp_n * 32 + ni2 * 16 + b_row) * GS + kk + b_koff) * 2;
                uint32_t r0, r1, r2, r3;
                ldmx4(r0, r1, r2, r3, addr);
                bf[ni2 * 2 + 0][0] = r0; bf[ni2 * 2 + 0][1] = r1;
                bf[ni2 * 2 + 1][0] = r2; bf[ni2 * 2 + 1][1] = r3;
            }
#pragma unroll
            for (int mi = 0; mi < 4; mi++)
#pragma unroll
                for (int ni = 0; ni < 4; ni++)
                    mma16816h(acc[mi][ni], af[mi], bf[ni]);
        }
        __syncthreads();
    }

    const int er = lane >> 2;
    const int ec = (lane & 3) * 2;
#pragma unroll
    for (int mi = 0; mi < 4; mi++) {
#pragma unroll
        for (int ni = 0; ni < 4; ni++) {
            int m0 = bm + warp_m * 64 + mi * 16 + er;
            int n0 = bn + warp_n * 32 + ni * 8 + ec;
            *(float2*)(C + (size_t)m0 * N + n0) = make_float2(acc[mi][ni][0], acc[mi][ni][1]);
            *(float2*)(C + (size_t)(m0 + 8) * N + n0) = make_float2(acc[mi][ni][2], acc[mi][ni][3]);
        }
    }
}

// ==== hmma_qlat_f16: qlat GEMM writing fp16 output [t][h*64+l] ====
__global__ __launch_bounds__(256) void hmma_qlat_f16(
    const __half* __restrict__ A, const __half* __restrict__ B,
    __half* __restrict__ Qh, int K)
{
    extern __shared__ __align__(16) __half smh[];
    const int tid = threadIdx.x;
    const int wid = tid >> 5;
    const int lane = tid & 31;
    const int warp_m = wid >> 2;
    const int warp_n = wid & 3;
    const int bm = blockIdx.y * 128;
    const int bn = blockIdx.x * 128;
    const uint32_t sbase = smem_u32(smh);
    const int nk = K >> 6;

    auto load_stage = [&](int stage, int k0) {
        __half* As = smh + stage * 2 * STAGE_ELTS;
        __half* Bs = As + STAGE_ELTS;
#pragma unroll
        for (int i = 0; i < 4; i++) {
            int c = tid + i * 256;
            int row = c >> 3;
            int col8 = (c & 7) * 8;
            CP_ASYNC16(smem_u32(As + row * GS + col8),
                       A + (size_t)(bm + row) * K + k0 + col8);
            CP_ASYNC16(smem_u32(Bs + row * GS + col8),
                       B + (size_t)(bn + row) * K + k0 + col8);
        }
    };

    float acc[4][4][4];
#pragma unroll
    for (int mi = 0; mi < 4; mi++)
#pragma unroll
        for (int ni = 0; ni < 4; ni++)
#pragma unroll
            for (int r = 0; r < 4; r++) acc[mi][ni][r] = 0.f;

    load_stage(0, 0); CP_COMMIT();
    if (nk > 1) { load_stage(1, 64); CP_COMMIT(); }

    const int a_row = (lane & 15);
    const int a_koff = (lane >> 4) * 8;
    const int b_row = (lane & 7) + ((lane >> 4) & 1) * 8;
    const int b_koff = ((lane >> 3) & 1) * 8;

    for (int it = 0; it < nk; it++) {
        CP_WAIT1();
        __syncthreads();
        if (it + 2 < nk) { load_stage((it + 2) % 3, (it + 2) * 64); CP_COMMIT(); }

        const int stage = it % 3;
        const uint32_t sA = sbase + (uint32_t)(stage * 2 * STAGE_ELTS) * 2;
        const uint32_t sB = sA + STAGE_ELTS * 2;

#pragma unroll
        for (int kk = 0; kk < 64; kk += 16) {
            uint32_t af[4][4];
#pragma unroll
            for (int mi = 0; mi < 4; mi++) {
                uint32_t addr = sA + ((warp_m * 64 + mi * 16 + a_row) * GS + kk + a_koff) * 2;
                ldmx4(af[mi][0], af[mi][1], af[mi][2], af[mi][3], addr);
            }
            uint32_t bf[4][2];
#pragma unroll
            for (int ni2 = 0; ni2 < 2; ni2++) {
                uint32_t addr = sB + ((warp_n * 32 + ni2 * 16 + b_row) * GS + kk + b_koff) * 2;
                uint32_t r0, r1, r2, r3;
                ldmx4(r0, r1, r2, r3, addr);
                bf[ni2 * 2 + 0][0] = r0; bf[ni2 * 2 + 0][1] = r1;
                bf[ni2 * 2 + 1][0] = r2; bf[ni2 * 2 + 1][1] = r3;
            }
#pragma unroll
            for (int mi = 0; mi < 4; mi++)
#pragma unroll
                for (int ni = 0; ni < 4; ni++)
                    mma16816h(acc[mi][ni], af[mi], bf[ni]);
        }
        __syncthreads();
    }

    const int er = lane >> 2;
    const int ec = (lane & 3) * 2;
#pragma unroll
    for (int mi = 0; mi < 4; mi++) {
#pragma unroll
        for (int ni = 0; ni < 4; ni++) {
            int n0 = bn + warp_n * 32 + ni * 8 + ec;
#pragma unroll
            for (int rr = 0; rr < 2; rr++) {
                int m0 = bm + warp_m * 64 + mi * 16 + er + rr * 8;
                __half2 hp = __floats2half2_rn(acc[mi][ni][rr * 2 + 0],
                                               acc[mi][ni][rr * 2 + 1]);
                *(__half2*)(Qh + (size_t)m0 * (NH * LAT) + n0) = hp;
            }
        }
    }
}

// ---- cvt_kv: lpart[8][T][128] -> lkh fp16 [T][64], lvTh [64][T], ksum ----
__global__ __launch_bounds__(256) void cvt_kv(
    const float* __restrict__ lpart, __half* __restrict__ lkh,
    __half* __restrict__ lvTh, float* __restrict__ ksum)
{
    __shared__ __half vh[64][65];
    __shared__ float kvs[64][65];
    const int t0 = blockIdx.x * 64;
    const int tid = threadIdx.x;
    for (int i = tid; i < 64 * 64; i += 256) {
        int r = i >> 6, l = i & 63;
        size_t idx = (size_t)(t0 + r) * 128 + l;
        float kv = 0.f, vv = 0.f;
#pragma unroll
        for (int s = 0; s < 8; s++) {
            kv += lpart[(size_t)s * T_SEQ * 128 + idx];
            vv += lpart[(size_t)s * T_SEQ * 128 + idx + 64];
        }
        vh[l][r] = __float2half(vv);
        kvs[r][l] = kv;
        lkh[(size_t)(t0 + r) * 64 + l] = __float2half(kv);
    }
    __syncthreads();
    for (int i = tid; i < 64 * 64; i += 256) {
        int l = i >> 6, r = i & 63;
        lvTh[(size_t)l * T_SEQ + t0 + r] = vh[l][r];
    }
    if (tid < 64) {
        float s = 0.f;
#pragma unroll 8
        for (int l = 0; l < 64; l++) s += kvs[tid][l];
        ksum[t0 + tid] = s;
    }
}

// ---------------- qsum from fp16 qlat ----------------
__global__ void qsum_kernel(const __half* __restrict__ qlath, float* __restrict__ qsum)
{
    int i = blockIdx.x * blockDim.x + threadIdx.x;
    if (i >= T_SEQ * NH) return;
    float s = 0.f;
#pragma unroll 8
    for (int l = 0; l < LAT; l++) s += __half2float(qlath[(size_t)i * LAT + l]);
    qsum[i] = s;
}

// ========== FA2-style fp16 flash, paired q-tiles ==========
#define FQS 72
#define FVS 136
#define FLASH_SMEM ((128 * FQS + 2 * 64 * FQS + 2 * 80 * FVS) * 2)   // 80384

__global__ __launch_bounds__(256) void flash_hmma(
    const __half* __restrict__ qlath, const __half* __restrict__ lkh,
    const __half* __restrict__ lvTh,
    const float* __restrict__ qsum, const float* __restrict__ ksum,
    __half* __restrict__ lctxh)
{
    extern __shared__ __align__(16) __half smh[];
    __half* Qs = smh;                      // 128 x FQS
    __half* Ks = Qs + 128 * FQS;           // 2 x 64 x FQS
    __half* VT = Ks + 2 * 64 * FQS;        // 2 x 80 x FVS
    __shared__ float kss[64];

    const int h = blockIdx.y;
    const int tid = threadIdx.x;
    const int lane = tid & 31;
    const int wid = tid >> 5;
    const int rm = wid * 16;

    const int a_row = lane & 15, a_koff = (lane >> 4) * 8;
    const int b_row = (lane & 7) + ((lane >> 4) & 1) * 8;
    const int b_koff = ((lane >> 3) & 1) * 8;
    const int er = lane >> 2, ec = (lane & 3) * 2;
    const float L2E = 1.4426950408889634f;

    // VT const rows 64..79: ones at row 64 (cols<64) -> row-sum column
    for (int i = tid; i < 2 * 16 * FVS; i += 256) {
        int buf = i / (16 * FVS);
        int rr = (i / FVS) % 16;
        int c = i % FVS;
        __half v = __ushort_as_half((unsigned short)0);
        if (rr == 0 && c < 64) v = __float2half(1.0f);
        VT[buf * 80 * FVS + (64 + rr) * FVS + c] = v;
    }

    auto load_kv = [&](int buf, int s0) {
        __half* ks = Ks + buf * 64 * FQS;
        __half* vt = VT + buf * 80 * FVS;
        for (int i = tid; i < 64 * 8; i += 256) {
            int r = i >> 3, c = i & 7;
            CP_ASYNC16(smem_u32(ks + r * FQS + c * 8),
                       lkh + (size_t)(s0 + r) * 64 + c * 8);
            CP_ASYNC16(smem_u32(vt + r * FVS + c * 8),
                       lvTh + (size_t)r * T_SEQ + s0 + c * 8);
        }
    };

#pragma unroll 1
    for (int pass = 0; pass < 2; pass++) {
        const int qt = pass == 0 ? (15 - blockIdx.x) : blockIdx.x;
        const int q0 = qt * 128;
        __syncthreads();

        for (int i = tid; i < 128 * 8; i += 256) {
            int r = i >> 3, c = i & 7;
            CP_ASYNC16(smem_u32(Qs + r * FQS + c * 8),
                       qlath + ((size_t)(q0 + r) * NH + h) * 64 + c * 8);
        }
        load_kv(0, 0); CP_COMMIT();

        const float qss0 = qsum[(size_t)(q0 + rm + er) * NH + h] * 0.0625f;
        const float qss1 = qsum[(size_t)(q0 + rm + er + 8) * NH + h] * 0.0625f;
        const int gi0 = q0 + rm + er, gi1 = gi0 + 8;

        float Oa[9][4];
#pragma unroll
        for (int ni = 0; ni < 9; ni++)
#pragma unroll
            for (int r = 0; r < 4; r++) Oa[ni][r] = 0.f;
        float m0 = -1e30f, m1 = -1e30f;

        const int nkb = 2 * qt + 2;
        for (int kb = 0; kb < nkb; kb++) {
            const int buf = kb & 1;
            const int s0 = kb * 64;
            if (kb + 1 < nkb) { load_kv(buf ^ 1, (kb + 1) * 64); CP_COMMIT(); CP_WAIT1(); }
            else              { CP_WAIT0(); }
            if (tid < 64) kss[tid] = ksum[s0 + tid];
            __syncthreads();

            // ---- S = Q @ K^T (fp16, K=64) ----
            float sacc[8][4];
#pragma unroll
            for (int ni = 0; ni < 8; ni++)
#pragma unroll
                for (int r = 0; r < 4; r++) sacc[ni][r] = 0.f;
            const uint32_t aQrow = smem_u32(Qs) + ((rm + a_row) * FQS + a_koff) * 2;
            const uint32_t sKb = smem_u32(Ks) + (uint32_t)(buf * 64 * FQS) * 2;
#pragma unroll
            for (int kk = 0; kk < 64; kk += 16) {
                uint32_t af[4];
                ldmx4(af[0], af[1], af[2], af[3], aQrow + kk * 2);
                uint32_t bfr[8][2];
#pragma unroll
                for (int n4 = 0; n4 < 4; n4++) {
                    uint32_t r0, r1, r2, r3;
                    ldmx4(r0, r1, r2, r3, sKb + ((n4 * 16 + b_row) * FQS + kk + b_koff) * 2);
                    bfr[n4 * 2 + 0][0] = r0; bfr[n4 * 2 + 0][1] = r1;
                    bfr[n4 * 2 + 1][0] = r2; bfr[n4 * 2 + 1][1] = r3;
                }
#pragma unroll
                for (int ni = 0; ni < 8; ni++) mma16816h(sacc[ni], af, bfr[ni]);
            }

            // ---- scale + causal mask + reciprocal band ----
#pragma unroll
            for (int ni = 0; ni < 8; ni++) {
#pragma unroll
                for (int cc = 0; cc < 2; cc++) {
                    int gj = s0 + ni * 8 + ec + cc;
                    float ksv = kss[ni * 8 + ec + cc];
                    float v = sacc[ni][cc] * 0.125f;
                    if (gi0 - gj <= 64) v += qss0 * ksv;
                    sacc[ni][cc] = (gj <= gi0) ? v : -1e30f;
                    float w = sacc[ni][2 + cc] * 0.125f;
                    if (gi1 - gj <= 64) w += qss1 * ksv;
                    sacc[ni][2 + cc] = (gj <= gi1) ? w : -1e30f;
                }
            }

            // ---- online softmax on registers ----
            float mx0 = -1e30f, mx1 = -1e30f;
#pragma unroll
            for (int ni = 0; ni < 8; ni++) {
                mx0 = fmaxf(mx0, fmaxf(sacc[ni][0], sacc[ni][1]));
                mx1 = fmaxf(mx1, fmaxf(sacc[ni][2], sacc[ni][3]));
            }
            mx0 = fmaxf(mx0, __shfl_xor_sync(0xffffffffu, mx0, 1));
            mx0 = fmaxf(mx0, __shfl_xor_sync(0xffffffffu, mx0, 2));
            mx1 = fmaxf(mx1, __shfl_xor_sync(0xffffffffu, mx1, 1));
            mx1 = fmaxf(mx1, __shfl_xor_sync(0xffffffffu, mx1, 2));
            float mn0 = fmaxf(m0, mx0), mn1 = fmaxf(m1, mx1);
            float al0 = exp2f((m0 - mn0) * L2E);
            float al1 = exp2f((m1 - mn1) * L2E);
            m0 = mn0; m1 = mn1;
#pragma unroll
            for (int ni = 0; ni < 9; ni++) {
                Oa[ni][0] *= al0; Oa[ni][1] *= al0;
                Oa[ni][2] *= al1; Oa[ni][3] *= al1;
            }
            uint32_t p01[8], p23[8];
#pragma unroll
            for (int ni = 0; ni < 8; ni++) {
                float x0 = (sacc[ni][0] - mn0) * L2E;
                float x1 = (sacc[ni][1] - mn0) * L2E;
                float x2 = (sacc[ni][2] - mn1) * L2E;
                float x3 = (sacc[ni][3] - mn1) * L2E;
                uint32_t hx;
                asm("cvt.rn.f16x2.f32 %0, %1, %2;" : "=r"(hx) : "f"(x1), "f"(x0));
                asm("ex2.approx.f16x2 %0, %1;" : "=r"(p01[ni]) : "r"(hx));
                asm("cvt.rn.f16x2.f32 %0, %1, %2;" : "=r"(hx) : "f"(x3), "f"(x2));
                asm("ex2.approx.f16x2 %0, %1;" : "=r"(p23[ni]) : "r"(hx));
            }

            // ---- O += P @ V^T (fp16; col 64 = ones -> row sum) ----
            const uint32_t sVb = smem_u32(VT) + (uint32_t)(buf * 80 * FVS) * 2;
#pragma unroll
            for (int kk = 0; kk < 64; kk += 16) {
                int f = kk >> 3;
                uint32_t af[4] = { p01[f], p23[f], p01[f + 1], p23[f + 1] };
                uint32_t bfr[10][2];
#pragma unroll
                for (int n4 = 0; n4 < 5; n4++) {
                    uint32_t r0, r1, r2, r3;
                    ldmx4(r0, r1, r2, r3,
                          sVb + ((n4 * 16 + b_row) * FVS + kk + b_koff) * 2);
                    bfr[n4 * 2 + 0][0] = r0; bfr[n4 * 2 + 0][1] = r1;
                    bfr[n4 * 2 + 1][0] = r2; bfr[n4 * 2 + 1][1] = r3;
                }
#pragma unroll
                for (int ni = 0; ni < 9; ni++) mma16816h(Oa[ni], af, bfr[ni]);
            }
            __syncthreads();
        }

        // ---- epilogue: normalize, write fp16 lctx ----
        float ls0 = __shfl_sync(0xffffffffu, Oa[8][0], lane & ~3);
        float ls1 = __shfl_sync(0xffffffffu, Oa[8][2], lane & ~3);
        float li0 = 1.f / ls0, li1 = 1.f / ls1;
        const int t0 = q0 + rm + er, t1 = t0 + 8;
#pragma unroll
        for (int ni = 0; ni < 8; ni++) {
            int c0 = ni * 8 + ec;
            __half2 o0 = __floats2half2_rn(Oa[ni][0] * li0, Oa[ni][1] * li0);
            __half2 o1 = __floats2half2_rn(Oa[ni][2] * li1, Oa[ni][3] * li1);
            *(__half2*)(lctxh + (size_t)t0 * (NH * LAT) + h * 64 + c0) = o0;
            *(__half2*)(lctxh + (size_t)t1 * (NH * LAT) + h * 64 + c0) = o1;
        }
    }
}

// ---------------- host launcher ----------------
extern "C" void kernel_launch(void* const* d_in, const int* in_sizes, int n_in,
                              void* d_out, int out_size)
{
    const float* hidden = (const float*)d_in[0];
    const float* Wq  = (const float*)d_in[1];
    const float* Wk  = (const float*)d_in[2];
    const float* Wv  = (const float*)d_in[3];
    const float* q2l = (const float*)d_in[4];
    const float* vup = (const float*)d_in[5];
    const float* Wo  = (const float*)d_in[6];
    float* out = (float*)d_out;

    float *q2lT, *lpart, *qs, *ks;
    __nv_bfloat16 *WqT2, *Wo2, *q2l2p, *vup2p;
    __half *hidh, *Wkvh, *Wf1h, *Wf2h, *qlath, *lkh, *lvTh, *lctxh;
    cudaGetSymbolAddress((void**)&q2lT,  g_q2lT);
    cudaGetSymbolAddress((void**)&lpart, g_lpart);
    cudaGetSymbolAddress((void**)&qs,    g_qsum);
    cudaGetSymbolAddress((void**)&ks,    g_ksum);
    cudaGetSymbolAddress((void**)&WqT2,  g_WqT2);
    cudaGetSymbolAddress((void**)&Wo2,   g_Wo2);
    cudaGetSymbolAddress((void**)&q2l2p, g_q2l2p);
    cudaGetSymbolAddress((void**)&vup2p, g_vup2p);
    cudaGetSymbolAddress((void**)&hidh,  g_hidh);
    cudaGetSymbolAddress((void**)&Wkvh,  g_Wkvh);
    cudaGetSymbolAddress((void**)&Wf1h,  g_Wf1h);
    cudaGetSymbolAddress((void**)&Wf2h,  g_Wf2h);
    cudaGetSymbolAddress((void**)&qlath, g_qlath);
    cudaGetSymbolAddress((void**)&lkh,   g_lkh);
    cudaGetSymbolAddress((void**)&lvTh,  g_lvTh);
    cudaGetSymbolAddress((void**)&lctxh, g_lctxh);

    cudaFuncSetAttribute(hmma_gemm_f16,
                         cudaFuncAttributeMaxDynamicSharedMemorySize, HMMA_SMEM);
    cudaFuncSetAttribute(hmma_qlat_f16,
                         cudaFuncAttributeMaxDynamicSharedMemorySize, HMMA_SMEM);
    cudaFuncSetAttribute(hmma_fold,
                         cudaFuncAttributeMaxDynamicSharedMemorySize, HMMA_SMEM);
    cudaFuncSetAttribute(flash_hmma,
                         cudaFuncAttributeMaxDynamicSharedMemorySize, FLASH_SMEM);

    // --- weight preprocessing (folds stay bf16x3 for weight precision) ---
    transpose_k<<<dim3(2, 4, NH), dim3(32, 8)>>>(q2l, q2lT, HD, LAT,
                                                 (long)HD * LAT, (long)LAT * HD);
    transpose_split2<<<dim3(64, 64), dim3(32, 8)>>>(Wq, WqT2);
    cvt_split2<<<(EMB * EMB / 4 + 255) / 256, 256>>>(Wo, Wo2, EMB * EMB, HD, HD);
    cvt_split2_pad<<<(NH * HD * HD / 4 + 255) / 256, 256>>>(
        q2lT, q2l2p, NH, LAT, HD, HD, HD);
    cvt_split2_pad<<<(NH * HD * HD / 4 + 255) / 256, 256>>>(
        vup, vup2p, NH, LAT, HD, HD, HD);

    // --- folds (bf16x3 in, fp16 out) ---
    // Wf1h[h*64+l][2048] = q2l[h]^T-fold
    hmma_fold<<<dim3(16, 1, NH), 256, HMMA_SMEM>>>(
        q2l2p, WqT2, Wf1h, HD, 2 * HD, NH * 2 * HD,
        (long)HD * 2 * HD, (long)2 * HD, (long)LAT * EMB,
        EMB, LAT, EMB);
    // Wf2h[e][h*64+l]
    hmma_fold<<<dim3(1, 16, NH), 256, HMMA_SMEM>>>(
        Wo2, vup2p, Wf2h, HD, NH * 2 * HD, 2 * HD,
        (long)2 * HD, (long)HD * 2 * HD, (long)LAT,
        NH * LAT, EMB, LAT);

    // --- fp16 input conversions ---
    cvt_f16<<<(T_SEQ * EMB / 4 + 255) / 256, 256>>>(hidden, hidh, T_SEQ * EMB);
    cvt_f16<<<(LAT * EMB / 4 + 255) / 256, 256>>>(Wk, Wkvh, LAT * EMB);
    cvt_f16<<<(LAT * EMB / 4 + 255) / 256, 256>>>(Wv, Wkvh + (size_t)LAT * EMB, LAT * EMB);

    // --- lkv = hid @ [Wk;Wv]^T (fp16, split-K x8; reduce fused in cvt_kv) ---
    hmma_gemm_f16<<<dim3(1, 16, 8), 256, HMMA_SMEM>>>(hidh, Wkvh, lpart,
                                                      T_SEQ, 2 * LAT, EMB, 8);
    cvt_kv<<<32, 256>>>(lpart, lkh, lvTh, ks);

    // --- q_latent (fp16) ---
    hmma_qlat_f16<<<dim3(8, 16), 256, HMMA_SMEM>>>(hidh, Wf1h, qlath, EMB);
    qsum_kernel<<<(T_SEQ * NH + 255) / 256, 256>>>(qlath, qs);

    // --- flash attention (fp16) ---
    flash_hmma<<<dim3(8, NH), 256, FLASH_SMEM>>>(qlath, lkh, lvTh, qs, ks, lctxh);

    // --- out = lctx @ Wf2^T (fp16, K=1024) ---
    hmma_gemm_f16<<<dim3(16, 16, 1), 256, HMMA_SMEM>>>(lctxh, Wf2h, out,
                                                       T_SEQ, EMB, NH * LAT, 1);
}